// round 1
// baseline (speedup 1.0000x reference)
#include <cuda_runtime.h>
#include <math.h>

#define NB 8
#define NH 8
#define SEQ 512
#define HID 512
#define HD 64

// ---------------- scratch (device globals; no allocations) ----------------
__device__ float g_Q[NB*NH*SEQ*HD];        // 8 MB  [b,h,n,d], pre-scaled by 1/8
__device__ float g_K[NB*NH*SEQ*HD];        // 8 MB
__device__ float g_V[NB*NH*SEQ*HD];        // 8 MB
__device__ float g_bias[(size_t)NB*NH*SEQ*SEQ]; // 64 MB [b,h,q,k]
__device__ float g_ctx[NB*SEQ*HID];        // 8 MB  [b,n,hid]
__device__ float g_maskf[NB*SEQ];          // 0/1 floats

// ---------------- mask normalization (dtype-agnostic) ----------------
// mask was produced by jax.random.bernoulli -> bool; it may arrive as
// uint8, int32, or float32. Detect the storage format from the raw bytes
// (deterministic), then expand to float 0/1.
__global__ void mask_convert_kernel(const unsigned char* __restrict__ raw) {
    __shared__ int mode;
    if (threadIdx.x == 0) {
        const unsigned int* w = (const unsigned int*)raw;
        int cf = 0, byteish = 0;
        for (int i = 0; i < 128; i++) {       // 512 bytes, safe for all layouts
            unsigned int v = w[i];
            if (v == 0x3F800000u) cf++;
            bool b01 = true;
            #pragma unroll
            for (int bb = 0; bb < 4; bb++) {
                unsigned int by = (v >> (8*bb)) & 0xFFu;
                if (by > 1u) b01 = false;
            }
            if (b01 && v > 1u) byteish++;     // multiple 1-bytes packed => uint8
        }
        mode = (cf > 64) ? 0 : ((byteish > 0) ? 2 : 1);  // 0=f32, 1=i32, 2=u8
    }
    __syncthreads();
    int md = mode;
    for (int i = threadIdx.x; i < NB*SEQ; i += blockDim.x) {
        float m;
        if (md == 0)      m = (((const float*)raw)[i] != 0.0f) ? 1.0f : 0.0f;
        else if (md == 1) m = (((const int*)raw)[i]   != 0)    ? 1.0f : 0.0f;
        else              m = (raw[i]                 != 0)    ? 1.0f : 0.0f;
        g_maskf[i] = m;
    }
}

// ---------------- fused QKV projection SGEMM ----------------
// C[4096,512] = X @ W + b, written head-split into g_Q/g_K/g_V.
// 128x128 tile, BK=8, 256 threads, 8x8 per thread.
__global__ __launch_bounds__(256) void sgemm_qkv_kernel(
    const float* __restrict__ X,
    const float* __restrict__ Wq, const float* __restrict__ Wk, const float* __restrict__ Wv,
    const float* __restrict__ bq, const float* __restrict__ bk, const float* __restrict__ bv)
{
    __shared__ float As[8][128];
    __shared__ float Bs[8][128];
    const int z = blockIdx.z;
    const float* W    = (z == 0) ? Wq : ((z == 1) ? Wk : Wv);
    const float* bias = (z == 0) ? bq : ((z == 1) ? bk : bv);
    float* OUT        = (z == 0) ? g_Q : ((z == 1) ? g_K : g_V);

    const int tid = threadIdx.x;
    const int m0 = blockIdx.y * 128, n0 = blockIdx.x * 128;
    const int arow = tid >> 1, acol = (tid & 1) << 2;
    const int brow = tid >> 5, bcol = (tid & 31) << 2;
    const int ty = tid >> 4, tx = tid & 15;

    float acc[8][8];
    #pragma unroll
    for (int i = 0; i < 8; i++)
        #pragma unroll
        for (int j = 0; j < 8; j++) acc[i][j] = 0.0f;

    const float* Aptr = X + (size_t)(m0 + arow) * HID + acol;
    const float* Bptr = W + (size_t)brow * HID + n0 + bcol;

    for (int k0 = 0; k0 < HID; k0 += 8) {
        float4 a = *(const float4*)(Aptr + k0);
        As[acol + 0][arow] = a.x;
        As[acol + 1][arow] = a.y;
        As[acol + 2][arow] = a.z;
        As[acol + 3][arow] = a.w;
        *(float4*)&Bs[brow][bcol] = *(const float4*)(Bptr + (size_t)k0 * HID);
        __syncthreads();
        #pragma unroll
        for (int kk = 0; kk < 8; kk++) {
            float4 a0 = *(float4*)&As[kk][ty * 8];
            float4 a1 = *(float4*)&As[kk][ty * 8 + 4];
            float4 b0 = *(float4*)&Bs[kk][tx * 8];
            float4 b1 = *(float4*)&Bs[kk][tx * 8 + 4];
            float ar[8] = {a0.x, a0.y, a0.z, a0.w, a1.x, a1.y, a1.z, a1.w};
            float br[8] = {b0.x, b0.y, b0.z, b0.w, b1.x, b1.y, b1.z, b1.w};
            #pragma unroll
            for (int i = 0; i < 8; i++)
                #pragma unroll
                for (int j = 0; j < 8; j++)
                    acc[i][j] = fmaf(ar[i], br[j], acc[i][j]);
        }
        __syncthreads();
    }

    const float scale = (z == 0) ? 0.125f : 1.0f;  // fold 1/sqrt(64) into Q
    #pragma unroll
    for (int i = 0; i < 8; i++) {
        int m = m0 + ty * 8 + i;
        int bb = m >> 9, n = m & 511;
        #pragma unroll
        for (int j = 0; j < 8; j++) {
            int col = n0 + tx * 8 + j;
            int hh = col >> 6, d = col & 63;
            OUT[(((size_t)(bb * NH + hh)) * SEQ + n) * HD + d] =
                (acc[i][j] + bias[col]) * scale;
        }
    }
}

// ---------------- output projection SGEMM (ctx @ Wo + bo, query-mask) ------
__global__ __launch_bounds__(256) void sgemm_out_kernel(
    const float* __restrict__ Wo, const float* __restrict__ bo,
    float* __restrict__ OUT)
{
    __shared__ float As[8][128];
    __shared__ float Bs[8][128];
    const int tid = threadIdx.x;
    const int m0 = blockIdx.y * 128, n0 = blockIdx.x * 128;
    const int arow = tid >> 1, acol = (tid & 1) << 2;
    const int brow = tid >> 5, bcol = (tid & 31) << 2;
    const int ty = tid >> 4, tx = tid & 15;

    float acc[8][8];
    #pragma unroll
    for (int i = 0; i < 8; i++)
        #pragma unroll
        for (int j = 0; j < 8; j++) acc[i][j] = 0.0f;

    const float* Aptr = g_ctx + (size_t)(m0 + arow) * HID + acol;
    const float* Bptr = Wo + (size_t)brow * HID + n0 + bcol;

    for (int k0 = 0; k0 < HID; k0 += 8) {
        float4 a = *(const float4*)(Aptr + k0);
        As[acol + 0][arow] = a.x;
        As[acol + 1][arow] = a.y;
        As[acol + 2][arow] = a.z;
        As[acol + 3][arow] = a.w;
        *(float4*)&Bs[brow][bcol] = *(const float4*)(Bptr + (size_t)k0 * HID);
        __syncthreads();
        #pragma unroll
        for (int kk = 0; kk < 8; kk++) {
            float4 a0 = *(float4*)&As[kk][ty * 8];
            float4 a1 = *(float4*)&As[kk][ty * 8 + 4];
            float4 b0 = *(float4*)&Bs[kk][tx * 8];
            float4 b1 = *(float4*)&Bs[kk][tx * 8 + 4];
            float ar[8] = {a0.x, a0.y, a0.z, a0.w, a1.x, a1.y, a1.z, a1.w};
            float br[8] = {b0.x, b0.y, b0.z, b0.w, b1.x, b1.y, b1.z, b1.w};
            #pragma unroll
            for (int i = 0; i < 8; i++)
                #pragma unroll
                for (int j = 0; j < 8; j++)
                    acc[i][j] = fmaf(ar[i], br[j], acc[i][j]);
        }
        __syncthreads();
    }

    #pragma unroll
    for (int i = 0; i < 8; i++) {
        int m = m0 + ty * 8 + i;
        float mf = g_maskf[m];
        #pragma unroll
        for (int j = 0; j < 8; j++) {
            int col = n0 + tx * 8 + j;
            OUT[(size_t)m * HID + col] = (mf > 0.5f) ? (acc[i][j] + bo[col]) : 0.0f;
        }
    }
}

// ---------------- distance bias: [B*N*N, 64] @ [64, 8] + bd ----------------
__global__ __launch_bounds__(256) void dist_bias_kernel(
    const float* __restrict__ D, const float* __restrict__ Wd,
    const float* __restrict__ bd)
{
    __shared__ float w[64 * 8];
    __shared__ float bsm[8];
    const int tid = threadIdx.x;
    w[tid]       = Wd[tid];
    w[tid + 256] = Wd[tid + 256];
    if (tid < 8) bsm[tid] = bd[tid];
    __syncthreads();

    size_t r = (size_t)blockIdx.x * 256 + tid;       // row over B*N*N = 2M
    const float* row = D + r * 64;
    float acc[8] = {0, 0, 0, 0, 0, 0, 0, 0};
    #pragma unroll
    for (int t = 0; t < 16; t++) {
        float4 v = *(const float4*)&row[t * 4];
        float vv[4] = {v.x, v.y, v.z, v.w};
        #pragma unroll
        for (int e = 0; e < 4; e++) {
            int d = t * 4 + e;
            #pragma unroll
            for (int h = 0; h < 8; h++)
                acc[h] = fmaf(vv[e], w[d * 8 + h], acc[h]);
        }
    }
    int b = (int)(r >> 18);
    int rem = (int)(r & 262143);
    int q = rem >> 9, k = rem & 511;
    #pragma unroll
    for (int h = 0; h < 8; h++)
        g_bias[(((size_t)(b * NH + h)) * SEQ + q) * SEQ + k] = acc[h] + bsm[h];
}

// ---------------- attention: per (b,h,q-block of 64) ----------------
#define SPAD 68   // stride for QsT/KsT/Vs tiles (float4-aligned, conflict-light)
#define STP  66   // stride for score matrix ST[key][q] (float2-aligned)
#define ATTN_SMEM_FLOATS (2*64*SPAD + 512*STP + 64)
#define ATTN_SMEM_BYTES  (ATTN_SMEM_FLOATS * 4)

__device__ __forceinline__ void load_tile_T(float* dstT, const float* __restrict__ src, int tid) {
    // src: 64x64 row-major; dstT[d*SPAD + r] = src[r*64 + d]
    #pragma unroll
    for (int j = 0; j < 4; j++) {
        int r  = (tid >> 4) + j * 16;
        int d0 = (tid & 15) * 4;
        float4 v = *(const float4*)&src[r * 64 + d0];
        dstT[(d0 + 0) * SPAD + r] = v.x;
        dstT[(d0 + 1) * SPAD + r] = v.y;
        dstT[(d0 + 2) * SPAD + r] = v.z;
        dstT[(d0 + 3) * SPAD + r] = v.w;
    }
}

__device__ __forceinline__ void load_tile(float* dst, const float* __restrict__ src, int tid) {
    #pragma unroll
    for (int j = 0; j < 4; j++) {
        int r  = (tid >> 4) + j * 16;
        int d0 = (tid & 15) * 4;
        *(float4*)&dst[r * SPAD + d0] = *(const float4*)&src[r * 64 + d0];
    }
}

__global__ __launch_bounds__(256) void attn_kernel() {
    extern __shared__ float sm[];
    float* QsT = sm;                       // [64][SPAD]  q transposed: [d][q]
    float* KVs = sm + 64 * SPAD;           // [64][SPAD]  K transposed / V natural
    float* ST  = sm + 2 * 64 * SPAD;       // [512][STP]  scores: [key][q]
    float* INV = ST + 512 * STP;           // [64] 1/rowsum

    const int tid = threadIdx.x;
    const int qb = blockIdx.x, h = blockIdx.y, b = blockIdx.z;
    const int bh = b * NH + h;

    const float* Qp = g_Q + ((size_t)bh * SEQ + qb * 64) * HD;
    const float* Kp = g_K + (size_t)bh * SEQ * HD;
    const float* Vp = g_V + (size_t)bh * SEQ * HD;
    const float* Bp = g_bias + ((size_t)bh * SEQ + qb * 64) * SEQ;

    load_tile_T(QsT, Qp, tid);

    const int ty = tid >> 4, tx = tid & 15;
    const int r0 = ty * 4, c0 = tx * 4;    // r0: q rows, c0: key cols / head dims

    // ---- scores: S = (Q/8) @ K^T + bias, key-mask fill ----
    for (int kb = 0; kb < 8; kb++) {
        __syncthreads();                    // Q/prev-K tile consumed
        load_tile_T(KVs, Kp + (size_t)kb * 64 * HD, tid);
        __syncthreads();
        float s[4][4] = {};
        #pragma unroll 8
        for (int k = 0; k < 64; k++) {
            float4 qv = *(float4*)&QsT[k * SPAD + r0];
            float4 kv = *(float4*)&KVs[k * SPAD + c0];
            s[0][0] = fmaf(qv.x, kv.x, s[0][0]); s[0][1] = fmaf(qv.x, kv.y, s[0][1]);
            s[0][2] = fmaf(qv.x, kv.z, s[0][2]); s[0][3] = fmaf(qv.x, kv.w, s[0][3]);
            s[1][0] = fmaf(qv.y, kv.x, s[1][0]); s[1][1] = fmaf(qv.y, kv.y, s[1][1]);
            s[1][2] = fmaf(qv.y, kv.z, s[1][2]); s[1][3] = fmaf(qv.y, kv.w, s[1][3]);
            s[2][0] = fmaf(qv.z, kv.x, s[2][0]); s[2][1] = fmaf(qv.z, kv.y, s[2][1]);
            s[2][2] = fmaf(qv.z, kv.z, s[2][2]); s[2][3] = fmaf(qv.z, kv.w, s[2][3]);
            s[3][0] = fmaf(qv.w, kv.x, s[3][0]); s[3][1] = fmaf(qv.w, kv.y, s[3][1]);
            s[3][2] = fmaf(qv.w, kv.z, s[3][2]); s[3][3] = fmaf(qv.w, kv.w, s[3][3]);
        }
        #pragma unroll
        for (int j = 0; j < 4; j++) {
            int kg = kb * 64 + c0 + j;
            float keep = g_maskf[b * SEQ + kg];
            #pragma unroll
            for (int i = 0; i < 4; i++) {
                float val = s[i][j] + Bp[(size_t)(r0 + i) * SEQ + kg];
                ST[kg * STP + (r0 + i)] = (keep > 0.5f) ? val : -1e9f;
            }
        }
    }
    __syncthreads();

    // ---- softmax over keys (per q column of ST), deferred 1/sum ----
    {
        int w = tid >> 5, lane = tid & 31;
        for (int q = w * 8; q < w * 8 + 8; q++) {
            float mx = -3.4e38f;
            for (int k = lane; k < SEQ; k += 32)
                mx = fmaxf(mx, ST[k * STP + q]);
            #pragma unroll
            for (int o = 16; o; o >>= 1)
                mx = fmaxf(mx, __shfl_xor_sync(0xffffffffu, mx, o));
            float sum = 0.0f;
            for (int k = lane; k < SEQ; k += 32) {
                float e = __expf(ST[k * STP + q] - mx);
                ST[k * STP + q] = e;
                sum += e;
            }
            #pragma unroll
            for (int o = 16; o; o >>= 1)
                sum += __shfl_xor_sync(0xffffffffu, sum, o);
            if (lane == 0) INV[q] = 1.0f / sum;
        }
    }

    // ---- O = P @ V ----
    float o[4][4] = {};
    for (int kb = 0; kb < 8; kb++) {
        __syncthreads();
        load_tile(KVs, Vp + (size_t)kb * 64 * HD, tid);
        __syncthreads();
        #pragma unroll 8
        for (int k = 0; k < 64; k++) {
            int kg = kb * 64 + k;
            float2 p01 = *(float2*)&ST[kg * STP + r0];
            float2 p23 = *(float2*)&ST[kg * STP + r0 + 2];
            float4 vv  = *(float4*)&KVs[k * SPAD + c0];
            o[0][0] = fmaf(p01.x, vv.x, o[0][0]); o[0][1] = fmaf(p01.x, vv.y, o[0][1]);
            o[0][2] = fmaf(p01.x, vv.z, o[0][2]); o[0][3] = fmaf(p01.x, vv.w, o[0][3]);
            o[1][0] = fmaf(p01.y, vv.x, o[1][0]); o[1][1] = fmaf(p01.y, vv.y, o[1][1]);
            o[1][2] = fmaf(p01.y, vv.z, o[1][2]); o[1][3] = fmaf(p01.y, vv.w, o[1][3]);
            o[2][0] = fmaf(p23.x, vv.x, o[2][0]); o[2][1] = fmaf(p23.x, vv.y, o[2][1]);
            o[2][2] = fmaf(p23.x, vv.z, o[2][2]); o[2][3] = fmaf(p23.x, vv.w, o[2][3]);
            o[3][0] = fmaf(p23.y, vv.x, o[3][0]); o[3][1] = fmaf(p23.y, vv.y, o[3][1]);
            o[3][2] = fmaf(p23.y, vv.z, o[3][2]); o[3][3] = fmaf(p23.y, vv.w, o[3][3]);
        }
    }

    // ---- write ctx[b, q, h*64+d] with deferred softmax normalization ----
    #pragma unroll
    for (int i = 0; i < 4; i++) {
        float inv = INV[r0 + i];
        size_t m = (size_t)b * SEQ + qb * 64 + r0 + i;
        #pragma unroll
        for (int j = 0; j < 4; j++)
            g_ctx[m * HID + h * HD + c0 + j] = o[i][j] * inv;
    }
}

// ---------------- launch ----------------
extern "C" void kernel_launch(void* const* d_in, const int* in_sizes, int n_in,
                              void* d_out, int out_size)
{
    const float* x    = (const float*)d_in[0];
    const float* dist = (const float*)d_in[1];
    const unsigned char* mask = (const unsigned char*)d_in[2];
    const float* Wq = (const float*)d_in[3];
    const float* bq = (const float*)d_in[4];
    const float* Wk = (const float*)d_in[5];
    const float* bk = (const float*)d_in[6];
    const float* Wv = (const float*)d_in[7];
    const float* bv = (const float*)d_in[8];
    const float* Wo = (const float*)d_in[9];
    const float* bo = (const float*)d_in[10];
    const float* Wd = (const float*)d_in[11];
    const float* bd = (const float*)d_in[12];
    float* out = (float*)d_out;

    cudaFuncSetAttribute(attn_kernel, cudaFuncAttributeMaxDynamicSharedMemorySize,
                         ATTN_SMEM_BYTES);

    mask_convert_kernel<<<1, 256>>>(mask);
    sgemm_qkv_kernel<<<dim3(4, 32, 3), 256>>>(x, Wq, Wk, Wv, bq, bk, bv);
    dist_bias_kernel<<<8192, 256>>>(dist, Wd, bd);
    attn_kernel<<<dim3(8, NH, NB), 256, ATTN_SMEM_BYTES>>>();
    sgemm_out_kernel<<<dim3(4, 32, 1), 256>>>(Wo, bo, out);
}

// round 2
// speedup vs baseline: 1.3295x; 1.3295x over previous
#include <cuda_runtime.h>
#include <math.h>

#define NB 8
#define NH 8
#define SEQ 512
#define HID 512
#define HD 64

// ---------------- scratch (device globals; no allocations) ----------------
__device__ float g_Q[NB*NH*SEQ*HD];        // 8 MB  [b,h,n,d], pre-scaled by 1/8
__device__ float g_K[NB*NH*SEQ*HD];        // 8 MB
__device__ float g_V[NB*NH*SEQ*HD];        // 8 MB
__device__ float g_bias[(size_t)NB*NH*SEQ*SEQ]; // 64 MB [b,h,q,k]
__device__ float g_ctx[NB*SEQ*HID];        // 8 MB  [b,n,hid]
__device__ float g_maskf[NB*SEQ];          // 0/1 floats

// ---------------- mask normalization (dtype-agnostic) ----------------
__global__ void mask_convert_kernel(const unsigned char* __restrict__ raw) {
    __shared__ int mode;
    if (threadIdx.x == 0) {
        const unsigned int* w = (const unsigned int*)raw;
        int cf = 0, byteish = 0;
        for (int i = 0; i < 128; i++) {
            unsigned int v = w[i];
            if (v == 0x3F800000u) cf++;
            bool b01 = true;
            #pragma unroll
            for (int bb = 0; bb < 4; bb++) {
                unsigned int by = (v >> (8*bb)) & 0xFFu;
                if (by > 1u) b01 = false;
            }
            if (b01 && v > 1u) byteish++;
        }
        mode = (cf > 64) ? 0 : ((byteish > 0) ? 2 : 1);  // 0=f32, 1=i32, 2=u8
    }
    __syncthreads();
    int md = mode;
    for (int i = threadIdx.x; i < NB*SEQ; i += blockDim.x) {
        float m;
        if (md == 0)      m = (((const float*)raw)[i] != 0.0f) ? 1.0f : 0.0f;
        else if (md == 1) m = (((const int*)raw)[i]   != 0)    ? 1.0f : 0.0f;
        else              m = (raw[i]                 != 0)    ? 1.0f : 0.0f;
        g_maskf[i] = m;
    }
}

// ================= double-buffered SGEMM core (128x128, BK=16) =============
#define GEMM_BODY(APTR_BASE)                                                  \
    __shared__ float As[2][16][132];                                          \
    __shared__ float Bs[2][16][128];                                          \
    const int tid = threadIdx.x;                                              \
    const int m0 = blockIdx.y * 128, n0 = blockIdx.x * 128;                   \
    const int ar = tid >> 2, ac = (tid & 3) << 2;                             \
    const int br = tid >> 5, bc = (tid & 31) << 2;                            \
    const int ty = tid >> 4, tx = tid & 15;                                   \
    const float* Ap0 = (APTR_BASE) + (size_t)(m0 + ar) * HID + ac;            \
    const float* Ap1 = Ap0 + (size_t)64 * HID;                                \
    const float* Bp0 = W + (size_t)br * HID + n0 + bc;                        \
    const float* Bp1 = Bp0 + (size_t)8 * HID;                                 \
    float4 a0 = *(const float4*)Ap0;                                          \
    float4 a1 = *(const float4*)Ap1;                                          \
    float4 b0 = *(const float4*)Bp0;                                          \
    float4 b1 = *(const float4*)Bp1;                                          \
    As[0][ac+0][ar] = a0.x; As[0][ac+1][ar] = a0.y;                           \
    As[0][ac+2][ar] = a0.z; As[0][ac+3][ar] = a0.w;                           \
    As[0][ac+0][ar+64] = a1.x; As[0][ac+1][ar+64] = a1.y;                     \
    As[0][ac+2][ar+64] = a1.z; As[0][ac+3][ar+64] = a1.w;                     \
    *(float4*)&Bs[0][br][bc] = b0;                                            \
    *(float4*)&Bs[0][br+8][bc] = b1;                                          \
    __syncthreads();                                                          \
    float acc[8][8];                                                          \
    _Pragma("unroll")                                                         \
    for (int i = 0; i < 8; i++)                                               \
        _Pragma("unroll")                                                     \
        for (int j = 0; j < 8; j++) acc[i][j] = 0.0f;                         \
    _Pragma("unroll 1")                                                       \
    for (int t = 0; t < 32; t++) {                                            \
        const int cur = t & 1;                                                \
        if (t < 31) {                                                         \
            const int k0 = (t + 1) * 16;                                      \
            a0 = *(const float4*)(Ap0 + k0);                                  \
            a1 = *(const float4*)(Ap1 + k0);                                  \
            b0 = *(const float4*)(Bp0 + (size_t)k0 * HID);                    \
            b1 = *(const float4*)(Bp1 + (size_t)k0 * HID);                    \
        }                                                                     \
        _Pragma("unroll")                                                     \
        for (int kk = 0; kk < 16; kk++) {                                     \
            float4 x0 = *(float4*)&As[cur][kk][ty * 8];                       \
            float4 x1 = *(float4*)&As[cur][kk][ty * 8 + 4];                   \
            float4 y0 = *(float4*)&Bs[cur][kk][tx * 8];                       \
            float4 y1 = *(float4*)&Bs[cur][kk][tx * 8 + 4];                   \
            float xr[8] = {x0.x,x0.y,x0.z,x0.w,x1.x,x1.y,x1.z,x1.w};          \
            float yr[8] = {y0.x,y0.y,y0.z,y0.w,y1.x,y1.y,y1.z,y1.w};          \
            _Pragma("unroll")                                                 \
            for (int i = 0; i < 8; i++)                                       \
                _Pragma("unroll")                                             \
                for (int j = 0; j < 8; j++)                                   \
                    acc[i][j] = fmaf(xr[i], yr[j], acc[i][j]);                \
        }                                                                     \
        if (t < 31) {                                                         \
            const int nxt = cur ^ 1;                                          \
            As[nxt][ac+0][ar] = a0.x; As[nxt][ac+1][ar] = a0.y;               \
            As[nxt][ac+2][ar] = a0.z; As[nxt][ac+3][ar] = a0.w;               \
            As[nxt][ac+0][ar+64] = a1.x; As[nxt][ac+1][ar+64] = a1.y;         \
            As[nxt][ac+2][ar+64] = a1.z; As[nxt][ac+3][ar+64] = a1.w;         \
            *(float4*)&Bs[nxt][br][bc] = b0;                                  \
            *(float4*)&Bs[nxt][br+8][bc] = b1;                                \
            __syncthreads();                                                  \
        }                                                                     \
    }

// ---------------- fused QKV projection ----------------
__global__ __launch_bounds__(256) void sgemm_qkv_kernel(
    const float* __restrict__ X,
    const float* __restrict__ Wq, const float* __restrict__ Wk, const float* __restrict__ Wv,
    const float* __restrict__ bq, const float* __restrict__ bk, const float* __restrict__ bv)
{
    const int z = blockIdx.z;
    const float* W    = (z == 0) ? Wq : ((z == 1) ? Wk : Wv);
    const float* bias = (z == 0) ? bq : ((z == 1) ? bk : bv);
    float* OUT        = (z == 0) ? g_Q : ((z == 1) ? g_K : g_V);

    GEMM_BODY(X)

    const float scale = (z == 0) ? 0.125f : 1.0f;
    #pragma unroll
    for (int i = 0; i < 8; i++) {
        int m = m0 + ty * 8 + i;
        int bb = m >> 9, n = m & 511;
        #pragma unroll
        for (int j = 0; j < 8; j++) {
            int col = n0 + tx * 8 + j;
            int hh = col >> 6, d = col & 63;
            OUT[(((size_t)(bb * NH + hh)) * SEQ + n) * HD + d] =
                (acc[i][j] + bias[col]) * scale;
        }
    }
}

// ---------------- output projection ----------------
__global__ __launch_bounds__(256) void sgemm_out_kernel(
    const float* __restrict__ Wo, const float* __restrict__ bo,
    float* __restrict__ OUT)
{
    const float* W = Wo;

    GEMM_BODY(g_ctx)

    #pragma unroll
    for (int i = 0; i < 8; i++) {
        int m = m0 + ty * 8 + i;
        float mf = g_maskf[m];
        #pragma unroll
        for (int j = 0; j < 8; j++) {
            int col = n0 + tx * 8 + j;
            OUT[(size_t)m * HID + col] = (mf > 0.5f) ? (acc[i][j] + bo[col]) : 0.0f;
        }
    }
}

// ---------------- distance bias: [B*N*N, 64] @ [64, 8] + bd ----------------
__global__ __launch_bounds__(256) void dist_bias_kernel(
    const float* __restrict__ D, const float* __restrict__ Wd,
    const float* __restrict__ bd)
{
    __shared__ float w[64 * 8];
    __shared__ float bsm[8];
    const int tid = threadIdx.x;
    w[tid]       = Wd[tid];
    w[tid + 256] = Wd[tid + 256];
    if (tid < 8) bsm[tid] = bd[tid];
    __syncthreads();

    size_t r = (size_t)blockIdx.x * 256 + tid;       // row over B*N*N = 2M
    const float* row = D + r * 64;
    float acc[8] = {0, 0, 0, 0, 0, 0, 0, 0};
    #pragma unroll
    for (int t = 0; t < 16; t++) {
        float4 v = *(const float4*)&row[t * 4];
        float vv[4] = {v.x, v.y, v.z, v.w};
        #pragma unroll
        for (int e = 0; e < 4; e++) {
            int d = t * 4 + e;
            #pragma unroll
            for (int h = 0; h < 8; h++)
                acc[h] = fmaf(vv[e], w[d * 8 + h], acc[h]);
        }
    }
    int b = (int)(r >> 18);
    int rem = (int)(r & 262143);
    int q = rem >> 9, k = rem & 511;
    #pragma unroll
    for (int h = 0; h < 8; h++)
        g_bias[(((size_t)(b * NH + h)) * SEQ + q) * SEQ + k] = acc[h] + bsm[h];
}

// ---------------- flash attention: per (b,h,q-block of 64) ----------------
#define SPAD 68
#define ATTN_SMEM_BYTES (3 * 64 * SPAD * 4)

__device__ __forceinline__ void load_tile_T(float* dstT, const float* __restrict__ src, int tid) {
    // src: 64x64 row-major; dstT[d*SPAD + r] = src[r*64 + d]
    #pragma unroll
    for (int j = 0; j < 4; j++) {
        int r  = (tid >> 4) + j * 16;
        int d0 = (tid & 15) * 4;
        float4 v = *(const float4*)&src[r * 64 + d0];
        dstT[(d0 + 0) * SPAD + r] = v.x;
        dstT[(d0 + 1) * SPAD + r] = v.y;
        dstT[(d0 + 2) * SPAD + r] = v.z;
        dstT[(d0 + 3) * SPAD + r] = v.w;
    }
}

__device__ __forceinline__ void load_tile(float* dst, const float* __restrict__ src, int tid) {
    #pragma unroll
    for (int j = 0; j < 4; j++) {
        int r  = (tid >> 4) + j * 16;
        int d0 = (tid & 15) * 4;
        *(float4*)&dst[r * SPAD + d0] = *(const float4*)&src[r * 64 + d0];
    }
}

__global__ __launch_bounds__(256) void attn_kernel() {
    extern __shared__ float sm[];
    float* QsT = sm;                  // [64][SPAD]  Q transposed [d][q]
    float* T1  = sm + 64 * SPAD;      // K transposed [d][k], then V natural [k][d]
    float* Ps  = sm + 2 * 64 * SPAD;  // [64 q][SPAD]  P tile [q][k]

    const int tid = threadIdx.x;
    const int qb = blockIdx.x, h = blockIdx.y, b = blockIdx.z;
    const int bh = b * NH + h;

    const float* Qp = g_Q + ((size_t)bh * SEQ + qb * 64) * HD;
    const float* Kp = g_K + (size_t)bh * SEQ * HD;
    const float* Vp = g_V + (size_t)bh * SEQ * HD;
    const float* Bp = g_bias + ((size_t)bh * SEQ + qb * 64) * SEQ;
    const float* Mp = g_maskf + b * SEQ;

    load_tile_T(QsT, Qp, tid);

    const int ty = tid >> 4, tx = tid & 15;
    const int r0 = ty * 4, c0 = tx * 4;

    float o[4][4] = {};
    float mrun[4] = {-3.0e38f, -3.0e38f, -3.0e38f, -3.0e38f};
    float lrun[4] = {};

    for (int kb = 0; kb < 8; kb++) {
        __syncthreads();                         // prior PV done with T1/Ps
        load_tile_T(T1, Kp + (size_t)kb * 64 * HD, tid);
        __syncthreads();

        // ---- S tile = Q @ K^T ----
        float s[4][4] = {};
        #pragma unroll 8
        for (int k = 0; k < 64; k++) {
            float4 qv = *(float4*)&QsT[k * SPAD + r0];
            float4 kv = *(float4*)&T1[k * SPAD + c0];
            s[0][0] = fmaf(qv.x, kv.x, s[0][0]); s[0][1] = fmaf(qv.x, kv.y, s[0][1]);
            s[0][2] = fmaf(qv.x, kv.z, s[0][2]); s[0][3] = fmaf(qv.x, kv.w, s[0][3]);
            s[1][0] = fmaf(qv.y, kv.x, s[1][0]); s[1][1] = fmaf(qv.y, kv.y, s[1][1]);
            s[1][2] = fmaf(qv.y, kv.z, s[1][2]); s[1][3] = fmaf(qv.y, kv.w, s[1][3]);
            s[2][0] = fmaf(qv.z, kv.x, s[2][0]); s[2][1] = fmaf(qv.z, kv.y, s[2][1]);
            s[2][2] = fmaf(qv.z, kv.z, s[2][2]); s[2][3] = fmaf(qv.z, kv.w, s[2][3]);
            s[3][0] = fmaf(qv.w, kv.x, s[3][0]); s[3][1] = fmaf(qv.w, kv.y, s[3][1]);
            s[3][2] = fmaf(qv.w, kv.z, s[3][2]); s[3][3] = fmaf(qv.w, kv.w, s[3][3]);
        }

        // ---- bias + key-mask + online softmax (stats replicated across tx) ----
        float4 km = *(const float4*)&Mp[kb * 64 + c0];
        float kmv[4] = {km.x, km.y, km.z, km.w};
        #pragma unroll
        for (int i = 0; i < 4; i++) {
            float4 b4 = *(const float4*)&Bp[(size_t)(r0 + i) * SEQ + kb * 64 + c0];
            float sv[4];
            sv[0] = (kmv[0] > 0.5f) ? s[i][0] + b4.x : -1e9f;
            sv[1] = (kmv[1] > 0.5f) ? s[i][1] + b4.y : -1e9f;
            sv[2] = (kmv[2] > 0.5f) ? s[i][2] + b4.z : -1e9f;
            sv[3] = (kmv[3] > 0.5f) ? s[i][3] + b4.w : -1e9f;
            float rm = fmaxf(fmaxf(sv[0], sv[1]), fmaxf(sv[2], sv[3]));
            #pragma unroll
            for (int off = 8; off; off >>= 1)
                rm = fmaxf(rm, __shfl_xor_sync(0xffffffffu, rm, off, 16));
            float newm = fmaxf(mrun[i], rm);
            float corr = __expf(mrun[i] - newm);
            mrun[i] = newm;
            float p0 = __expf(sv[0] - newm);
            float p1 = __expf(sv[1] - newm);
            float p2 = __expf(sv[2] - newm);
            float p3 = __expf(sv[3] - newm);
            float rs = (p0 + p1) + (p2 + p3);
            #pragma unroll
            for (int off = 8; off; off >>= 1)
                rs += __shfl_xor_sync(0xffffffffu, rs, off, 16);
            lrun[i] = lrun[i] * corr + rs;
            o[i][0] *= corr; o[i][1] *= corr; o[i][2] *= corr; o[i][3] *= corr;
            *(float4*)&Ps[(r0 + i) * SPAD + c0] = make_float4(p0, p1, p2, p3);
        }

        __syncthreads();                         // S phase done with T1 (K)
        load_tile(T1, Vp + (size_t)kb * 64 * HD, tid);
        __syncthreads();

        // ---- O += P @ V ----
        #pragma unroll 8
        for (int k = 0; k < 64; k++) {
            float pa = Ps[(r0 + 0) * SPAD + k];
            float pb = Ps[(r0 + 1) * SPAD + k];
            float pc = Ps[(r0 + 2) * SPAD + k];
            float pd = Ps[(r0 + 3) * SPAD + k];
            float4 vv = *(float4*)&T1[k * SPAD + c0];
            o[0][0] = fmaf(pa, vv.x, o[0][0]); o[0][1] = fmaf(pa, vv.y, o[0][1]);
            o[0][2] = fmaf(pa, vv.z, o[0][2]); o[0][3] = fmaf(pa, vv.w, o[0][3]);
            o[1][0] = fmaf(pb, vv.x, o[1][0]); o[1][1] = fmaf(pb, vv.y, o[1][1]);
            o[1][2] = fmaf(pb, vv.z, o[1][2]); o[1][3] = fmaf(pb, vv.w, o[1][3]);
            o[2][0] = fmaf(pc, vv.x, o[2][0]); o[2][1] = fmaf(pc, vv.y, o[2][1]);
            o[2][2] = fmaf(pc, vv.z, o[2][2]); o[2][3] = fmaf(pc, vv.w, o[2][3]);
            o[3][0] = fmaf(pd, vv.x, o[3][0]); o[3][1] = fmaf(pd, vv.y, o[3][1]);
            o[3][2] = fmaf(pd, vv.z, o[3][2]); o[3][3] = fmaf(pd, vv.w, o[3][3]);
        }
    }

    // ---- write ctx[b, q, h*64+d] with 1/l normalization ----
    #pragma unroll
    for (int i = 0; i < 4; i++) {
        float inv = 1.0f / lrun[i];
        size_t m = (size_t)b * SEQ + qb * 64 + r0 + i;
        #pragma unroll
        for (int j = 0; j < 4; j++)
            g_ctx[m * HID + h * HD + c0 + j] = o[i][j] * inv;
    }
}

// ---------------- launch ----------------
extern "C" void kernel_launch(void* const* d_in, const int* in_sizes, int n_in,
                              void* d_out, int out_size)
{
    const float* x    = (const float*)d_in[0];
    const float* dist = (const float*)d_in[1];
    const unsigned char* mask = (const unsigned char*)d_in[2];
    const float* Wq = (const float*)d_in[3];
    const float* bq = (const float*)d_in[4];
    const float* Wk = (const float*)d_in[5];
    const float* bk = (const float*)d_in[6];
    const float* Wv = (const float*)d_in[7];
    const float* bv = (const float*)d_in[8];
    const float* Wo = (const float*)d_in[9];
    const float* bo = (const float*)d_in[10];
    const float* Wd = (const float*)d_in[11];
    const float* bd = (const float*)d_in[12];
    float* out = (float*)d_out;

    cudaFuncSetAttribute(attn_kernel, cudaFuncAttributeMaxDynamicSharedMemorySize,
                         ATTN_SMEM_BYTES);

    mask_convert_kernel<<<1, 256>>>(mask);
    sgemm_qkv_kernel<<<dim3(4, 32, 3), 256>>>(x, Wq, Wk, Wv, bq, bk, bv);
    dist_bias_kernel<<<8192, 256>>>(dist, Wd, bd);
    attn_kernel<<<dim3(8, NH, NB), 256, ATTN_SMEM_BYTES>>>();
    sgemm_out_kernel<<<dim3(4, 32, 1), 256>>>(Wo, bo, out);
}

// round 4
// speedup vs baseline: 1.7970x; 1.3517x over previous
#include <cuda_runtime.h>
#include <cuda_bf16.h>
#include <stdint.h>
#include <math.h>

#define NB 8
#define NH 8
#define SEQ 512
#define HID 512
#define HD 64

// ---------------- scratch (device globals; no allocations) ----------------
__device__ float g_Q[NB*NH*SEQ*HD];        // 8 MB  [b,h,n,d], Q pre-scaled by 1/8
__device__ float g_K[NB*NH*SEQ*HD];        // 8 MB
__device__ float g_V[NB*NH*SEQ*HD];        // 8 MB
__device__ float g_bias[(size_t)NB*NH*SEQ*SEQ]; // 64 MB [b,h,q,k]
__device__ float g_ctx[NB*SEQ*HID];        // 8 MB  [b,n,hid]
__device__ float g_maskf[NB*SEQ];          // 0/1 floats

// bf16x3 operand stores
__device__ __nv_bfloat16 g_Ahi[NB*SEQ*HID];     // x or ctx, hi part [m][k]
__device__ __nv_bfloat16 g_Alo[NB*SEQ*HID];     // lo part
__device__ __nv_bfloat16 g_WThi[4][HID*HID];    // W^T [n][k] hi: q,k,v,o
__device__ __nv_bfloat16 g_WTlo[4][HID*HID];    // lo

// ---------------- PTX helpers ----------------
__device__ __forceinline__ uint32_t sm_u32(const void* p) {
    return (uint32_t)__cvta_generic_to_shared(p);
}
#define CP16(dst_u32, gptr) \
    asm volatile("cp.async.ca.shared.global [%0], [%1], 16;" :: "r"(dst_u32), "l"(gptr))
#define CP_COMMIT() asm volatile("cp.async.commit_group;")
#define CP_WAIT0()  asm volatile("cp.async.wait_group 0;")
#define LDMX4(r, addr) \
    asm volatile("ldmatrix.sync.aligned.m8n8.x4.shared.b16 {%0,%1,%2,%3}, [%4];" \
        : "=r"((r)[0]), "=r"((r)[1]), "=r"((r)[2]), "=r"((r)[3]) : "r"(addr))
#define MMA16816(d, a, b) \
    asm volatile("mma.sync.aligned.m16n8k16.row.col.f32.bf16.bf16.f32 " \
        "{%0,%1,%2,%3},{%4,%5,%6,%7},{%8,%9},{%0,%1,%2,%3};\n" \
        : "+f"((d)[0]), "+f"((d)[1]), "+f"((d)[2]), "+f"((d)[3]) \
        : "r"((a)[0]), "r"((a)[1]), "r"((a)[2]), "r"((a)[3]), "r"((b)[0]), "r"((b)[1]))

// ---------------- mask normalization (dtype-agnostic) ----------------
__global__ void mask_convert_kernel(const unsigned char* __restrict__ raw) {
    __shared__ int mode;
    if (threadIdx.x == 0) {
        const unsigned int* w = (const unsigned int*)raw;
        int cf = 0, byteish = 0;
        for (int i = 0; i < 128; i++) {
            unsigned int v = w[i];
            if (v == 0x3F800000u) cf++;
            bool b01 = true;
            #pragma unroll
            for (int bb = 0; bb < 4; bb++) {
                unsigned int by = (v >> (8*bb)) & 0xFFu;
                if (by > 1u) b01 = false;
            }
            if (b01 && v > 1u) byteish++;
        }
        mode = (cf > 64) ? 0 : ((byteish > 0) ? 2 : 1);  // 0=f32, 1=i32, 2=u8
    }
    __syncthreads();
    int md = mode;
    for (int i = threadIdx.x; i < NB*SEQ; i += blockDim.x) {
        float m;
        if (md == 0)      m = (((const float*)raw)[i] != 0.0f) ? 1.0f : 0.0f;
        else if (md == 1) m = (((const int*)raw)[i]   != 0)    ? 1.0f : 0.0f;
        else              m = (raw[i]                 != 0)    ? 1.0f : 0.0f;
        g_maskf[i] = m;
    }
}

// ---------------- hi/lo bf16 split of a dense f32 array ----------------
__global__ __launch_bounds__(256) void conv_pair_kernel(
    const float* __restrict__ src, __nv_bfloat16* __restrict__ hi,
    __nv_bfloat16* __restrict__ lo)
{
    int i = blockIdx.x * 256 + threadIdx.x;       // over float4s
    float4 v = ((const float4*)src)[i];
    __nv_bfloat16 h0 = __float2bfloat16(v.x), h1 = __float2bfloat16(v.y);
    __nv_bfloat16 h2 = __float2bfloat16(v.z), h3 = __float2bfloat16(v.w);
    __nv_bfloat16 l0 = __float2bfloat16(v.x - __bfloat162float(h0));
    __nv_bfloat16 l1 = __float2bfloat16(v.y - __bfloat162float(h1));
    __nv_bfloat16 l2 = __float2bfloat16(v.z - __bfloat162float(h2));
    __nv_bfloat16 l3 = __float2bfloat16(v.w - __bfloat162float(h3));
    __nv_bfloat162* hp = (__nv_bfloat162*)(hi + 4*(size_t)i);
    __nv_bfloat162* lp = (__nv_bfloat162*)(lo + 4*(size_t)i);
    hp[0] = __nv_bfloat162(h0, h1); hp[1] = __nv_bfloat162(h2, h3);
    lp[0] = __nv_bfloat162(l0, l1); lp[1] = __nv_bfloat162(l2, l3);
}

// ---------------- W -> W^T hi/lo (32x32 smem tile transpose) ----------------
__global__ __launch_bounds__(256) void conv_wT_kernel(
    const float* __restrict__ Wq, const float* __restrict__ Wk,
    const float* __restrict__ Wv, const float* __restrict__ Wo)
{
    __shared__ float t[32][33];
    const int z = blockIdx.z;
    const float* W = (z == 0) ? Wq : (z == 1) ? Wk : (z == 2) ? Wv : Wo;
    __nv_bfloat16* Th = g_WThi[z];
    __nv_bfloat16* Tl = g_WTlo[z];
    int tx = threadIdx.x & 31, ty = threadIdx.x >> 5;      // 32 x 8
    int n0 = blockIdx.x * 32, k0 = blockIdx.y * 32;
    #pragma unroll
    for (int j = 0; j < 4; j++)
        t[ty + 8*j][tx] = W[(size_t)(k0 + ty + 8*j) * HID + n0 + tx];
    __syncthreads();
    #pragma unroll
    for (int j = 0; j < 4; j++) {
        float v = t[tx][ty + 8*j];
        __nv_bfloat16 h = __float2bfloat16(v);
        __nv_bfloat16 l = __float2bfloat16(v - __bfloat162float(h));
        size_t o = (size_t)(n0 + ty + 8*j) * HID + k0 + tx;
        Th[o] = h;
        Tl[o] = l;
    }
}

// ================= bf16x3 tensor-core GEMM core =================
// C[128,128] tile of A[m][k] @ W^T[n][k]; 256 threads, 8 warps (2m x 4n).
#define GBK 32
#define LDT 40                       // bf16 row stride (80B: ldmatrix conflict-free)
#define BUF_ELEMS (128 * LDT)        // 5120 bf16 per buffer
#define AH_OFS 0
#define ALO_OFS (2 * BUF_ELEMS)
#define BH_OFS  (4 * BUF_ELEMS)
#define BLO_OFS (6 * BUF_ELEMS)
#define GEMM_SMEM_BYTES (8 * BUF_ELEMS * 2)   // 81920

__device__ __forceinline__ void bf16x3_gemm(
    const __nv_bfloat16* __restrict__ Ahi, const __nv_bfloat16* __restrict__ Alo,
    const __nv_bfloat16* __restrict__ Bhi, const __nv_bfloat16* __restrict__ Blo,
    int m0, int n0, __nv_bfloat16* sm, float acc[4][4][4])
{
    const int tid = threadIdx.x;
    const int lane = tid & 31, wid = tid >> 5;
    const int wm = wid >> 2, wn = wid & 3;
    const uint32_t smb = sm_u32(sm);

    #pragma unroll
    for (int mi = 0; mi < 4; mi++)
        #pragma unroll
        for (int ni = 0; ni < 4; ni++)
            #pragma unroll
            for (int r = 0; r < 4; r++) acc[mi][ni][r] = 0.0f;

    // per-thread load slots: two 16B chunks per matrix per K-chunk
    const int c0 = tid, c1 = tid + 256;          // chunk ids 0..511
    const int r0 = c0 >> 2, s0 = c0 & 3;
    const int r1 = c1 >> 2, s1 = c1 & 3;

    auto load_chunk = [&](int kc, int buf) {
        const int k0 = kc * GBK;
        const uint32_t so0 = (uint32_t)(buf * BUF_ELEMS + r0 * LDT + s0 * 8) * 2;
        const uint32_t so1 = (uint32_t)(buf * BUF_ELEMS + r1 * LDT + s1 * 8) * 2;
        const size_t ga0 = (size_t)(m0 + r0) * HID + k0 + s0 * 8;
        const size_t ga1 = (size_t)(m0 + r1) * HID + k0 + s1 * 8;
        const size_t gb0 = (size_t)(n0 + r0) * HID + k0 + s0 * 8;
        const size_t gb1 = (size_t)(n0 + r1) * HID + k0 + s1 * 8;
        CP16(smb + AH_OFS*2  + so0, Ahi + ga0);
        CP16(smb + AH_OFS*2  + so1, Ahi + ga1);
        CP16(smb + ALO_OFS*2 + so0, Alo + ga0);
        CP16(smb + ALO_OFS*2 + so1, Alo + ga1);
        CP16(smb + BH_OFS*2  + so0, Bhi + gb0);
        CP16(smb + BH_OFS*2  + so1, Bhi + gb1);
        CP16(smb + BLO_OFS*2 + so0, Blo + gb0);
        CP16(smb + BLO_OFS*2 + so1, Blo + gb1);
    };

    const int arow = wm * 64 + (lane & 15);
    const int acolb = (lane >> 4) << 3;
    const int brow = wn * 32 + (lane & 7) + ((lane & 16) >> 1);
    const int bcolb = lane & 8;

    load_chunk(0, 0);
    CP_COMMIT();

    for (int kc = 0; kc < HID / GBK; kc++) {
        CP_WAIT0();
        __syncthreads();
        if (kc + 1 < HID / GBK) {
            load_chunk(kc + 1, (kc + 1) & 1);
            CP_COMMIT();
        }
        const int buf = kc & 1;
        #pragma unroll
        for (int ks = 0; ks < 2; ks++) {
            uint32_t ah[4][4], al[4][4], bh[2][4], bl[2][4];
            const int acol = ks * 16 + acolb;
            const int bcol = ks * 16 + bcolb;
            #pragma unroll
            for (int mi = 0; mi < 4; mi++) {
                uint32_t off = (uint32_t)(buf * BUF_ELEMS + (arow + mi*16) * LDT + acol) * 2;
                LDMX4(ah[mi], smb + AH_OFS*2 + off);
                LDMX4(al[mi], smb + ALO_OFS*2 + off);
            }
            #pragma unroll
            for (int p = 0; p < 2; p++) {
                uint32_t off = (uint32_t)(buf * BUF_ELEMS + (brow + p*16) * LDT + bcol) * 2;
                LDMX4(bh[p], smb + BH_OFS*2 + off);
                LDMX4(bl[p], smb + BLO_OFS*2 + off);
            }
            #pragma unroll
            for (int mi = 0; mi < 4; mi++)
                #pragma unroll
                for (int ni = 0; ni < 4; ni++) {
                    uint32_t* bhf = &bh[ni >> 1][(ni & 1) * 2];
                    uint32_t* blf = &bl[ni >> 1][(ni & 1) * 2];
                    MMA16816(acc[mi][ni], ah[mi], bhf);   // hi*hi
                    MMA16816(acc[mi][ni], ah[mi], blf);   // hi*lo
                    MMA16816(acc[mi][ni], al[mi], bhf);   // lo*hi
                }
        }
        __syncthreads();
    }
}

// ---------------- QKV projection via bf16x3 tensor GEMM ----------------
__global__ __launch_bounds__(256) void gemm_qkv_kernel(
    const float* __restrict__ bq, const float* __restrict__ bk,
    const float* __restrict__ bv)
{
    extern __shared__ __nv_bfloat16 sm[];
    const int z = blockIdx.z;
    const float* bias = (z == 0) ? bq : (z == 1) ? bk : bv;
    float* OUT        = (z == 0) ? g_Q : (z == 1) ? g_K : g_V;
    const int m0 = blockIdx.y * 128, n0 = blockIdx.x * 128;

    float acc[4][4][4];
    bf16x3_gemm(g_Ahi, g_Alo, g_WThi[z], g_WTlo[z], m0, n0, sm, acc);

    const int lane = threadIdx.x & 31, wid = threadIdx.x >> 5;
    const int wm = wid >> 2, wn = wid & 3;
    const int g = lane >> 2, tg = lane & 3;
    const float scale = (z == 0) ? 0.125f : 1.0f;

    #pragma unroll
    for (int mi = 0; mi < 4; mi++) {
        #pragma unroll
        for (int ni = 0; ni < 4; ni++) {
            int c = n0 + wn * 32 + ni * 8 + tg * 2;
            int hh = c >> 6, d = c & 63;
            float b0 = bias[c], b1 = bias[c + 1];
            #pragma unroll
            for (int half = 0; half < 2; half++) {
                int m = m0 + wm * 64 + mi * 16 + g + half * 8;
                int bb = m >> 9, n = m & 511;
                float2 v;
                v.x = (acc[mi][ni][half*2 + 0] + b0) * scale;
                v.y = (acc[mi][ni][half*2 + 1] + b1) * scale;
                *(float2*)&OUT[(((size_t)(bb * NH + hh)) * SEQ + n) * HD + d] = v;
            }
        }
    }
}

// ---------------- output projection via bf16x3 tensor GEMM ----------------
__global__ __launch_bounds__(256) void gemm_out_kernel(
    const float* __restrict__ bo, float* __restrict__ OUT)
{
    extern __shared__ __nv_bfloat16 sm[];
    const int m0 = blockIdx.y * 128, n0 = blockIdx.x * 128;

    float acc[4][4][4];
    bf16x3_gemm(g_Ahi, g_Alo, g_WThi[3], g_WTlo[3], m0, n0, sm, acc);

    const int lane = threadIdx.x & 31, wid = threadIdx.x >> 5;
    const int wm = wid >> 2, wn = wid & 3;
    const int g = lane >> 2, tg = lane & 3;

    #pragma unroll
    for (int mi = 0; mi < 4; mi++) {
        #pragma unroll
        for (int ni = 0; ni < 4; ni++) {
            int c = n0 + wn * 32 + ni * 8 + tg * 2;
            float b0 = bo[c], b1 = bo[c + 1];
            #pragma unroll
            for (int half = 0; half < 2; half++) {
                int m = m0 + wm * 64 + mi * 16 + g + half * 8;
                float mf = g_maskf[m];
                float2 v;
                v.x = (mf > 0.5f) ? acc[mi][ni][half*2 + 0] + b0 : 0.0f;
                v.y = (mf > 0.5f) ? acc[mi][ni][half*2 + 1] + b1 : 0.0f;
                *(float2*)&OUT[(size_t)m * HID + c] = v;
            }
        }
    }
}

// ---------------- distance bias: [B*N*N, 64] @ [64, 8] + bd ----------------
__global__ __launch_bounds__(256) void dist_bias_kernel(
    const float* __restrict__ D, const float* __restrict__ Wd,
    const float* __restrict__ bd)
{
    __shared__ float w[64 * 8];
    __shared__ float bsm[8];
    const int tid = threadIdx.x;
    w[tid]       = Wd[tid];
    w[tid + 256] = Wd[tid + 256];
    if (tid < 8) bsm[tid] = bd[tid];
    __syncthreads();

    size_t r = (size_t)blockIdx.x * 256 + tid;
    const float* row = D + r * 64;
    float acc[8] = {0, 0, 0, 0, 0, 0, 0, 0};
    #pragma unroll
    for (int t = 0; t < 16; t++) {
        float4 v = *(const float4*)&row[t * 4];
        float vv[4] = {v.x, v.y, v.z, v.w};
        #pragma unroll
        for (int e = 0; e < 4; e++) {
            int d = t * 4 + e;
            #pragma unroll
            for (int h = 0; h < 8; h++)
                acc[h] = fmaf(vv[e], w[d * 8 + h], acc[h]);
        }
    }
    int b = (int)(r >> 18);
    int rem = (int)(r & 262143);
    int q = rem >> 9, k = rem & 511;
    #pragma unroll
    for (int h = 0; h < 8; h++)
        g_bias[(((size_t)(b * NH + h)) * SEQ + q) * SEQ + k] = acc[h] + bsm[h];
}

// ---------------- flash attention: per (b,h,q-block of 64) ----------------
#define SPAD 68
#define ATTN_SMEM_BYTES (3 * 64 * SPAD * 4)

__device__ __forceinline__ void load_tile_T(float* dstT, const float* __restrict__ src, int tid) {
    #pragma unroll
    for (int j = 0; j < 4; j++) {
        int r  = (tid >> 4) + j * 16;
        int d0 = (tid & 15) * 4;
        float4 v = *(const float4*)&src[r * 64 + d0];
        dstT[(d0 + 0) * SPAD + r] = v.x;
        dstT[(d0 + 1) * SPAD + r] = v.y;
        dstT[(d0 + 2) * SPAD + r] = v.z;
        dstT[(d0 + 3) * SPAD + r] = v.w;
    }
}

__device__ __forceinline__ void load_tile(float* dst, const float* __restrict__ src, int tid) {
    #pragma unroll
    for (int j = 0; j < 4; j++) {
        int r  = (tid >> 4) + j * 16;
        int d0 = (tid & 15) * 4;
        *(float4*)&dst[r * SPAD + d0] = *(const float4*)&src[r * 64 + d0];
    }
}

__global__ __launch_bounds__(256) void attn_kernel() {
    extern __shared__ float smf[];
    float* QsT = smf;
    float* T1  = smf + 64 * SPAD;
    float* Ps  = smf + 2 * 64 * SPAD;

    const int tid = threadIdx.x;
    const int qb = blockIdx.x, h = blockIdx.y, b = blockIdx.z;
    const int bh = b * NH + h;

    const float* Qp = g_Q + ((size_t)bh * SEQ + qb * 64) * HD;
    const float* Kp = g_K + (size_t)bh * SEQ * HD;
    const float* Vp = g_V + (size_t)bh * SEQ * HD;
    const float* Bp = g_bias + ((size_t)bh * SEQ + qb * 64) * SEQ;
    const float* Mp = g_maskf + b * SEQ;

    load_tile_T(QsT, Qp, tid);

    const int ty = tid >> 4, tx = tid & 15;
    const int r0 = ty * 4, c0 = tx * 4;

    float o[4][4] = {};
    float mrun[4] = {-3.0e38f, -3.0e38f, -3.0e38f, -3.0e38f};
    float lrun[4] = {};

    for (int kb = 0; kb < 8; kb++) {
        __syncthreads();
        load_tile_T(T1, Kp + (size_t)kb * 64 * HD, tid);
        __syncthreads();

        float s[4][4] = {};
        #pragma unroll 8
        for (int k = 0; k < 64; k++) {
            float4 qv = *(float4*)&QsT[k * SPAD + r0];
            float4 kv = *(float4*)&T1[k * SPAD + c0];
            s[0][0] = fmaf(qv.x, kv.x, s[0][0]); s[0][1] = fmaf(qv.x, kv.y, s[0][1]);
            s[0][2] = fmaf(qv.x, kv.z, s[0][2]); s[0][3] = fmaf(qv.x, kv.w, s[0][3]);
            s[1][0] = fmaf(qv.y, kv.x, s[1][0]); s[1][1] = fmaf(qv.y, kv.y, s[1][1]);
            s[1][2] = fmaf(qv.y, kv.z, s[1][2]); s[1][3] = fmaf(qv.y, kv.w, s[1][3]);
            s[2][0] = fmaf(qv.z, kv.x, s[2][0]); s[2][1] = fmaf(qv.z, kv.y, s[2][1]);
            s[2][2] = fmaf(qv.z, kv.z, s[2][2]); s[2][3] = fmaf(qv.z, kv.w, s[2][3]);
            s[3][0] = fmaf(qv.w, kv.x, s[3][0]); s[3][1] = fmaf(qv.w, kv.y, s[3][1]);
            s[3][2] = fmaf(qv.w, kv.z, s[3][2]); s[3][3] = fmaf(qv.w, kv.w, s[3][3]);
        }

        float4 km = *(const float4*)&Mp[kb * 64 + c0];
        float kmv[4] = {km.x, km.y, km.z, km.w};
        #pragma unroll
        for (int i = 0; i < 4; i++) {
            float4 b4 = *(const float4*)&Bp[(size_t)(r0 + i) * SEQ + kb * 64 + c0];
            float sv[4];
            sv[0] = (kmv[0] > 0.5f) ? s[i][0] + b4.x : -1e9f;
            sv[1] = (kmv[1] > 0.5f) ? s[i][1] + b4.y : -1e9f;
            sv[2] = (kmv[2] > 0.5f) ? s[i][2] + b4.z : -1e9f;
            sv[3] = (kmv[3] > 0.5f) ? s[i][3] + b4.w : -1e9f;
            float rm = fmaxf(fmaxf(sv[0], sv[1]), fmaxf(sv[2], sv[3]));
            #pragma unroll
            for (int off = 8; off; off >>= 1)
                rm = fmaxf(rm, __shfl_xor_sync(0xffffffffu, rm, off, 16));
            float newm = fmaxf(mrun[i], rm);
            float corr = __expf(mrun[i] - newm);
            mrun[i] = newm;
            float p0 = __expf(sv[0] - newm);
            float p1 = __expf(sv[1] - newm);
            float p2 = __expf(sv[2] - newm);
            float p3 = __expf(sv[3] - newm);
            float rs = (p0 + p1) + (p2 + p3);
            #pragma unroll
            for (int off = 8; off; off >>= 1)
                rs += __shfl_xor_sync(0xffffffffu, rs, off, 16);
            lrun[i] = lrun[i] * corr + rs;
            o[i][0] *= corr; o[i][1] *= corr; o[i][2] *= corr; o[i][3] *= corr;
            *(float4*)&Ps[(r0 + i) * SPAD + c0] = make_float4(p0, p1, p2, p3);
        }

        __syncthreads();
        load_tile(T1, Vp + (size_t)kb * 64 * HD, tid);
        __syncthreads();

        #pragma unroll 8
        for (int k = 0; k < 64; k++) {
            float pa = Ps[(r0 + 0) * SPAD + k];
            float pb = Ps[(r0 + 1) * SPAD + k];
            float pc = Ps[(r0 + 2) * SPAD + k];
            float pd = Ps[(r0 + 3) * SPAD + k];
            float4 vv = *(float4*)&T1[k * SPAD + c0];
            o[0][0] = fmaf(pa, vv.x, o[0][0]); o[0][1] = fmaf(pa, vv.y, o[0][1]);
            o[0][2] = fmaf(pa, vv.z, o[0][2]); o[0][3] = fmaf(pa, vv.w, o[0][3]);
            o[1][0] = fmaf(pb, vv.x, o[1][0]); o[1][1] = fmaf(pb, vv.y, o[1][1]);
            o[1][2] = fmaf(pb, vv.z, o[1][2]); o[1][3] = fmaf(pb, vv.w, o[1][3]);
            o[2][0] = fmaf(pc, vv.x, o[2][0]); o[2][1] = fmaf(pc, vv.y, o[2][1]);
            o[2][2] = fmaf(pc, vv.z, o[2][2]); o[2][3] = fmaf(pc, vv.w, o[2][3]);
            o[3][0] = fmaf(pd, vv.x, o[3][0]); o[3][1] = fmaf(pd, vv.y, o[3][1]);
            o[3][2] = fmaf(pd, vv.z, o[3][2]); o[3][3] = fmaf(pd, vv.w, o[3][3]);
        }
    }

    #pragma unroll
    for (int i = 0; i < 4; i++) {
        float inv = 1.0f / lrun[i];
        size_t m = (size_t)b * SEQ + qb * 64 + r0 + i;
        #pragma unroll
        for (int j = 0; j < 4; j++)
            g_ctx[m * HID + h * HD + c0 + j] = o[i][j] * inv;
    }
}

// ---------------- launch ----------------
extern "C" void kernel_launch(void* const* d_in, const int* in_sizes, int n_in,
                              void* d_out, int out_size)
{
    const float* x    = (const float*)d_in[0];
    const float* dist = (const float*)d_in[1];
    const unsigned char* mask = (const unsigned char*)d_in[2];
    const float* Wq = (const float*)d_in[3];
    const float* bq = (const float*)d_in[4];
    const float* Wk = (const float*)d_in[5];
    const float* bk = (const float*)d_in[6];
    const float* Wv = (const float*)d_in[7];
    const float* bv = (const float*)d_in[8];
    const float* Wo = (const float*)d_in[9];
    const float* bo = (const float*)d_in[10];
    const float* Wd = (const float*)d_in[11];
    const float* bd = (const float*)d_in[12];
    float* out = (float*)d_out;

    cudaFuncSetAttribute(attn_kernel, cudaFuncAttributeMaxDynamicSharedMemorySize,
                         ATTN_SMEM_BYTES);
    cudaFuncSetAttribute(gemm_qkv_kernel, cudaFuncAttributeMaxDynamicSharedMemorySize,
                         GEMM_SMEM_BYTES);
    cudaFuncSetAttribute(gemm_out_kernel, cudaFuncAttributeMaxDynamicSharedMemorySize,
                         GEMM_SMEM_BYTES);

    float* ctx_ptr = 0;
    cudaGetSymbolAddress((void**)&ctx_ptr, g_ctx);
    __nv_bfloat16 *ahi_ptr = 0, *alo_ptr = 0;
    cudaGetSymbolAddress((void**)&ahi_ptr, g_Ahi);
    cudaGetSymbolAddress((void**)&alo_ptr, g_Alo);

    mask_convert_kernel<<<1, 256>>>(mask);
    conv_pair_kernel<<<2048, 256>>>(x, ahi_ptr, alo_ptr);
    conv_wT_kernel<<<dim3(16, 16, 4), 256>>>(Wq, Wk, Wv, Wo);
    gemm_qkv_kernel<<<dim3(4, 32, 3), 256, GEMM_SMEM_BYTES>>>(bq, bk, bv);
    dist_bias_kernel<<<8192, 256>>>(dist, Wd, bd);
    attn_kernel<<<dim3(8, NH, NB), 256, ATTN_SMEM_BYTES>>>();
    conv_pair_kernel<<<2048, 256>>>(ctx_ptr, ahi_ptr, alo_ptr);
    gemm_out_kernel<<<dim3(4, 32), 256, GEMM_SMEM_BYTES>>>(bo, out);
}

// round 5
// speedup vs baseline: 1.9173x; 1.0669x over previous
#include <cuda_runtime.h>
#include <cuda_bf16.h>
#include <stdint.h>
#include <math.h>

#define NB 8
#define NH 8
#define SEQ 512
#define HID 512
#define HD 64

// ---------------- scratch (device globals; no allocations) ----------------
__device__ float g_maskf[NB*SEQ];                       // 0/1 floats
__device__ __nv_bfloat16 g_biasb[(size_t)NB*NH*SEQ*SEQ]; // 32 MB bf16 bias
__device__ __nv_bfloat16 g_Qh[NB*NH*SEQ*HD], g_Ql[NB*NH*SEQ*HD];   // [b,h,n,d]
__device__ __nv_bfloat16 g_Kh[NB*NH*SEQ*HD], g_Kl[NB*NH*SEQ*HD];   // [b,h,n,d]
__device__ __nv_bfloat16 g_VTh[NB*NH*SEQ*HD], g_VTl[NB*NH*SEQ*HD]; // [b,h,d,n]
__device__ __nv_bfloat16 g_Ahi[NB*SEQ*HID], g_Alo[NB*SEQ*HID];     // x / ctx
__device__ __nv_bfloat16 g_WThi[4][HID*HID], g_WTlo[4][HID*HID];   // W^T [n][k]

// ---------------- PTX helpers ----------------
__device__ __forceinline__ uint32_t sm_u32(const void* p) {
    return (uint32_t)__cvta_generic_to_shared(p);
}
#define CP16(dst_u32, gptr) \
    asm volatile("cp.async.ca.shared.global [%0], [%1], 16;" :: "r"(dst_u32), "l"(gptr))
#define CP_COMMIT() asm volatile("cp.async.commit_group;")
#define CP_WAIT0()  asm volatile("cp.async.wait_group 0;")
#define LDMX4(r, addr) \
    asm volatile("ldmatrix.sync.aligned.m8n8.x4.shared.b16 {%0,%1,%2,%3}, [%4];" \
        : "=r"((r)[0]), "=r"((r)[1]), "=r"((r)[2]), "=r"((r)[3]) : "r"(addr))
#define MMA16816(d, a, b) \
    asm volatile("mma.sync.aligned.m16n8k16.row.col.f32.bf16.bf16.f32 " \
        "{%0,%1,%2,%3},{%4,%5,%6,%7},{%8,%9},{%0,%1,%2,%3};\n" \
        : "+f"((d)[0]), "+f"((d)[1]), "+f"((d)[2]), "+f"((d)[3]) \
        : "r"((a)[0]), "r"((a)[1]), "r"((a)[2]), "r"((a)[3]), "r"((b)[0]), "r"((b)[1]))

__device__ __forceinline__ uint32_t pack_bf16x2(float lo, float hi) {
    __nv_bfloat16 l = __float2bfloat16(lo), h = __float2bfloat16(hi);
    return ((uint32_t)__bfloat16_as_ushort(h) << 16) | (uint32_t)__bfloat16_as_ushort(l);
}
// split pair (a=elem0, b=elem1) into packed bf16x2 hi and lo residual
__device__ __forceinline__ void split2(float a, float b, uint32_t& hi, uint32_t& lo) {
    __nv_bfloat16 ha = __float2bfloat16(a), hb = __float2bfloat16(b);
    __nv_bfloat16 la = __float2bfloat16(a - __bfloat162float(ha));
    __nv_bfloat16 lb = __float2bfloat16(b - __bfloat162float(hb));
    hi = ((uint32_t)__bfloat16_as_ushort(hb) << 16) | (uint32_t)__bfloat16_as_ushort(ha);
    lo = ((uint32_t)__bfloat16_as_ushort(lb) << 16) | (uint32_t)__bfloat16_as_ushort(la);
}

// ---------------- mask normalization (dtype-agnostic) ----------------
__global__ void mask_convert_kernel(const unsigned char* __restrict__ raw) {
    __shared__ int mode;
    if (threadIdx.x == 0) {
        const unsigned int* w = (const unsigned int*)raw;
        int cf = 0, byteish = 0;
        for (int i = 0; i < 128; i++) {
            unsigned int v = w[i];
            if (v == 0x3F800000u) cf++;
            bool b01 = true;
            #pragma unroll
            for (int bb = 0; bb < 4; bb++) {
                unsigned int by = (v >> (8*bb)) & 0xFFu;
                if (by > 1u) b01 = false;
            }
            if (b01 && v > 1u) byteish++;
        }
        mode = (cf > 64) ? 0 : ((byteish > 0) ? 2 : 1);  // 0=f32, 1=i32, 2=u8
    }
    __syncthreads();
    int md = mode;
    for (int i = threadIdx.x; i < NB*SEQ; i += blockDim.x) {
        float m;
        if (md == 0)      m = (((const float*)raw)[i] != 0.0f) ? 1.0f : 0.0f;
        else if (md == 1) m = (((const int*)raw)[i]   != 0)    ? 1.0f : 0.0f;
        else              m = (raw[i]                 != 0)    ? 1.0f : 0.0f;
        g_maskf[i] = m;
    }
}

// ---------------- hi/lo bf16 split of a dense f32 array ----------------
__global__ __launch_bounds__(256) void conv_pair_kernel(
    const float* __restrict__ src, __nv_bfloat16* __restrict__ hi,
    __nv_bfloat16* __restrict__ lo)
{
    int i = blockIdx.x * 256 + threadIdx.x;       // over float4s
    float4 v = ((const float4*)src)[i];
    uint32_t h0, l0, h1, l1;
    split2(v.x, v.y, h0, l0);
    split2(v.z, v.w, h1, l1);
    uint32_t* hp = (uint32_t*)(hi + 4*(size_t)i);
    uint32_t* lp = (uint32_t*)(lo + 4*(size_t)i);
    hp[0] = h0; hp[1] = h1;
    lp[0] = l0; lp[1] = l1;
}

// ---------------- W -> W^T hi/lo (32x32 smem tile transpose) ----------------
__global__ __launch_bounds__(256) void conv_wT_kernel(
    const float* __restrict__ Wq, const float* __restrict__ Wk,
    const float* __restrict__ Wv, const float* __restrict__ Wo)
{
    __shared__ float t[32][33];
    const int z = blockIdx.z;
    const float* W = (z == 0) ? Wq : (z == 1) ? Wk : (z == 2) ? Wv : Wo;
    __nv_bfloat16* Th = g_WThi[z];
    __nv_bfloat16* Tl = g_WTlo[z];
    int tx = threadIdx.x & 31, ty = threadIdx.x >> 5;      // 32 x 8
    int n0 = blockIdx.x * 32, k0 = blockIdx.y * 32;
    #pragma unroll
    for (int j = 0; j < 4; j++)
        t[ty + 8*j][tx] = W[(size_t)(k0 + ty + 8*j) * HID + n0 + tx];
    __syncthreads();
    #pragma unroll
    for (int j = 0; j < 4; j++) {
        float v = t[tx][ty + 8*j];
        __nv_bfloat16 h = __float2bfloat16(v);
        __nv_bfloat16 l = __float2bfloat16(v - __bfloat162float(h));
        size_t o = (size_t)(n0 + ty + 8*j) * HID + k0 + tx;
        Th[o] = h;
        Tl[o] = l;
    }
}

// ================= bf16x3 tensor-core GEMM core (verified R4) =============
#define GBK 32
#define LDT 40
#define BUF_ELEMS (128 * LDT)
#define AH_OFS 0
#define ALO_OFS (2 * BUF_ELEMS)
#define BH_OFS  (4 * BUF_ELEMS)
#define BLO_OFS (6 * BUF_ELEMS)
#define GEMM_SMEM_BYTES (8 * BUF_ELEMS * 2)

__device__ __forceinline__ void bf16x3_gemm(
    const __nv_bfloat16* __restrict__ Ahi, const __nv_bfloat16* __restrict__ Alo,
    const __nv_bfloat16* __restrict__ Bhi, const __nv_bfloat16* __restrict__ Blo,
    int m0, int n0, __nv_bfloat16* sm, float acc[4][4][4])
{
    const int tid = threadIdx.x;
    const int lane = tid & 31, wid = tid >> 5;
    const int wm = wid >> 2, wn = wid & 3;
    const uint32_t smb = sm_u32(sm);

    #pragma unroll
    for (int mi = 0; mi < 4; mi++)
        #pragma unroll
        for (int ni = 0; ni < 4; ni++)
            #pragma unroll
            for (int r = 0; r < 4; r++) acc[mi][ni][r] = 0.0f;

    const int c0 = tid, c1 = tid + 256;
    const int r0 = c0 >> 2, s0 = c0 & 3;
    const int r1 = c1 >> 2, s1 = c1 & 3;

    auto load_chunk = [&](int kc, int buf) {
        const int k0 = kc * GBK;
        const uint32_t so0 = (uint32_t)(buf * BUF_ELEMS + r0 * LDT + s0 * 8) * 2;
        const uint32_t so1 = (uint32_t)(buf * BUF_ELEMS + r1 * LDT + s1 * 8) * 2;
        const size_t ga0 = (size_t)(m0 + r0) * HID + k0 + s0 * 8;
        const size_t ga1 = (size_t)(m0 + r1) * HID + k0 + s1 * 8;
        const size_t gb0 = (size_t)(n0 + r0) * HID + k0 + s0 * 8;
        const size_t gb1 = (size_t)(n0 + r1) * HID + k0 + s1 * 8;
        CP16(smb + AH_OFS*2  + so0, Ahi + ga0);
        CP16(smb + AH_OFS*2  + so1, Ahi + ga1);
        CP16(smb + ALO_OFS*2 + so0, Alo + ga0);
        CP16(smb + ALO_OFS*2 + so1, Alo + ga1);
        CP16(smb + BH_OFS*2  + so0, Bhi + gb0);
        CP16(smb + BH_OFS*2  + so1, Bhi + gb1);
        CP16(smb + BLO_OFS*2 + so0, Blo + gb0);
        CP16(smb + BLO_OFS*2 + so1, Blo + gb1);
    };

    const int arow = wm * 64 + (lane & 15);
    const int acolb = (lane >> 4) << 3;
    const int brow = wn * 32 + (lane & 7) + ((lane & 16) >> 1);
    const int bcolb = lane & 8;

    load_chunk(0, 0);
    CP_COMMIT();

    for (int kc = 0; kc < HID / GBK; kc++) {
        CP_WAIT0();
        __syncthreads();
        if (kc + 1 < HID / GBK) {
            load_chunk(kc + 1, (kc + 1) & 1);
            CP_COMMIT();
        }
        const int buf = kc & 1;
        #pragma unroll
        for (int ks = 0; ks < 2; ks++) {
            uint32_t ah[4][4], al[4][4], bh[2][4], bl[2][4];
            const int acol = ks * 16 + acolb;
            const int bcol = ks * 16 + bcolb;
            #pragma unroll
            for (int mi = 0; mi < 4; mi++) {
                uint32_t off = (uint32_t)(buf * BUF_ELEMS + (arow + mi*16) * LDT + acol) * 2;
                LDMX4(ah[mi], smb + AH_OFS*2 + off);
                LDMX4(al[mi], smb + ALO_OFS*2 + off);
            }
            #pragma unroll
            for (int p = 0; p < 2; p++) {
                uint32_t off = (uint32_t)(buf * BUF_ELEMS + (brow + p*16) * LDT + bcol) * 2;
                LDMX4(bh[p], smb + BH_OFS*2 + off);
                LDMX4(bl[p], smb + BLO_OFS*2 + off);
            }
            #pragma unroll
            for (int mi = 0; mi < 4; mi++)
                #pragma unroll
                for (int ni = 0; ni < 4; ni++) {
                    uint32_t* bhf = &bh[ni >> 1][(ni & 1) * 2];
                    uint32_t* blf = &bl[ni >> 1][(ni & 1) * 2];
                    MMA16816(acc[mi][ni], ah[mi], bhf);
                    MMA16816(acc[mi][ni], ah[mi], blf);
                    MMA16816(acc[mi][ni], al[mi], bhf);
                }
        }
        __syncthreads();
    }
}

// ---------------- QKV projection: epilogue writes bf16 hi/lo ----------------
__global__ __launch_bounds__(256) void gemm_qkv_kernel(
    const float* __restrict__ bq, const float* __restrict__ bk,
    const float* __restrict__ bv)
{
    extern __shared__ __nv_bfloat16 sm[];
    const int z = blockIdx.z;
    const float* bias = (z == 0) ? bq : (z == 1) ? bk : bv;
    const int m0 = blockIdx.y * 128, n0 = blockIdx.x * 128;

    float acc[4][4][4];
    bf16x3_gemm(g_Ahi, g_Alo, g_WThi[z], g_WTlo[z], m0, n0, sm, acc);

    const int lane = threadIdx.x & 31, wid = threadIdx.x >> 5;
    const int wm = wid >> 2, wn = wid & 3;
    const int g = lane >> 2, tg = lane & 3;
    const float scale = (z == 0) ? 0.125f : 1.0f;

    __nv_bfloat16* OUTh = (z == 0) ? g_Qh : g_Kh;
    __nv_bfloat16* OUTl = (z == 0) ? g_Ql : g_Kl;

    #pragma unroll
    for (int mi = 0; mi < 4; mi++) {
        #pragma unroll
        for (int ni = 0; ni < 4; ni++) {
            int c = n0 + wn * 32 + ni * 8 + tg * 2;
            int hh = c >> 6, d = c & 63;
            float b0 = bias[c], b1 = bias[c + 1];
            #pragma unroll
            for (int half = 0; half < 2; half++) {
                int m = m0 + wm * 64 + mi * 16 + g + half * 8;
                int bb = m >> 9, n = m & 511;
                int bh = bb * NH + hh;
                float v0 = (acc[mi][ni][half*2 + 0] + b0) * scale;
                float v1 = (acc[mi][ni][half*2 + 1] + b1) * scale;
                if (z < 2) {
                    uint32_t hiw, low;
                    split2(v0, v1, hiw, low);
                    size_t a = ((size_t)bh * SEQ + n) * HD + d;
                    *(uint32_t*)&OUTh[a] = hiw;
                    *(uint32_t*)&OUTl[a] = low;
                } else {
                    // V stored transposed: [b,h,d,n]
                    __nv_bfloat16 h0 = __float2bfloat16(v0);
                    __nv_bfloat16 l0 = __float2bfloat16(v0 - __bfloat162float(h0));
                    __nv_bfloat16 h1 = __float2bfloat16(v1);
                    __nv_bfloat16 l1 = __float2bfloat16(v1 - __bfloat162float(h1));
                    size_t a0 = ((size_t)bh * HD + d) * SEQ + n;
                    g_VTh[a0] = h0;  g_VTl[a0] = l0;
                    g_VTh[a0 + SEQ] = h1;  g_VTl[a0 + SEQ] = l1;
                }
            }
        }
    }
}

// ---------------- output projection (reads ctx hi/lo written by attn) ------
__global__ __launch_bounds__(256) void gemm_out_kernel(
    const float* __restrict__ bo, float* __restrict__ OUT)
{
    extern __shared__ __nv_bfloat16 sm[];
    const int m0 = blockIdx.y * 128, n0 = blockIdx.x * 128;

    float acc[4][4][4];
    bf16x3_gemm(g_Ahi, g_Alo, g_WThi[3], g_WTlo[3], m0, n0, sm, acc);

    const int lane = threadIdx.x & 31, wid = threadIdx.x >> 5;
    const int wm = wid >> 2, wn = wid & 3;
    const int g = lane >> 2, tg = lane & 3;

    #pragma unroll
    for (int mi = 0; mi < 4; mi++) {
        #pragma unroll
        for (int ni = 0; ni < 4; ni++) {
            int c = n0 + wn * 32 + ni * 8 + tg * 2;
            float b0 = bo[c], b1 = bo[c + 1];
            #pragma unroll
            for (int half = 0; half < 2; half++) {
                int m = m0 + wm * 64 + mi * 16 + g + half * 8;
                float mf = g_maskf[m];
                float2 v;
                v.x = (mf > 0.5f) ? acc[mi][ni][half*2 + 0] + b0 : 0.0f;
                v.y = (mf > 0.5f) ? acc[mi][ni][half*2 + 1] + b1 : 0.0f;
                *(float2*)&OUT[(size_t)m * HID + c] = v;
            }
        }
    }
}

// ---------------- distance bias: [B*N*N, 64] @ [64, 8] + bd -> bf16 --------
__global__ __launch_bounds__(256) void dist_bias_kernel(
    const float* __restrict__ D, const float* __restrict__ Wd,
    const float* __restrict__ bd)
{
    __shared__ float w[64 * 8];
    __shared__ float bsm[8];
    const int tid = threadIdx.x;
    w[tid]       = Wd[tid];
    w[tid + 256] = Wd[tid + 256];
    if (tid < 8) bsm[tid] = bd[tid];
    __syncthreads();

    size_t r = (size_t)blockIdx.x * 256 + tid;       // row over B*N*N
    const float* row = D + r * 64;
    float acc[8] = {0, 0, 0, 0, 0, 0, 0, 0};
    #pragma unroll
    for (int t = 0; t < 16; t++) {
        float4 v = __ldcs((const float4*)&row[t * 4]);
        float vv[4] = {v.x, v.y, v.z, v.w};
        #pragma unroll
        for (int e = 0; e < 4; e++) {
            int d = t * 4 + e;
            #pragma unroll
            for (int h = 0; h < 8; h++)
                acc[h] = fmaf(vv[e], w[d * 8 + h], acc[h]);
        }
    }
    int b = (int)(r >> 18);
    int rem = (int)(r & 262143);
    int q = rem >> 9, k = rem & 511;
    #pragma unroll
    for (int h = 0; h < 8; h++)
        g_biasb[(((size_t)(b * NH + h)) * SEQ + q) * SEQ + k] =
            __float2bfloat16(acc[h] + bsm[h]);
}

// ============ tensor-core flash attention: CTA = (qb64, h, b) ==============
#define AT_LD 72                      // bf16 row stride (144B, ldmatrix-safe)
#define O_QH 0
#define O_QL 4608
#define O_KH 9216                     // [2][4608]
#define O_KL 18432
#define O_VH 27648
#define O_VL 36864
#define AT_MADD_B 92160
#define ATTN_SMEM_BYTES (92160 + 2048)

__device__ __forceinline__ void attn_load_kv(
    uint32_t smb, int buf, int kb, int tid,
    const __nv_bfloat16* Kh, const __nv_bfloat16* Kl,
    const __nv_bfloat16* Vh, const __nv_bfloat16* Vl)
{
    const uint32_t bo = (uint32_t)(buf * 4608 * 2);
    #pragma unroll
    for (int j = 0; j < 4; j++) {
        int ch = j * 128 + tid;
        int r = ch >> 3, cc = ch & 7;
        uint32_t so = (uint32_t)((r * AT_LD + cc * 8) * 2);
        size_t gk = (size_t)(kb * 64 + r) * HD + cc * 8;   // K: [key][d]
        size_t gv = (size_t)r * SEQ + kb * 64 + cc * 8;    // VT: [d][key]
        CP16(smb + O_KH*2 + bo + so, Kh + gk);
        CP16(smb + O_KL*2 + bo + so, Kl + gk);
        CP16(smb + O_VH*2 + bo + so, Vh + gv);
        CP16(smb + O_VL*2 + bo + so, Vl + gv);
    }
}

__global__ __launch_bounds__(128) void attn_mma_kernel() {
    extern __shared__ __nv_bfloat16 smB[];
    float* madd = (float*)((char*)smB + AT_MADD_B);
    const uint32_t smb = sm_u32(smB);
    const int tid = threadIdx.x, lane = tid & 31, w = tid >> 5;
    const int qb = blockIdx.x, h = blockIdx.y, b = blockIdx.z;
    const int bh = b * NH + h;
    const int g = lane >> 2, t4 = lane & 3;

    const __nv_bfloat16* Qh = g_Qh + ((size_t)bh * SEQ + qb * 64) * HD;
    const __nv_bfloat16* Ql = g_Ql + ((size_t)bh * SEQ + qb * 64) * HD;
    const __nv_bfloat16* Kh = g_Kh + (size_t)bh * SEQ * HD;
    const __nv_bfloat16* Kl = g_Kl + (size_t)bh * SEQ * HD;
    const __nv_bfloat16* Vh = g_VTh + (size_t)bh * HD * SEQ;
    const __nv_bfloat16* Vl = g_VTl + (size_t)bh * HD * SEQ;
    const __nv_bfloat16* Bb = g_biasb + ((size_t)bh * SEQ + qb * 64) * SEQ;

    // additive key mask into smem
    #pragma unroll
    for (int j = 0; j < 4; j++) {
        int i = j * 128 + tid;
        madd[i] = (g_maskf[b * SEQ + i] > 0.5f) ? 0.0f : -1e9f;
    }

    // Q tiles + first KV tile
    #pragma unroll
    for (int j = 0; j < 4; j++) {
        int ch = j * 128 + tid;
        int r = ch >> 3, cc = ch & 7;
        uint32_t so = (uint32_t)((r * AT_LD + cc * 8) * 2);
        CP16(smb + O_QH*2 + so, Qh + (size_t)r * HD + cc * 8);
        CP16(smb + O_QL*2 + so, Ql + (size_t)r * HD + cc * 8);
    }
    attn_load_kv(smb, 0, 0, tid, Kh, Kl, Vh, Vl);
    CP_COMMIT();
    CP_WAIT0();
    __syncthreads();

    // Q fragments (A, m16k16 per k-step), hi+lo
    uint32_t qh[4][4], ql[4][4];
    {
        int arow = w * 16 + (lane & 15);
        int acolb = (lane >> 4) << 3;
        #pragma unroll
        for (int ks = 0; ks < 4; ks++) {
            uint32_t off = (uint32_t)((arow * AT_LD + ks * 16 + acolb) * 2);
            LDMX4(qh[ks], smb + O_QH*2 + off);
            LDMX4(ql[ks], smb + O_QL*2 + off);
        }
    }

    float o[4][2][4];
    #pragma unroll
    for (int i = 0; i < 4; i++)
        #pragma unroll
        for (int j = 0; j < 2; j++)
            #pragma unroll
            for (int r = 0; r < 4; r++) o[i][j][r] = 0.0f;
    float mrun[2] = {-1e30f, -1e30f}, lrun[2] = {0.0f, 0.0f};

    const int browc = (lane & 7) + ((lane & 16) >> 1);
    const int bcolc = lane & 8;

    for (int kb = 0; kb < 8; kb++) {
        if (kb > 0) { CP_WAIT0(); __syncthreads(); }
        if (kb + 1 < 8) {
            attn_load_kv(smb, (kb + 1) & 1, kb + 1, tid, Kh, Kl, Vh, Vl);
            CP_COMMIT();
        }
        const uint32_t bufo = (uint32_t)((kb & 1) * 4608 * 2);

        // ---- S = Q K^T (bf16x3) + bias + mask ----
        float sv[2][16];
        #pragma unroll
        for (int ni2 = 0; ni2 < 4; ni2++) {
            float s0[4] = {0, 0, 0, 0}, s1[4] = {0, 0, 0, 0};
            #pragma unroll
            for (int ks = 0; ks < 4; ks++) {
                uint32_t off = (uint32_t)(((ni2 * 16 + browc) * AT_LD + ks * 16 + bcolc) * 2);
                uint32_t kh4[4], kl4[4];
                LDMX4(kh4, smb + O_KH*2 + bufo + off);
                LDMX4(kl4, smb + O_KL*2 + bufo + off);
                MMA16816(s0, qh[ks], &kh4[0]);
                MMA16816(s0, qh[ks], &kl4[0]);
                MMA16816(s0, ql[ks], &kh4[0]);
                MMA16816(s1, qh[ks], &kh4[2]);
                MMA16816(s1, qh[ks], &kl4[2]);
                MMA16816(s1, ql[ks], &kh4[2]);
            }
            #pragma unroll
            for (int n8p = 0; n8p < 2; n8p++) {
                const float* sp = n8p ? s1 : s0;
                int col = kb * 64 + ni2 * 16 + n8p * 8 + t4 * 2;
                float2 mm = *(float2*)&madd[col];
                #pragma unroll
                for (int rh = 0; rh < 2; rh++) {
                    __nv_bfloat162 bb = *(const __nv_bfloat162*)
                        &Bb[(size_t)(w * 16 + g + rh * 8) * SEQ + col];
                    sv[rh][ni2*4 + n8p*2 + 0] = sp[rh*2 + 0] + __low2float(bb)  + mm.x;
                    sv[rh][ni2*4 + n8p*2 + 1] = sp[rh*2 + 1] + __high2float(bb) + mm.y;
                }
            }
        }

        // ---- online softmax ----
        float corr[2];
        #pragma unroll
        for (int rh = 0; rh < 2; rh++) {
            float rmx = -1e30f;
            #pragma unroll
            for (int i = 0; i < 16; i++) rmx = fmaxf(rmx, sv[rh][i]);
            rmx = fmaxf(rmx, __shfl_xor_sync(0xffffffffu, rmx, 1));
            rmx = fmaxf(rmx, __shfl_xor_sync(0xffffffffu, rmx, 2));
            float mnew = fmaxf(mrun[rh], rmx);
            corr[rh] = __expf(mrun[rh] - mnew);
            mrun[rh] = mnew;
            float rs = 0.0f;
            #pragma unroll
            for (int i = 0; i < 16; i++) {
                float p = __expf(sv[rh][i] - mnew);
                sv[rh][i] = p;
                rs += p;
            }
            rs += __shfl_xor_sync(0xffffffffu, rs, 1);
            rs += __shfl_xor_sync(0xffffffffu, rs, 2);
            lrun[rh] = lrun[rh] * corr[rh] + rs;
        }
        #pragma unroll
        for (int ni2 = 0; ni2 < 4; ni2++)
            #pragma unroll
            for (int n8p = 0; n8p < 2; n8p++) {
                o[ni2][n8p][0] *= corr[0];
                o[ni2][n8p][1] *= corr[0];
                o[ni2][n8p][2] *= corr[1];
                o[ni2][n8p][3] *= corr[1];
            }

        // ---- P fragments (hi/lo) from S accumulator layout ----
        uint32_t ph[4][4], pl[4][4];
        #pragma unroll
        for (int ks = 0; ks < 4; ks++) {
            split2(sv[0][ks*4 + 0], sv[0][ks*4 + 1], ph[ks][0], pl[ks][0]);
            split2(sv[1][ks*4 + 0], sv[1][ks*4 + 1], ph[ks][1], pl[ks][1]);
            split2(sv[0][ks*4 + 2], sv[0][ks*4 + 3], ph[ks][2], pl[ks][2]);
            split2(sv[1][ks*4 + 2], sv[1][ks*4 + 3], ph[ks][3], pl[ks][3]);
        }

        // ---- O += P V (bf16x3), B = V^T tiles [d][key] ----
        #pragma unroll
        for (int ni2 = 0; ni2 < 4; ni2++) {
            #pragma unroll
            for (int ks = 0; ks < 4; ks++) {
                uint32_t off = (uint32_t)(((ni2 * 16 + browc) * AT_LD + ks * 16 + bcolc) * 2);
                uint32_t vh4[4], vl4[4];
                LDMX4(vh4, smb + O_VH*2 + bufo + off);
                LDMX4(vl4, smb + O_VL*2 + bufo + off);
                MMA16816(o[ni2][0], ph[ks], &vh4[0]);
                MMA16816(o[ni2][0], ph[ks], &vl4[0]);
                MMA16816(o[ni2][0], pl[ks], &vh4[0]);
                MMA16816(o[ni2][1], ph[ks], &vh4[2]);
                MMA16816(o[ni2][1], ph[ks], &vl4[2]);
                MMA16816(o[ni2][1], pl[ks], &vh4[2]);
            }
        }
    }

    // ---- epilogue: normalize, split hi/lo, write ctx ----
    float inv[2] = {1.0f / lrun[0], 1.0f / lrun[1]};
    #pragma unroll
    for (int ni2 = 0; ni2 < 4; ni2++) {
        #pragma unroll
        for (int n8p = 0; n8p < 2; n8p++) {
            int col = h * 64 + ni2 * 16 + n8p * 8 + t4 * 2;
            #pragma unroll
            for (int rh = 0; rh < 2; rh++) {
                size_t m = (size_t)b * SEQ + qb * 64 + w * 16 + g + rh * 8;
                float v0 = o[ni2][n8p][rh*2 + 0] * inv[rh];
                float v1 = o[ni2][n8p][rh*2 + 1] * inv[rh];
                uint32_t hiw, low;
                split2(v0, v1, hiw, low);
                *(uint32_t*)&g_Ahi[m * HID + col] = hiw;
                *(uint32_t*)&g_Alo[m * HID + col] = low;
            }
        }
    }
}

// ---------------- launch ----------------
extern "C" void kernel_launch(void* const* d_in, const int* in_sizes, int n_in,
                              void* d_out, int out_size)
{
    const float* x    = (const float*)d_in[0];
    const float* dist = (const float*)d_in[1];
    const unsigned char* mask = (const unsigned char*)d_in[2];
    const float* Wq = (const float*)d_in[3];
    const float* bq = (const float*)d_in[4];
    const float* Wk = (const float*)d_in[5];
    const float* bk = (const float*)d_in[6];
    const float* Wv = (const float*)d_in[7];
    const float* bv = (const float*)d_in[8];
    const float* Wo = (const float*)d_in[9];
    const float* bo = (const float*)d_in[10];
    const float* Wd = (const float*)d_in[11];
    const float* bd = (const float*)d_in[12];
    float* out = (float*)d_out;

    cudaFuncSetAttribute(gemm_qkv_kernel, cudaFuncAttributeMaxDynamicSharedMemorySize,
                         GEMM_SMEM_BYTES);
    cudaFuncSetAttribute(gemm_out_kernel, cudaFuncAttributeMaxDynamicSharedMemorySize,
                         GEMM_SMEM_BYTES);
    cudaFuncSetAttribute(attn_mma_kernel, cudaFuncAttributeMaxDynamicSharedMemorySize,
                         ATTN_SMEM_BYTES);

    __nv_bfloat16 *ahi_ptr = 0, *alo_ptr = 0;
    cudaGetSymbolAddress((void**)&ahi_ptr, g_Ahi);
    cudaGetSymbolAddress((void**)&alo_ptr, g_Alo);

    mask_convert_kernel<<<1, 256>>>(mask);
    conv_pair_kernel<<<2048, 256>>>(x, ahi_ptr, alo_ptr);
    conv_wT_kernel<<<dim3(16, 16, 4), 256>>>(Wq, Wk, Wv, Wo);
    gemm_qkv_kernel<<<dim3(4, 32, 3), 256, GEMM_SMEM_BYTES>>>(bq, bk, bv);
    dist_bias_kernel<<<8192, 256>>>(dist, Wd, bd);
    attn_mma_kernel<<<dim3(8, NH, NB), 128, ATTN_SMEM_BYTES>>>();
    gemm_out_kernel<<<dim3(4, 32), 256, GEMM_SMEM_BYTES>>>(bo, out);
}

// round 6
// speedup vs baseline: 2.0336x; 1.0607x over previous
#include <cuda_runtime.h>
#include <cuda_bf16.h>
#include <stdint.h>
#include <math.h>

#define NB 8
#define NH 8
#define SEQ 512
#define HID 512
#define HD 64

// ---------------- scratch (device globals; no allocations) ----------------
__device__ float g_maskf[NB*SEQ];                       // 0/1 floats
__device__ __nv_bfloat16 g_biasb[(size_t)NB*NH*SEQ*SEQ]; // 32 MB bf16 bias
__device__ __nv_bfloat16 g_Qh[NB*NH*SEQ*HD], g_Ql[NB*NH*SEQ*HD];   // [b,h,n,d]
__device__ __nv_bfloat16 g_Kh[NB*NH*SEQ*HD], g_Kl[NB*NH*SEQ*HD];   // [b,h,n,d]
__device__ __nv_bfloat16 g_VTh[NB*NH*SEQ*HD], g_VTl[NB*NH*SEQ*HD]; // [b,h,d,n]
__device__ __nv_bfloat16 g_Ahi[NB*SEQ*HID], g_Alo[NB*SEQ*HID];     // x / ctx
__device__ __nv_bfloat16 g_WThi[4][HID*HID], g_WTlo[4][HID*HID];   // W^T [n][k]

// ---------------- PTX helpers ----------------
__device__ __forceinline__ uint32_t sm_u32(const void* p) {
    return (uint32_t)__cvta_generic_to_shared(p);
}
#define CP16(dst_u32, gptr) \
    asm volatile("cp.async.ca.shared.global [%0], [%1], 16;" :: "r"(dst_u32), "l"(gptr))
#define CP_COMMIT() asm volatile("cp.async.commit_group;")
#define CP_WAIT0()  asm volatile("cp.async.wait_group 0;")
#define LDMX4(r, addr) \
    asm volatile("ldmatrix.sync.aligned.m8n8.x4.shared.b16 {%0,%1,%2,%3}, [%4];" \
        : "=r"((r)[0]), "=r"((r)[1]), "=r"((r)[2]), "=r"((r)[3]) : "r"(addr))
#define MMA16816(d, a, b) \
    asm volatile("mma.sync.aligned.m16n8k16.row.col.f32.bf16.bf16.f32 " \
        "{%0,%1,%2,%3},{%4,%5,%6,%7},{%8,%9},{%0,%1,%2,%3};\n" \
        : "+f"((d)[0]), "+f"((d)[1]), "+f"((d)[2]), "+f"((d)[3]) \
        : "r"((a)[0]), "r"((a)[1]), "r"((a)[2]), "r"((a)[3]), "r"((b)[0]), "r"((b)[1]))

// split pair (a=elem0, b=elem1) into packed bf16x2 hi and lo residual
__device__ __forceinline__ void split2(float a, float b, uint32_t& hi, uint32_t& lo) {
    __nv_bfloat16 ha = __float2bfloat16(a), hb = __float2bfloat16(b);
    __nv_bfloat16 la = __float2bfloat16(a - __bfloat162float(ha));
    __nv_bfloat16 lb = __float2bfloat16(b - __bfloat162float(hb));
    hi = ((uint32_t)__bfloat16_as_ushort(hb) << 16) | (uint32_t)__bfloat16_as_ushort(ha);
    lo = ((uint32_t)__bfloat16_as_ushort(lb) << 16) | (uint32_t)__bfloat16_as_ushort(la);
}

// ---------------- mask normalization (dtype-agnostic) ----------------
__global__ void mask_convert_kernel(const unsigned char* __restrict__ raw) {
    __shared__ int mode;
    if (threadIdx.x == 0) {
        const unsigned int* w = (const unsigned int*)raw;
        int cf = 0, byteish = 0;
        for (int i = 0; i < 128; i++) {
            unsigned int v = w[i];
            if (v == 0x3F800000u) cf++;
            bool b01 = true;
            #pragma unroll
            for (int bb = 0; bb < 4; bb++) {
                unsigned int by = (v >> (8*bb)) & 0xFFu;
                if (by > 1u) b01 = false;
            }
            if (b01 && v > 1u) byteish++;
        }
        mode = (cf > 64) ? 0 : ((byteish > 0) ? 2 : 1);  // 0=f32, 1=i32, 2=u8
    }
    __syncthreads();
    int md = mode;
    for (int i = threadIdx.x; i < NB*SEQ; i += blockDim.x) {
        float m;
        if (md == 0)      m = (((const float*)raw)[i] != 0.0f) ? 1.0f : 0.0f;
        else if (md == 1) m = (((const int*)raw)[i]   != 0)    ? 1.0f : 0.0f;
        else              m = (raw[i]                 != 0)    ? 1.0f : 0.0f;
        g_maskf[i] = m;
    }
}

// ---------------- hi/lo bf16 split of a dense f32 array ----------------
__global__ __launch_bounds__(256) void conv_pair_kernel(
    const float* __restrict__ src, __nv_bfloat16* __restrict__ hi,
    __nv_bfloat16* __restrict__ lo)
{
    int i = blockIdx.x * 256 + threadIdx.x;       // over float4s
    float4 v = ((const float4*)src)[i];
    uint32_t h0, l0, h1, l1;
    split2(v.x, v.y, h0, l0);
    split2(v.z, v.w, h1, l1);
    uint32_t* hp = (uint32_t*)(hi + 4*(size_t)i);
    uint32_t* lp = (uint32_t*)(lo + 4*(size_t)i);
    hp[0] = h0; hp[1] = h1;
    lp[0] = l0; lp[1] = l1;
}

// ---------------- W -> W^T hi/lo (32x32 smem tile transpose) ----------------
__global__ __launch_bounds__(256) void conv_wT_kernel(
    const float* __restrict__ Wq, const float* __restrict__ Wk,
    const float* __restrict__ Wv, const float* __restrict__ Wo)
{
    __shared__ float t[32][33];
    const int z = blockIdx.z;
    const float* W = (z == 0) ? Wq : (z == 1) ? Wk : (z == 2) ? Wv : Wo;
    __nv_bfloat16* Th = g_WThi[z];
    __nv_bfloat16* Tl = g_WTlo[z];
    int tx = threadIdx.x & 31, ty = threadIdx.x >> 5;      // 32 x 8
    int n0 = blockIdx.x * 32, k0 = blockIdx.y * 32;
    #pragma unroll
    for (int j = 0; j < 4; j++)
        t[ty + 8*j][tx] = W[(size_t)(k0 + ty + 8*j) * HID + n0 + tx];
    __syncthreads();
    #pragma unroll
    for (int j = 0; j < 4; j++) {
        float v = t[tx][ty + 8*j];
        __nv_bfloat16 h = __float2bfloat16(v);
        __nv_bfloat16 l = __float2bfloat16(v - __bfloat162float(h));
        size_t o = (size_t)(n0 + ty + 8*j) * HID + k0 + tx;
        Th[o] = h;
        Tl[o] = l;
    }
}

// ================= bf16x3 tensor-core GEMM core (verified R4) =============
#define GBK 32
#define LDT 40
#define BUF_ELEMS (128 * LDT)
#define AH_OFS 0
#define ALO_OFS (2 * BUF_ELEMS)
#define BH_OFS  (4 * BUF_ELEMS)
#define BLO_OFS (6 * BUF_ELEMS)
#define GEMM_SMEM_BYTES (8 * BUF_ELEMS * 2)

__device__ __forceinline__ void bf16x3_gemm(
    const __nv_bfloat16* __restrict__ Ahi, const __nv_bfloat16* __restrict__ Alo,
    const __nv_bfloat16* __restrict__ Bhi, const __nv_bfloat16* __restrict__ Blo,
    int m0, int n0, __nv_bfloat16* sm, float acc[4][4][4])
{
    const int tid = threadIdx.x;
    const int lane = tid & 31, wid = tid >> 5;
    const int wm = wid >> 2, wn = wid & 3;
    const uint32_t smb = sm_u32(sm);

    #pragma unroll
    for (int mi = 0; mi < 4; mi++)
        #pragma unroll
        for (int ni = 0; ni < 4; ni++)
            #pragma unroll
            for (int r = 0; r < 4; r++) acc[mi][ni][r] = 0.0f;

    const int c0 = tid, c1 = tid + 256;
    const int r0 = c0 >> 2, s0 = c0 & 3;
    const int r1 = c1 >> 2, s1 = c1 & 3;

    auto load_chunk = [&](int kc, int buf) {
        const int k0 = kc * GBK;
        const uint32_t so0 = (uint32_t)(buf * BUF_ELEMS + r0 * LDT + s0 * 8) * 2;
        const uint32_t so1 = (uint32_t)(buf * BUF_ELEMS + r1 * LDT + s1 * 8) * 2;
        const size_t ga0 = (size_t)(m0 + r0) * HID + k0 + s0 * 8;
        const size_t ga1 = (size_t)(m0 + r1) * HID + k0 + s1 * 8;
        const size_t gb0 = (size_t)(n0 + r0) * HID + k0 + s0 * 8;
        const size_t gb1 = (size_t)(n0 + r1) * HID + k0 + s1 * 8;
        CP16(smb + AH_OFS*2  + so0, Ahi + ga0);
        CP16(smb + AH_OFS*2  + so1, Ahi + ga1);
        CP16(smb + ALO_OFS*2 + so0, Alo + ga0);
        CP16(smb + ALO_OFS*2 + so1, Alo + ga1);
        CP16(smb + BH_OFS*2  + so0, Bhi + gb0);
        CP16(smb + BH_OFS*2  + so1, Bhi + gb1);
        CP16(smb + BLO_OFS*2 + so0, Blo + gb0);
        CP16(smb + BLO_OFS*2 + so1, Blo + gb1);
    };

    const int arow = wm * 64 + (lane & 15);
    const int acolb = (lane >> 4) << 3;
    const int brow = wn * 32 + (lane & 7) + ((lane & 16) >> 1);
    const int bcolb = lane & 8;

    load_chunk(0, 0);
    CP_COMMIT();

    for (int kc = 0; kc < HID / GBK; kc++) {
        CP_WAIT0();
        __syncthreads();
        if (kc + 1 < HID / GBK) {
            load_chunk(kc + 1, (kc + 1) & 1);
            CP_COMMIT();
        }
        const int buf = kc & 1;
        #pragma unroll
        for (int ks = 0; ks < 2; ks++) {
            uint32_t ah[4][4], al[4][4], bh[2][4], bl[2][4];
            const int acol = ks * 16 + acolb;
            const int bcol = ks * 16 + bcolb;
            #pragma unroll
            for (int mi = 0; mi < 4; mi++) {
                uint32_t off = (uint32_t)(buf * BUF_ELEMS + (arow + mi*16) * LDT + acol) * 2;
                LDMX4(ah[mi], smb + AH_OFS*2 + off);
                LDMX4(al[mi], smb + ALO_OFS*2 + off);
            }
            #pragma unroll
            for (int p = 0; p < 2; p++) {
                uint32_t off = (uint32_t)(buf * BUF_ELEMS + (brow + p*16) * LDT + bcol) * 2;
                LDMX4(bh[p], smb + BH_OFS*2 + off);
                LDMX4(bl[p], smb + BLO_OFS*2 + off);
            }
            #pragma unroll
            for (int mi = 0; mi < 4; mi++)
                #pragma unroll
                for (int ni = 0; ni < 4; ni++) {
                    uint32_t* bhf = &bh[ni >> 1][(ni & 1) * 2];
                    uint32_t* blf = &bl[ni >> 1][(ni & 1) * 2];
                    MMA16816(acc[mi][ni], ah[mi], bhf);
                    MMA16816(acc[mi][ni], ah[mi], blf);
                    MMA16816(acc[mi][ni], al[mi], bhf);
                }
        }
        __syncthreads();
    }
}

// ---------------- QKV projection: epilogue writes bf16 hi/lo ----------------
__global__ __launch_bounds__(256) void gemm_qkv_kernel(
    const float* __restrict__ bq, const float* __restrict__ bk,
    const float* __restrict__ bv)
{
    extern __shared__ __nv_bfloat16 sm[];
    const int z = blockIdx.z;
    const float* bias = (z == 0) ? bq : (z == 1) ? bk : bv;
    const int m0 = blockIdx.y * 128, n0 = blockIdx.x * 128;

    float acc[4][4][4];
    bf16x3_gemm(g_Ahi, g_Alo, g_WThi[z], g_WTlo[z], m0, n0, sm, acc);

    const int lane = threadIdx.x & 31, wid = threadIdx.x >> 5;
    const int wm = wid >> 2, wn = wid & 3;
    const int g = lane >> 2, tg = lane & 3;
    const float scale = (z == 0) ? 0.125f : 1.0f;

    __nv_bfloat16* OUTh = (z == 0) ? g_Qh : g_Kh;
    __nv_bfloat16* OUTl = (z == 0) ? g_Ql : g_Kl;

    #pragma unroll
    for (int mi = 0; mi < 4; mi++) {
        #pragma unroll
        for (int ni = 0; ni < 4; ni++) {
            int c = n0 + wn * 32 + ni * 8 + tg * 2;
            int hh = c >> 6, d = c & 63;
            float b0 = bias[c], b1 = bias[c + 1];
            #pragma unroll
            for (int half = 0; half < 2; half++) {
                int m = m0 + wm * 64 + mi * 16 + g + half * 8;
                int bb = m >> 9, n = m & 511;
                int bh = bb * NH + hh;
                float v0 = (acc[mi][ni][half*2 + 0] + b0) * scale;
                float v1 = (acc[mi][ni][half*2 + 1] + b1) * scale;
                if (z < 2) {
                    uint32_t hiw, low;
                    split2(v0, v1, hiw, low);
                    size_t a = ((size_t)bh * SEQ + n) * HD + d;
                    *(uint32_t*)&OUTh[a] = hiw;
                    *(uint32_t*)&OUTl[a] = low;
                } else {
                    // V stored transposed: [b,h,d,n]
                    __nv_bfloat16 h0 = __float2bfloat16(v0);
                    __nv_bfloat16 l0 = __float2bfloat16(v0 - __bfloat162float(h0));
                    __nv_bfloat16 h1 = __float2bfloat16(v1);
                    __nv_bfloat16 l1 = __float2bfloat16(v1 - __bfloat162float(h1));
                    size_t a0 = ((size_t)bh * HD + d) * SEQ + n;
                    g_VTh[a0] = h0;  g_VTl[a0] = l0;
                    g_VTh[a0 + SEQ] = h1;  g_VTl[a0 + SEQ] = l1;
                }
            }
        }
    }
}

// ---------------- output projection (reads ctx hi/lo written by attn) ------
__global__ __launch_bounds__(256) void gemm_out_kernel(
    const float* __restrict__ bo, float* __restrict__ OUT)
{
    extern __shared__ __nv_bfloat16 sm[];
    const int m0 = blockIdx.y * 128, n0 = blockIdx.x * 128;

    float acc[4][4][4];
    bf16x3_gemm(g_Ahi, g_Alo, g_WThi[3], g_WTlo[3], m0, n0, sm, acc);

    const int lane = threadIdx.x & 31, wid = threadIdx.x >> 5;
    const int wm = wid >> 2, wn = wid & 3;
    const int g = lane >> 2, tg = lane & 3;

    #pragma unroll
    for (int mi = 0; mi < 4; mi++) {
        #pragma unroll
        for (int ni = 0; ni < 4; ni++) {
            int c = n0 + wn * 32 + ni * 8 + tg * 2;
            float b0 = bo[c], b1 = bo[c + 1];
            #pragma unroll
            for (int half = 0; half < 2; half++) {
                int m = m0 + wm * 64 + mi * 16 + g + half * 8;
                float mf = g_maskf[m];
                float2 v;
                v.x = (mf > 0.5f) ? acc[mi][ni][half*2 + 0] + b0 : 0.0f;
                v.y = (mf > 0.5f) ? acc[mi][ni][half*2 + 1] + b1 : 0.0f;
                *(float2*)&OUT[(size_t)m * HID + c] = v;
            }
        }
    }
}

// ---------------- distance bias: [B*N*N, 64] @ [64, 8] + bd -> bf16 --------
__global__ __launch_bounds__(256) void dist_bias_kernel(
    const float* __restrict__ D, const float* __restrict__ Wd,
    const float* __restrict__ bd)
{
    __shared__ float w[64 * 8];
    __shared__ float bsm[8];
    const int tid = threadIdx.x;
    w[tid]       = Wd[tid];
    w[tid + 256] = Wd[tid + 256];
    if (tid < 8) bsm[tid] = bd[tid];
    __syncthreads();

    size_t r = (size_t)blockIdx.x * 256 + tid;       // row over B*N*N
    const float* row = D + r * 64;
    float acc[8] = {0, 0, 0, 0, 0, 0, 0, 0};
    #pragma unroll
    for (int t = 0; t < 16; t++) {
        float4 v = __ldcs((const float4*)&row[t * 4]);
        float vv[4] = {v.x, v.y, v.z, v.w};
        #pragma unroll
        for (int e = 0; e < 4; e++) {
            int d = t * 4 + e;
            #pragma unroll
            for (int h = 0; h < 8; h++)
                acc[h] = fmaf(vv[e], w[d * 8 + h], acc[h]);
        }
    }
    int b = (int)(r >> 18);
    int rem = (int)(r & 262143);
    int q = rem >> 9, k = rem & 511;
    #pragma unroll
    for (int h = 0; h < 8; h++)
        g_biasb[(((size_t)(b * NH + h)) * SEQ + q) * SEQ + k] =
            __float2bfloat16(acc[h] + bsm[h]);
}

// ======= tensor-core flash attention: CTA = (qb128, h, b), 8 warps =========
#define AT_LD 72                      // bf16 row stride (144B, ldmatrix-safe)
#define O_QH 0                        // Q hi: 128 x AT_LD = 9216 elems
#define O_QL 9216
#define O_KH 18432                    // [2 buf][4608]
#define O_KL 27648
#define O_VH 36864
#define O_VL 46080
#define AT_MADD_B 110592              // byte offset of mask floats
#define ATTN_SMEM_BYTES (110592 + 2048)

__device__ __forceinline__ void attn_load_kv(
    uint32_t smb, int buf, int kb, int tid,
    const __nv_bfloat16* Kh, const __nv_bfloat16* Kl,
    const __nv_bfloat16* Vh, const __nv_bfloat16* Vl)
{
    const uint32_t bo = (uint32_t)(buf * 4608 * 2);
    #pragma unroll
    for (int j = 0; j < 2; j++) {
        int ch = j * 256 + tid;                // 512 chunks per matrix
        int r = ch >> 3, cc = ch & 7;
        uint32_t so = (uint32_t)((r * AT_LD + cc * 8) * 2);
        size_t gk = (size_t)(kb * 64 + r) * HD + cc * 8;   // K: [key][d]
        size_t gv = (size_t)r * SEQ + kb * 64 + cc * 8;    // VT: [d][key]
        CP16(smb + O_KH*2 + bo + so, Kh + gk);
        CP16(smb + O_KL*2 + bo + so, Kl + gk);
        CP16(smb + O_VH*2 + bo + so, Vh + gv);
        CP16(smb + O_VL*2 + bo + so, Vl + gv);
    }
}

__global__ __launch_bounds__(256, 2) void attn_mma_kernel() {
    extern __shared__ __nv_bfloat16 smB[];
    float* madd = (float*)((char*)smB + AT_MADD_B);
    const uint32_t smb = sm_u32(smB);
    const int tid = threadIdx.x, lane = tid & 31, w = tid >> 5;   // 8 warps
    const int qb = blockIdx.x, h = blockIdx.y, b = blockIdx.z;
    const int bh = b * NH + h;
    const int g = lane >> 2, t4 = lane & 3;

    const __nv_bfloat16* Qh = g_Qh + ((size_t)bh * SEQ + qb * 128) * HD;
    const __nv_bfloat16* Ql = g_Ql + ((size_t)bh * SEQ + qb * 128) * HD;
    const __nv_bfloat16* Kh = g_Kh + (size_t)bh * SEQ * HD;
    const __nv_bfloat16* Kl = g_Kl + (size_t)bh * SEQ * HD;
    const __nv_bfloat16* Vh = g_VTh + (size_t)bh * HD * SEQ;
    const __nv_bfloat16* Vl = g_VTl + (size_t)bh * HD * SEQ;
    const __nv_bfloat16* Bb = g_biasb + ((size_t)bh * SEQ + qb * 128) * SEQ;

    // additive key mask into smem
    #pragma unroll
    for (int j = 0; j < 2; j++) {
        int i = j * 256 + tid;
        madd[i] = (g_maskf[b * SEQ + i] > 0.5f) ? 0.0f : -1e9f;
    }

    // Q tiles (128 x 64, hi+lo) + first KV tile
    #pragma unroll
    for (int j = 0; j < 4; j++) {
        int ch = j * 256 + tid;                // 1024 chunks per matrix
        int r = ch >> 3, cc = ch & 7;
        uint32_t so = (uint32_t)((r * AT_LD + cc * 8) * 2);
        CP16(smb + O_QH*2 + so, Qh + (size_t)r * HD + cc * 8);
        CP16(smb + O_QL*2 + so, Ql + (size_t)r * HD + cc * 8);
    }
    attn_load_kv(smb, 0, 0, tid, Kh, Kl, Vh, Vl);
    CP_COMMIT();
    CP_WAIT0();
    __syncthreads();

    // Q fragments (A, m16k16 per k-step), hi+lo; warp w owns rows [w*16, w*16+16)
    uint32_t qh[4][4], ql[4][4];
    {
        int arow = w * 16 + (lane & 15);
        int acolb = (lane >> 4) << 3;
        #pragma unroll
        for (int ks = 0; ks < 4; ks++) {
            uint32_t off = (uint32_t)((arow * AT_LD + ks * 16 + acolb) * 2);
            LDMX4(qh[ks], smb + O_QH*2 + off);
            LDMX4(ql[ks], smb + O_QL*2 + off);
        }
    }

    float o[4][2][4];
    #pragma unroll
    for (int i = 0; i < 4; i++)
        #pragma unroll
        for (int j = 0; j < 2; j++)
            #pragma unroll
            for (int r = 0; r < 4; r++) o[i][j][r] = 0.0f;
    float mrun[2] = {-1e30f, -1e30f}, lrun[2] = {0.0f, 0.0f};

    const int browc = (lane & 7) + ((lane & 16) >> 1);
    const int bcolc = lane & 8;

    for (int kb = 0; kb < 8; kb++) {
        if (kb > 0) { CP_WAIT0(); __syncthreads(); }
        if (kb + 1 < 8) {
            attn_load_kv(smb, (kb + 1) & 1, kb + 1, tid, Kh, Kl, Vh, Vl);
            CP_COMMIT();
        }
        const uint32_t bufo = (uint32_t)((kb & 1) * 4608 * 2);

        // ---- S = Q K^T (bf16x3) + bias + mask ----
        float sv[2][16];
        #pragma unroll
        for (int ni2 = 0; ni2 < 4; ni2++) {
            float s0[4] = {0, 0, 0, 0}, s1[4] = {0, 0, 0, 0};
            #pragma unroll
            for (int ks = 0; ks < 4; ks++) {
                uint32_t off = (uint32_t)(((ni2 * 16 + browc) * AT_LD + ks * 16 + bcolc) * 2);
                uint32_t kh4[4], kl4[4];
                LDMX4(kh4, smb + O_KH*2 + bufo + off);
                LDMX4(kl4, smb + O_KL*2 + bufo + off);
                MMA16816(s0, qh[ks], &kh4[0]);
                MMA16816(s0, qh[ks], &kl4[0]);
                MMA16816(s0, ql[ks], &kh4[0]);
                MMA16816(s1, qh[ks], &kh4[2]);
                MMA16816(s1, qh[ks], &kl4[2]);
                MMA16816(s1, ql[ks], &kh4[2]);
            }
            #pragma unroll
            for (int n8p = 0; n8p < 2; n8p++) {
                const float* sp = n8p ? s1 : s0;
                int col = kb * 64 + ni2 * 16 + n8p * 8 + t4 * 2;
                float2 mm = *(float2*)&madd[col];
                #pragma unroll
                for (int rh = 0; rh < 2; rh++) {
                    __nv_bfloat162 bb = *(const __nv_bfloat162*)
                        &Bb[(size_t)(w * 16 + g + rh * 8) * SEQ + col];
                    sv[rh][ni2*4 + n8p*2 + 0] = sp[rh*2 + 0] + __low2float(bb)  + mm.x;
                    sv[rh][ni2*4 + n8p*2 + 1] = sp[rh*2 + 1] + __high2float(bb) + mm.y;
                }
            }
        }

        // ---- online softmax ----
        float corr[2];
        #pragma unroll
        for (int rh = 0; rh < 2; rh++) {
            float rmx = -1e30f;
            #pragma unroll
            for (int i = 0; i < 16; i++) rmx = fmaxf(rmx, sv[rh][i]);
            rmx = fmaxf(rmx, __shfl_xor_sync(0xffffffffu, rmx, 1));
            rmx = fmaxf(rmx, __shfl_xor_sync(0xffffffffu, rmx, 2));
            float mnew = fmaxf(mrun[rh], rmx);
            corr[rh] = __expf(mrun[rh] - mnew);
            mrun[rh] = mnew;
            float rs = 0.0f;
            #pragma unroll
            for (int i = 0; i < 16; i++) {
                float p = __expf(sv[rh][i] - mnew);
                sv[rh][i] = p;
                rs += p;
            }
            rs += __shfl_xor_sync(0xffffffffu, rs, 1);
            rs += __shfl_xor_sync(0xffffffffu, rs, 2);
            lrun[rh] = lrun[rh] * corr[rh] + rs;
        }
        #pragma unroll
        for (int ni2 = 0; ni2 < 4; ni2++)
            #pragma unroll
            for (int n8p = 0; n8p < 2; n8p++) {
                o[ni2][n8p][0] *= corr[0];
                o[ni2][n8p][1] *= corr[0];
                o[ni2][n8p][2] *= corr[1];
                o[ni2][n8p][3] *= corr[1];
            }

        // ---- O += P V (bf16x3); ks outer keeps P fragments short-lived ----
        #pragma unroll
        for (int ks = 0; ks < 4; ks++) {
            uint32_t ph[4], pl[4];
            split2(sv[0][ks*4 + 0], sv[0][ks*4 + 1], ph[0], pl[0]);
            split2(sv[1][ks*4 + 0], sv[1][ks*4 + 1], ph[1], pl[1]);
            split2(sv[0][ks*4 + 2], sv[0][ks*4 + 3], ph[2], pl[2]);
            split2(sv[1][ks*4 + 2], sv[1][ks*4 + 3], ph[3], pl[3]);
            #pragma unroll
            for (int ni2 = 0; ni2 < 4; ni2++) {
                uint32_t off = (uint32_t)(((ni2 * 16 + browc) * AT_LD + ks * 16 + bcolc) * 2);
                uint32_t vh4[4], vl4[4];
                LDMX4(vh4, smb + O_VH*2 + bufo + off);
                LDMX4(vl4, smb + O_VL*2 + bufo + off);
                MMA16816(o[ni2][0], ph, &vh4[0]);
                MMA16816(o[ni2][0], ph, &vl4[0]);
                MMA16816(o[ni2][0], pl, &vh4[0]);
                MMA16816(o[ni2][1], ph, &vh4[2]);
                MMA16816(o[ni2][1], ph, &vl4[2]);
                MMA16816(o[ni2][1], pl, &vh4[2]);
            }
        }
    }

    // ---- epilogue: normalize, split hi/lo, write ctx ----
    float inv[2] = {1.0f / lrun[0], 1.0f / lrun[1]};
    #pragma unroll
    for (int ni2 = 0; ni2 < 4; ni2++) {
        #pragma unroll
        for (int n8p = 0; n8p < 2; n8p++) {
            int col = h * 64 + ni2 * 16 + n8p * 8 + t4 * 2;
            #pragma unroll
            for (int rh = 0; rh < 2; rh++) {
                size_t m = (size_t)b * SEQ + qb * 128 + w * 16 + g + rh * 8;
                float v0 = o[ni2][n8p][rh*2 + 0] * inv[rh];
                float v1 = o[ni2][n8p][rh*2 + 1] * inv[rh];
                uint32_t hiw, low;
                split2(v0, v1, hiw, low);
                *(uint32_t*)&g_Ahi[m * HID + col] = hiw;
                *(uint32_t*)&g_Alo[m * HID + col] = low;
            }
        }
    }
}

// ---------------- launch ----------------
extern "C" void kernel_launch(void* const* d_in, const int* in_sizes, int n_in,
                              void* d_out, int out_size)
{
    const float* x    = (const float*)d_in[0];
    const float* dist = (const float*)d_in[1];
    const unsigned char* mask = (const unsigned char*)d_in[2];
    const float* Wq = (const float*)d_in[3];
    const float* bq = (const float*)d_in[4];
    const float* Wk = (const float*)d_in[5];
    const float* bk = (const float*)d_in[6];
    const float* Wv = (const float*)d_in[7];
    const float* bv = (const float*)d_in[8];
    const float* Wo = (const float*)d_in[9];
    const float* bo = (const float*)d_in[10];
    const float* Wd = (const float*)d_in[11];
    const float* bd = (const float*)d_in[12];
    float* out = (float*)d_out;

    cudaFuncSetAttribute(gemm_qkv_kernel, cudaFuncAttributeMaxDynamicSharedMemorySize,
                         GEMM_SMEM_BYTES);
    cudaFuncSetAttribute(gemm_out_kernel, cudaFuncAttributeMaxDynamicSharedMemorySize,
                         GEMM_SMEM_BYTES);
    cudaFuncSetAttribute(attn_mma_kernel, cudaFuncAttributeMaxDynamicSharedMemorySize,
                         ATTN_SMEM_BYTES);

    __nv_bfloat16 *ahi_ptr = 0, *alo_ptr = 0;
    cudaGetSymbolAddress((void**)&ahi_ptr, g_Ahi);
    cudaGetSymbolAddress((void**)&alo_ptr, g_Alo);

    mask_convert_kernel<<<1, 256>>>(mask);
    conv_pair_kernel<<<2048, 256>>>(x, ahi_ptr, alo_ptr);
    conv_wT_kernel<<<dim3(16, 16, 4), 256>>>(Wq, Wk, Wv, Wo);
    gemm_qkv_kernel<<<dim3(4, 32, 3), 256, GEMM_SMEM_BYTES>>>(bq, bk, bv);
    dist_bias_kernel<<<8192, 256>>>(dist, Wd, bd);
    attn_mma_kernel<<<dim3(4, NH, NB), 256, ATTN_SMEM_BYTES>>>();
    gemm_out_kernel<<<dim3(4, 32), 256, GEMM_SMEM_BYTES>>>(bo, out);
}

// round 7
// speedup vs baseline: 2.1805x; 1.0722x over previous
#include <cuda_runtime.h>
#include <cuda_bf16.h>
#include <stdint.h>
#include <math.h>

#define NB 8
#define NH 8
#define SEQ 512
#define HID 512
#define HD 64

// ---------------- scratch (device globals; no allocations) ----------------
__device__ float g_maskf[NB*SEQ];                       // 0/1 floats
__device__ __nv_bfloat16 g_biasb[(size_t)NB*NH*SEQ*SEQ]; // 32 MB bf16 bias
__device__ __nv_bfloat16 g_Qh[NB*NH*SEQ*HD], g_Ql[NB*NH*SEQ*HD];   // [b,h,n,d]
__device__ __nv_bfloat16 g_Kh[NB*NH*SEQ*HD], g_Kl[NB*NH*SEQ*HD];   // [b,h,n,d]
__device__ __nv_bfloat16 g_VTh[NB*NH*SEQ*HD], g_VTl[NB*NH*SEQ*HD]; // [b,h,d,n]
__device__ __nv_bfloat16 g_Ahi[NB*SEQ*HID], g_Alo[NB*SEQ*HID];     // x / ctx
__device__ __nv_bfloat16 g_WThi[4][HID*HID], g_WTlo[4][HID*HID];   // W^T [n][k]

// ---------------- PTX helpers ----------------
__device__ __forceinline__ uint32_t sm_u32(const void* p) {
    return (uint32_t)__cvta_generic_to_shared(p);
}
#define CP16(dst_u32, gptr) \
    asm volatile("cp.async.ca.shared.global [%0], [%1], 16;" :: "r"(dst_u32), "l"(gptr))
#define CP_COMMIT() asm volatile("cp.async.commit_group;")
#define CP_WAIT0()  asm volatile("cp.async.wait_group 0;")
#define LDMX4(r, addr) \
    asm volatile("ldmatrix.sync.aligned.m8n8.x4.shared.b16 {%0,%1,%2,%3}, [%4];" \
        : "=r"((r)[0]), "=r"((r)[1]), "=r"((r)[2]), "=r"((r)[3]) : "r"(addr))
#define MMA16816(d, a, b) \
    asm volatile("mma.sync.aligned.m16n8k16.row.col.f32.bf16.bf16.f32 " \
        "{%0,%1,%2,%3},{%4,%5,%6,%7},{%8,%9},{%0,%1,%2,%3};\n" \
        : "+f"((d)[0]), "+f"((d)[1]), "+f"((d)[2]), "+f"((d)[3]) \
        : "r"((a)[0]), "r"((a)[1]), "r"((a)[2]), "r"((a)[3]), "r"((b)[0]), "r"((b)[1]))

// split pair (a=elem0, b=elem1) into packed bf16x2 hi and lo residual
__device__ __forceinline__ void split2(float a, float b, uint32_t& hi, uint32_t& lo) {
    __nv_bfloat16 ha = __float2bfloat16(a), hb = __float2bfloat16(b);
    __nv_bfloat16 la = __float2bfloat16(a - __bfloat162float(ha));
    __nv_bfloat16 lb = __float2bfloat16(b - __bfloat162float(hb));
    hi = ((uint32_t)__bfloat16_as_ushort(hb) << 16) | (uint32_t)__bfloat16_as_ushort(ha);
    lo = ((uint32_t)__bfloat16_as_ushort(lb) << 16) | (uint32_t)__bfloat16_as_ushort(la);
}

// ================= prep kernel: conv_pair(x) + conv_wT + mask ==============
__global__ __launch_bounds__(256) void prep_kernel(
    const float* __restrict__ x,
    const float* __restrict__ Wq, const float* __restrict__ Wk,
    const float* __restrict__ Wv, const float* __restrict__ Wo,
    const unsigned char* __restrict__ raw)
{
    __shared__ float t[32][33];
    __shared__ int mode;
    const int bx = blockIdx.x;
    const int tid = threadIdx.x;

    if (bx < 2048) {
        // ---- x -> hi/lo bf16 split ----
        int i = bx * 256 + tid;                 // over float4s (2M floats)
        float4 v = ((const float4*)x)[i];
        uint32_t h0, l0, h1, l1;
        split2(v.x, v.y, h0, l0);
        split2(v.z, v.w, h1, l1);
        uint32_t* hp = (uint32_t*)(g_Ahi + 4*(size_t)i);
        uint32_t* lp = (uint32_t*)(g_Alo + 4*(size_t)i);
        hp[0] = h0; hp[1] = h1;
        lp[0] = l0; lp[1] = l1;
    } else if (bx < 3072) {
        // ---- W -> W^T hi/lo (32x32 tile transpose) ----
        const int tt = bx - 2048;               // 0..1023
        const int z = tt >> 8;
        const int bxx = tt & 15, byy = (tt >> 4) & 15;
        const float* W = (z == 0) ? Wq : (z == 1) ? Wk : (z == 2) ? Wv : Wo;
        __nv_bfloat16* Th = g_WThi[z];
        __nv_bfloat16* Tl = g_WTlo[z];
        int tx = tid & 31, ty = tid >> 5;       // 32 x 8
        int n0 = bxx * 32, k0 = byy * 32;
        #pragma unroll
        for (int j = 0; j < 4; j++)
            t[ty + 8*j][tx] = W[(size_t)(k0 + ty + 8*j) * HID + n0 + tx];
        __syncthreads();
        #pragma unroll
        for (int j = 0; j < 4; j++) {
            float v = t[tx][ty + 8*j];
            __nv_bfloat16 h = __float2bfloat16(v);
            __nv_bfloat16 l = __float2bfloat16(v - __bfloat162float(h));
            size_t o = (size_t)(n0 + ty + 8*j) * HID + k0 + tx;
            Th[o] = h;
            Tl[o] = l;
        }
    } else {
        // ---- mask normalization (dtype-agnostic) ----
        if (tid == 0) {
            const unsigned int* w = (const unsigned int*)raw;
            int cf = 0, byteish = 0;
            for (int i = 0; i < 128; i++) {
                unsigned int v = w[i];
                if (v == 0x3F800000u) cf++;
                bool b01 = true;
                #pragma unroll
                for (int bb = 0; bb < 4; bb++) {
                    unsigned int by = (v >> (8*bb)) & 0xFFu;
                    if (by > 1u) b01 = false;
                }
                if (b01 && v > 1u) byteish++;
            }
            mode = (cf > 64) ? 0 : ((byteish > 0) ? 2 : 1);  // 0=f32, 1=i32, 2=u8
        }
        __syncthreads();
        int md = mode;
        for (int i = tid; i < NB*SEQ; i += 256) {
            float m;
            if (md == 0)      m = (((const float*)raw)[i] != 0.0f) ? 1.0f : 0.0f;
            else if (md == 1) m = (((const int*)raw)[i]   != 0)    ? 1.0f : 0.0f;
            else              m = (raw[i]                 != 0)    ? 1.0f : 0.0f;
            g_maskf[i] = m;
        }
    }
}

// ================= bf16x3 tensor-core GEMM core (verified R4) =============
#define GBK 32
#define LDT 40
#define BUF_ELEMS (128 * LDT)
#define AH_OFS 0
#define ALO_OFS (2 * BUF_ELEMS)
#define BH_OFS  (4 * BUF_ELEMS)
#define BLO_OFS (6 * BUF_ELEMS)
#define GEMM_SMEM_BYTES (8 * BUF_ELEMS * 2)

__device__ __forceinline__ void bf16x3_gemm(
    const __nv_bfloat16* __restrict__ Ahi, const __nv_bfloat16* __restrict__ Alo,
    const __nv_bfloat16* __restrict__ Bhi, const __nv_bfloat16* __restrict__ Blo,
    int m0, int n0, __nv_bfloat16* sm, float acc[4][4][4])
{
    const int tid = threadIdx.x;
    const int lane = tid & 31, wid = tid >> 5;
    const int wm = wid >> 2, wn = wid & 3;
    const uint32_t smb = sm_u32(sm);

    #pragma unroll
    for (int mi = 0; mi < 4; mi++)
        #pragma unroll
        for (int ni = 0; ni < 4; ni++)
            #pragma unroll
            for (int r = 0; r < 4; r++) acc[mi][ni][r] = 0.0f;

    const int c0 = tid, c1 = tid + 256;
    const int r0 = c0 >> 2, s0 = c0 & 3;
    const int r1 = c1 >> 2, s1 = c1 & 3;

    auto load_chunk = [&](int kc, int buf) {
        const int k0 = kc * GBK;
        const uint32_t so0 = (uint32_t)(buf * BUF_ELEMS + r0 * LDT + s0 * 8) * 2;
        const uint32_t so1 = (uint32_t)(buf * BUF_ELEMS + r1 * LDT + s1 * 8) * 2;
        const size_t ga0 = (size_t)(m0 + r0) * HID + k0 + s0 * 8;
        const size_t ga1 = (size_t)(m0 + r1) * HID + k0 + s1 * 8;
        const size_t gb0 = (size_t)(n0 + r0) * HID + k0 + s0 * 8;
        const size_t gb1 = (size_t)(n0 + r1) * HID + k0 + s1 * 8;
        CP16(smb + AH_OFS*2  + so0, Ahi + ga0);
        CP16(smb + AH_OFS*2  + so1, Ahi + ga1);
        CP16(smb + ALO_OFS*2 + so0, Alo + ga0);
        CP16(smb + ALO_OFS*2 + so1, Alo + ga1);
        CP16(smb + BH_OFS*2  + so0, Bhi + gb0);
        CP16(smb + BH_OFS*2  + so1, Bhi + gb1);
        CP16(smb + BLO_OFS*2 + so0, Blo + gb0);
        CP16(smb + BLO_OFS*2 + so1, Blo + gb1);
    };

    const int arow = wm * 64 + (lane & 15);
    const int acolb = (lane >> 4) << 3;
    const int brow = wn * 32 + (lane & 7) + ((lane & 16) >> 1);
    const int bcolb = lane & 8;

    load_chunk(0, 0);
    CP_COMMIT();

    for (int kc = 0; kc < HID / GBK; kc++) {
        CP_WAIT0();
        __syncthreads();
        if (kc + 1 < HID / GBK) {
            load_chunk(kc + 1, (kc + 1) & 1);
            CP_COMMIT();
        }
        const int buf = kc & 1;
        #pragma unroll
        for (int ks = 0; ks < 2; ks++) {
            uint32_t ah[4][4], al[4][4], bh[2][4], bl[2][4];
            const int acol = ks * 16 + acolb;
            const int bcol = ks * 16 + bcolb;
            #pragma unroll
            for (int mi = 0; mi < 4; mi++) {
                uint32_t off = (uint32_t)(buf * BUF_ELEMS + (arow + mi*16) * LDT + acol) * 2;
                LDMX4(ah[mi], smb + AH_OFS*2 + off);
                LDMX4(al[mi], smb + ALO_OFS*2 + off);
            }
            #pragma unroll
            for (int p = 0; p < 2; p++) {
                uint32_t off = (uint32_t)(buf * BUF_ELEMS + (brow + p*16) * LDT + bcol) * 2;
                LDMX4(bh[p], smb + BH_OFS*2 + off);
                LDMX4(bl[p], smb + BLO_OFS*2 + off);
            }
            #pragma unroll
            for (int mi = 0; mi < 4; mi++)
                #pragma unroll
                for (int ni = 0; ni < 4; ni++) {
                    uint32_t* bhf = &bh[ni >> 1][(ni & 1) * 2];
                    uint32_t* blf = &bl[ni >> 1][(ni & 1) * 2];
                    MMA16816(acc[mi][ni], ah[mi], bhf);
                    MMA16816(acc[mi][ni], ah[mi], blf);
                    MMA16816(acc[mi][ni], al[mi], bhf);
                }
        }
        __syncthreads();
    }
}

// ---------------- qkv block body (one 128x128 tile of one of Q/K/V) --------
__device__ __forceinline__ void qkv_block(
    int qkv_id, __nv_bfloat16* sm,
    const float* __restrict__ bq, const float* __restrict__ bk,
    const float* __restrict__ bv)
{
    const int z = qkv_id >> 7;            // 0..2
    const int rem = qkv_id & 127;
    const int m0 = (rem >> 2) * 128;      // 32 m-tiles
    const int n0 = (rem & 3) * 128;       // 4 n-tiles
    const float* bias = (z == 0) ? bq : (z == 1) ? bk : bv;

    float acc[4][4][4];
    bf16x3_gemm(g_Ahi, g_Alo, g_WThi[z], g_WTlo[z], m0, n0, sm, acc);

    const int lane = threadIdx.x & 31, wid = threadIdx.x >> 5;
    const int wm = wid >> 2, wn = wid & 3;
    const int g = lane >> 2, tg = lane & 3;
    const float scale = (z == 0) ? 0.125f : 1.0f;

    __nv_bfloat16* OUTh = (z == 0) ? g_Qh : g_Kh;
    __nv_bfloat16* OUTl = (z == 0) ? g_Ql : g_Kl;

    #pragma unroll
    for (int mi = 0; mi < 4; mi++) {
        #pragma unroll
        for (int ni = 0; ni < 4; ni++) {
            int c = n0 + wn * 32 + ni * 8 + tg * 2;
            int hh = c >> 6, d = c & 63;
            float b0 = bias[c], b1 = bias[c + 1];
            #pragma unroll
            for (int half = 0; half < 2; half++) {
                int m = m0 + wm * 64 + mi * 16 + g + half * 8;
                int bb = m >> 9, n = m & 511;
                int bh = bb * NH + hh;
                float v0 = (acc[mi][ni][half*2 + 0] + b0) * scale;
                float v1 = (acc[mi][ni][half*2 + 1] + b1) * scale;
                if (z < 2) {
                    uint32_t hiw, low;
                    split2(v0, v1, hiw, low);
                    size_t a = ((size_t)bh * SEQ + n) * HD + d;
                    *(uint32_t*)&OUTh[a] = hiw;
                    *(uint32_t*)&OUTl[a] = low;
                } else {
                    // V stored transposed: [b,h,d,n]
                    __nv_bfloat16 h0 = __float2bfloat16(v0);
                    __nv_bfloat16 l0 = __float2bfloat16(v0 - __bfloat162float(h0));
                    __nv_bfloat16 h1 = __float2bfloat16(v1);
                    __nv_bfloat16 l1 = __float2bfloat16(v1 - __bfloat162float(h1));
                    size_t a0 = ((size_t)bh * HD + d) * SEQ + n;
                    g_VTh[a0] = h0;  g_VTl[a0] = l0;
                    g_VTh[a0 + SEQ] = h1;  g_VTl[a0 + SEQ] = l1;
                }
            }
        }
    }
}

// ---------------- dist block body ([256 rows, 64] @ [64, 8] + bd) ----------
__device__ __forceinline__ void dist_block(
    int dist_id, float* w /*shared 512+8*/,
    const float* __restrict__ D, const float* __restrict__ Wd,
    const float* __restrict__ bd)
{
    float* bsm = w + 512;
    const int tid = threadIdx.x;
    w[tid]       = Wd[tid];
    w[tid + 256] = Wd[tid + 256];
    if (tid < 8) bsm[tid] = bd[tid];
    __syncthreads();

    size_t r = (size_t)dist_id * 256 + tid;          // row over B*N*N
    const float* row = D + r * 64;
    float acc[8] = {0, 0, 0, 0, 0, 0, 0, 0};
    #pragma unroll
    for (int t = 0; t < 16; t++) {
        float4 v = __ldcs((const float4*)&row[t * 4]);
        float vv[4] = {v.x, v.y, v.z, v.w};
        #pragma unroll
        for (int e = 0; e < 4; e++) {
            int d = t * 4 + e;
            #pragma unroll
            for (int h = 0; h < 8; h++)
                acc[h] = fmaf(vv[e], w[d * 8 + h], acc[h]);
        }
    }
    int b = (int)(r >> 18);
    int rem = (int)(r & 262143);
    int q = rem >> 9, k = rem & 511;
    #pragma unroll
    for (int h = 0; h < 8; h++)
        g_biasb[(((size_t)(b * NH + h)) * SEQ + q) * SEQ + k] =
            __float2bfloat16(acc[h] + bsm[h]);
}

// ============== fused kernel: qkv GEMM (tensor) ∥ dist_bias (HBM) ==========
// 8576 blocks: every 22nd index (while qkv_id < 384) is a qkv block so the
// tensor pipeline ramps immediately while dist blocks keep HBM saturated.
__global__ __launch_bounds__(256, 2) void fused_qkv_dist_kernel(
    const float* __restrict__ bq, const float* __restrict__ bk,
    const float* __restrict__ bv,
    const float* __restrict__ D, const float* __restrict__ Wd,
    const float* __restrict__ bd)
{
    extern __shared__ __nv_bfloat16 sm[];
    const int idx = blockIdx.x;
    const bool is_qkv = ((idx % 22) == 0) && (idx < 8448);
    if (is_qkv) {
        qkv_block(idx / 22, sm, bq, bk, bv);
    } else {
        const int nq_before = (idx < 8448) ? (idx / 22 + 1) : 384;
        dist_block(idx - nq_before, (float*)sm, D, Wd, bd);
    }
}

// ---------------- output projection (reads ctx hi/lo written by attn) ------
__global__ __launch_bounds__(256) void gemm_out_kernel(
    const float* __restrict__ bo, float* __restrict__ OUT)
{
    extern __shared__ __nv_bfloat16 sm[];
    const int m0 = blockIdx.y * 128, n0 = blockIdx.x * 128;

    float acc[4][4][4];
    bf16x3_gemm(g_Ahi, g_Alo, g_WThi[3], g_WTlo[3], m0, n0, sm, acc);

    const int lane = threadIdx.x & 31, wid = threadIdx.x >> 5;
    const int wm = wid >> 2, wn = wid & 3;
    const int g = lane >> 2, tg = lane & 3;

    #pragma unroll
    for (int mi = 0; mi < 4; mi++) {
        #pragma unroll
        for (int ni = 0; ni < 4; ni++) {
            int c = n0 + wn * 32 + ni * 8 + tg * 2;
            float b0 = bo[c], b1 = bo[c + 1];
            #pragma unroll
            for (int half = 0; half < 2; half++) {
                int m = m0 + wm * 64 + mi * 16 + g + half * 8;
                float mf = g_maskf[m];
                float2 v;
                v.x = (mf > 0.5f) ? acc[mi][ni][half*2 + 0] + b0 : 0.0f;
                v.y = (mf > 0.5f) ? acc[mi][ni][half*2 + 1] + b1 : 0.0f;
                *(float2*)&OUT[(size_t)m * HID + c] = v;
            }
        }
    }
}

// ======= tensor-core flash attention: CTA = (qb128, h, b), 8 warps =========
#define AT_LD 72                      // bf16 row stride (144B, ldmatrix-safe)
#define O_QH 0                        // Q hi: 128 x AT_LD = 9216 elems
#define O_QL 9216
#define O_KH 18432                    // [2 buf][4608]
#define O_KL 27648
#define O_VH 36864
#define O_VL 46080
#define AT_MADD_B 110592              // byte offset of mask floats
#define ATTN_SMEM_BYTES (110592 + 2048)

__device__ __forceinline__ void attn_load_kv(
    uint32_t smb, int buf, int kb, int tid,
    const __nv_bfloat16* Kh, const __nv_bfloat16* Kl,
    const __nv_bfloat16* Vh, const __nv_bfloat16* Vl)
{
    const uint32_t bo = (uint32_t)(buf * 4608 * 2);
    #pragma unroll
    for (int j = 0; j < 2; j++) {
        int ch = j * 256 + tid;                // 512 chunks per matrix
        int r = ch >> 3, cc = ch & 7;
        uint32_t so = (uint32_t)((r * AT_LD + cc * 8) * 2);
        size_t gk = (size_t)(kb * 64 + r) * HD + cc * 8;   // K: [key][d]
        size_t gv = (size_t)r * SEQ + kb * 64 + cc * 8;    // VT: [d][key]
        CP16(smb + O_KH*2 + bo + so, Kh + gk);
        CP16(smb + O_KL*2 + bo + so, Kl + gk);
        CP16(smb + O_VH*2 + bo + so, Vh + gv);
        CP16(smb + O_VL*2 + bo + so, Vl + gv);
    }
}

__global__ __launch_bounds__(256, 2) void attn_mma_kernel() {
    extern __shared__ __nv_bfloat16 smB[];
    float* madd = (float*)((char*)smB + AT_MADD_B);
    const uint32_t smb = sm_u32(smB);
    const int tid = threadIdx.x, lane = tid & 31, w = tid >> 5;   // 8 warps
    const int qb = blockIdx.x, h = blockIdx.y, b = blockIdx.z;
    const int bh = b * NH + h;
    const int g = lane >> 2, t4 = lane & 3;

    const __nv_bfloat16* Qh = g_Qh + ((size_t)bh * SEQ + qb * 128) * HD;
    const __nv_bfloat16* Ql = g_Ql + ((size_t)bh * SEQ + qb * 128) * HD;
    const __nv_bfloat16* Kh = g_Kh + (size_t)bh * SEQ * HD;
    const __nv_bfloat16* Kl = g_Kl + (size_t)bh * SEQ * HD;
    const __nv_bfloat16* Vh = g_VTh + (size_t)bh * HD * SEQ;
    const __nv_bfloat16* Vl = g_VTl + (size_t)bh * HD * SEQ;
    const __nv_bfloat16* Bb = g_biasb + ((size_t)bh * SEQ + qb * 128) * SEQ;

    // additive key mask into smem
    #pragma unroll
    for (int j = 0; j < 2; j++) {
        int i = j * 256 + tid;
        madd[i] = (g_maskf[b * SEQ + i] > 0.5f) ? 0.0f : -1e9f;
    }

    // Q tiles (128 x 64, hi+lo) + first KV tile
    #pragma unroll
    for (int j = 0; j < 4; j++) {
        int ch = j * 256 + tid;                // 1024 chunks per matrix
        int r = ch >> 3, cc = ch & 7;
        uint32_t so = (uint32_t)((r * AT_LD + cc * 8) * 2);
        CP16(smb + O_QH*2 + so, Qh + (size_t)r * HD + cc * 8);
        CP16(smb + O_QL*2 + so, Ql + (size_t)r * HD + cc * 8);
    }
    attn_load_kv(smb, 0, 0, tid, Kh, Kl, Vh, Vl);
    CP_COMMIT();
    CP_WAIT0();
    __syncthreads();

    // Q fragments (A, m16k16 per k-step), hi+lo; warp w owns rows [w*16, w*16+16)
    uint32_t qh[4][4], ql[4][4];
    {
        int arow = w * 16 + (lane & 15);
        int acolb = (lane >> 4) << 3;
        #pragma unroll
        for (int ks = 0; ks < 4; ks++) {
            uint32_t off = (uint32_t)((arow * AT_LD + ks * 16 + acolb) * 2);
            LDMX4(qh[ks], smb + O_QH*2 + off);
            LDMX4(ql[ks], smb + O_QL*2 + off);
        }
    }

    float o[4][2][4];
    #pragma unroll
    for (int i = 0; i < 4; i++)
        #pragma unroll
        for (int j = 0; j < 2; j++)
            #pragma unroll
            for (int r = 0; r < 4; r++) o[i][j][r] = 0.0f;
    float mrun[2] = {-1e30f, -1e30f}, lrun[2] = {0.0f, 0.0f};

    const int browc = (lane & 7) + ((lane & 16) >> 1);
    const int bcolc = lane & 8;

    for (int kb = 0; kb < 8; kb++) {
        if (kb > 0) { CP_WAIT0(); __syncthreads(); }
        if (kb + 1 < 8) {
            attn_load_kv(smb, (kb + 1) & 1, kb + 1, tid, Kh, Kl, Vh, Vl);
            CP_COMMIT();
        }
        const uint32_t bufo = (uint32_t)((kb & 1) * 4608 * 2);

        // ---- S = Q K^T (bf16x3) + bias + mask ----
        float sv[2][16];
        #pragma unroll
        for (int ni2 = 0; ni2 < 4; ni2++) {
            float s0[4] = {0, 0, 0, 0}, s1[4] = {0, 0, 0, 0};
            #pragma unroll
            for (int ks = 0; ks < 4; ks++) {
                uint32_t off = (uint32_t)(((ni2 * 16 + browc) * AT_LD + ks * 16 + bcolc) * 2);
                uint32_t kh4[4], kl4[4];
                LDMX4(kh4, smb + O_KH*2 + bufo + off);
                LDMX4(kl4, smb + O_KL*2 + bufo + off);
                MMA16816(s0, qh[ks], &kh4[0]);
                MMA16816(s0, qh[ks], &kl4[0]);
                MMA16816(s0, ql[ks], &kh4[0]);
                MMA16816(s1, qh[ks], &kh4[2]);
                MMA16816(s1, qh[ks], &kl4[2]);
                MMA16816(s1, ql[ks], &kh4[2]);
            }
            #pragma unroll
            for (int n8p = 0; n8p < 2; n8p++) {
                const float* sp = n8p ? s1 : s0;
                int col = kb * 64 + ni2 * 16 + n8p * 8 + t4 * 2;
                float2 mm = *(float2*)&madd[col];
                #pragma unroll
                for (int rh = 0; rh < 2; rh++) {
                    __nv_bfloat162 bb = *(const __nv_bfloat162*)
                        &Bb[(size_t)(w * 16 + g + rh * 8) * SEQ + col];
                    sv[rh][ni2*4 + n8p*2 + 0] = sp[rh*2 + 0] + __low2float(bb)  + mm.x;
                    sv[rh][ni2*4 + n8p*2 + 1] = sp[rh*2 + 1] + __high2float(bb) + mm.y;
                }
            }
        }

        // ---- online softmax ----
        float corr[2];
        #pragma unroll
        for (int rh = 0; rh < 2; rh++) {
            float rmx = -1e30f;
            #pragma unroll
            for (int i = 0; i < 16; i++) rmx = fmaxf(rmx, sv[rh][i]);
            rmx = fmaxf(rmx, __shfl_xor_sync(0xffffffffu, rmx, 1));
            rmx = fmaxf(rmx, __shfl_xor_sync(0xffffffffu, rmx, 2));
            float mnew = fmaxf(mrun[rh], rmx);
            corr[rh] = __expf(mrun[rh] - mnew);
            mrun[rh] = mnew;
            float rs = 0.0f;
            #pragma unroll
            for (int i = 0; i < 16; i++) {
                float p = __expf(sv[rh][i] - mnew);
                sv[rh][i] = p;
                rs += p;
            }
            rs += __shfl_xor_sync(0xffffffffu, rs, 1);
            rs += __shfl_xor_sync(0xffffffffu, rs, 2);
            lrun[rh] = lrun[rh] * corr[rh] + rs;
        }
        #pragma unroll
        for (int ni2 = 0; ni2 < 4; ni2++)
            #pragma unroll
            for (int n8p = 0; n8p < 2; n8p++) {
                o[ni2][n8p][0] *= corr[0];
                o[ni2][n8p][1] *= corr[0];
                o[ni2][n8p][2] *= corr[1];
                o[ni2][n8p][3] *= corr[1];
            }

        // ---- O += P V (bf16x3); ks outer keeps P fragments short-lived ----
        #pragma unroll
        for (int ks = 0; ks < 4; ks++) {
            uint32_t ph[4], pl[4];
            split2(sv[0][ks*4 + 0], sv[0][ks*4 + 1], ph[0], pl[0]);
            split2(sv[1][ks*4 + 0], sv[1][ks*4 + 1], ph[1], pl[1]);
            split2(sv[0][ks*4 + 2], sv[0][ks*4 + 3], ph[2], pl[2]);
            split2(sv[1][ks*4 + 2], sv[1][ks*4 + 3], ph[3], pl[3]);
            #pragma unroll
            for (int ni2 = 0; ni2 < 4; ni2++) {
                uint32_t off = (uint32_t)(((ni2 * 16 + browc) * AT_LD + ks * 16 + bcolc) * 2);
                uint32_t vh4[4], vl4[4];
                LDMX4(vh4, smb + O_VH*2 + bufo + off);
                LDMX4(vl4, smb + O_VL*2 + bufo + off);
                MMA16816(o[ni2][0], ph, &vh4[0]);
                MMA16816(o[ni2][0], ph, &vl4[0]);
                MMA16816(o[ni2][0], pl, &vh4[0]);
                MMA16816(o[ni2][1], ph, &vh4[2]);
                MMA16816(o[ni2][1], ph, &vl4[2]);
                MMA16816(o[ni2][1], pl, &vh4[2]);
            }
        }
    }

    // ---- epilogue: normalize, split hi/lo, write ctx ----
    float inv[2] = {1.0f / lrun[0], 1.0f / lrun[1]};
    #pragma unroll
    for (int ni2 = 0; ni2 < 4; ni2++) {
        #pragma unroll
        for (int n8p = 0; n8p < 2; n8p++) {
            int col = h * 64 + ni2 * 16 + n8p * 8 + t4 * 2;
            #pragma unroll
            for (int rh = 0; rh < 2; rh++) {
                size_t m = (size_t)b * SEQ + qb * 128 + w * 16 + g + rh * 8;
                float v0 = o[ni2][n8p][rh*2 + 0] * inv[rh];
                float v1 = o[ni2][n8p][rh*2 + 1] * inv[rh];
                uint32_t hiw, low;
                split2(v0, v1, hiw, low);
                *(uint32_t*)&g_Ahi[m * HID + col] = hiw;
                *(uint32_t*)&g_Alo[m * HID + col] = low;
            }
        }
    }
}

// ---------------- launch ----------------
extern "C" void kernel_launch(void* const* d_in, const int* in_sizes, int n_in,
                              void* d_out, int out_size)
{
    const float* x    = (const float*)d_in[0];
    const float* dist = (const float*)d_in[1];
    const unsigned char* mask = (const unsigned char*)d_in[2];
    const float* Wq = (const float*)d_in[3];
    const float* bq = (const float*)d_in[4];
    const float* Wk = (const float*)d_in[5];
    const float* bk = (const float*)d_in[6];
    const float* Wv = (const float*)d_in[7];
    const float* bv = (const float*)d_in[8];
    const float* Wo = (const float*)d_in[9];
    const float* bo = (const float*)d_in[10];
    const float* Wd = (const float*)d_in[11];
    const float* bd = (const float*)d_in[12];
    float* out = (float*)d_out;

    cudaFuncSetAttribute(fused_qkv_dist_kernel, cudaFuncAttributeMaxDynamicSharedMemorySize,
                         GEMM_SMEM_BYTES);
    cudaFuncSetAttribute(gemm_out_kernel, cudaFuncAttributeMaxDynamicSharedMemorySize,
                         GEMM_SMEM_BYTES);
    cudaFuncSetAttribute(attn_mma_kernel, cudaFuncAttributeMaxDynamicSharedMemorySize,
                         ATTN_SMEM_BYTES);

    prep_kernel<<<3073, 256>>>(x, Wq, Wk, Wv, Wo, mask);
    fused_qkv_dist_kernel<<<8576, 256, GEMM_SMEM_BYTES>>>(bq, bk, bv, dist, Wd, bd);
    attn_mma_kernel<<<dim3(4, NH, NB), 256, ATTN_SMEM_BYTES>>>();
    gemm_out_kernel<<<dim3(4, 32), 256, GEMM_SMEM_BYTES>>>(bo, out);
}

// round 8
// speedup vs baseline: 2.3994x; 1.1004x over previous
#include <cuda_runtime.h>
#include <cuda_bf16.h>
#include <cuda_fp16.h>
#include <stdint.h>
#include <math.h>

#define NB 8
#define NH 8
#define SEQ 512
#define HID 512
#define HD 64

// ---------------- scratch (device globals; no allocations) ----------------
__device__ float g_maskf[NB*SEQ];                        // 0/1 floats
__device__ __half g_biasf[(size_t)NB*NH*SEQ*SEQ];        // 32 MB fp16 bias
__device__ __half g_Qf[NB*NH*SEQ*HD];                    // [b,h,n,d] (pre-scaled)
__device__ __half g_Kf[NB*NH*SEQ*HD];                    // [b,h,n,d]
__device__ __half g_VTf[NB*NH*SEQ*HD];                   // [b,h,d,n]
__device__ __nv_bfloat16 g_Ahi[NB*SEQ*HID], g_Alo[NB*SEQ*HID];   // x / ctx
__device__ __nv_bfloat16 g_WThi[4][HID*HID], g_WTlo[4][HID*HID]; // W^T [n][k]

// ---------------- PTX helpers ----------------
__device__ __forceinline__ uint32_t sm_u32(const void* p) {
    return (uint32_t)__cvta_generic_to_shared(p);
}
#define CP16(dst_u32, gptr) \
    asm volatile("cp.async.ca.shared.global [%0], [%1], 16;" :: "r"(dst_u32), "l"(gptr))
#define CP_COMMIT() asm volatile("cp.async.commit_group;")
#define CP_WAIT0()  asm volatile("cp.async.wait_group 0;")
#define LDMX4(r, addr) \
    asm volatile("ldmatrix.sync.aligned.m8n8.x4.shared.b16 {%0,%1,%2,%3}, [%4];" \
        : "=r"((r)[0]), "=r"((r)[1]), "=r"((r)[2]), "=r"((r)[3]) : "r"(addr))
#define MMA16816(d, a, b) \
    asm volatile("mma.sync.aligned.m16n8k16.row.col.f32.bf16.bf16.f32 " \
        "{%0,%1,%2,%3},{%4,%5,%6,%7},{%8,%9},{%0,%1,%2,%3};\n" \
        : "+f"((d)[0]), "+f"((d)[1]), "+f"((d)[2]), "+f"((d)[3]) \
        : "r"((a)[0]), "r"((a)[1]), "r"((a)[2]), "r"((a)[3]), "r"((b)[0]), "r"((b)[1]))
#define MMA16816H(d, a, b) \
    asm volatile("mma.sync.aligned.m16n8k16.row.col.f32.f16.f16.f32 " \
        "{%0,%1,%2,%3},{%4,%5,%6,%7},{%8,%9},{%0,%1,%2,%3};\n" \
        : "+f"((d)[0]), "+f"((d)[1]), "+f"((d)[2]), "+f"((d)[3]) \
        : "r"((a)[0]), "r"((a)[1]), "r"((a)[2]), "r"((a)[3]), "r"((b)[0]), "r"((b)[1]))

// split pair (a=elem0, b=elem1) into packed bf16x2 hi and lo residual
__device__ __forceinline__ void split2(float a, float b, uint32_t& hi, uint32_t& lo) {
    __nv_bfloat16 ha = __float2bfloat16(a), hb = __float2bfloat16(b);
    __nv_bfloat16 la = __float2bfloat16(a - __bfloat162float(ha));
    __nv_bfloat16 lb = __float2bfloat16(b - __bfloat162float(hb));
    hi = ((uint32_t)__bfloat16_as_ushort(hb) << 16) | (uint32_t)__bfloat16_as_ushort(ha);
    lo = ((uint32_t)__bfloat16_as_ushort(lb) << 16) | (uint32_t)__bfloat16_as_ushort(la);
}

__device__ __forceinline__ uint32_t packh2(float a, float b) {
    __half2 h = __floats2half2_rn(a, b);
    return *reinterpret_cast<uint32_t*>(&h);
}

// ================= prep kernel: conv_pair(x) + conv_wT + mask ==============
__global__ __launch_bounds__(256) void prep_kernel(
    const float* __restrict__ x,
    const float* __restrict__ Wq, const float* __restrict__ Wk,
    const float* __restrict__ Wv, const float* __restrict__ Wo,
    const unsigned char* __restrict__ raw)
{
    __shared__ float t[32][33];
    __shared__ int mode;
    const int bx = blockIdx.x;
    const int tid = threadIdx.x;

    if (bx < 2048) {
        // ---- x -> hi/lo bf16 split ----
        int i = bx * 256 + tid;                 // over float4s (2M floats)
        float4 v = ((const float4*)x)[i];
        uint32_t h0, l0, h1, l1;
        split2(v.x, v.y, h0, l0);
        split2(v.z, v.w, h1, l1);
        uint32_t* hp = (uint32_t*)(g_Ahi + 4*(size_t)i);
        uint32_t* lp = (uint32_t*)(g_Alo + 4*(size_t)i);
        hp[0] = h0; hp[1] = h1;
        lp[0] = l0; lp[1] = l1;
    } else if (bx < 3072) {
        // ---- W -> W^T hi/lo (32x32 tile transpose) ----
        const int tt = bx - 2048;               // 0..1023
        const int z = tt >> 8;
        const int bxx = tt & 15, byy = (tt >> 4) & 15;
        const float* W = (z == 0) ? Wq : (z == 1) ? Wk : (z == 2) ? Wv : Wo;
        __nv_bfloat16* Th = g_WThi[z];
        __nv_bfloat16* Tl = g_WTlo[z];
        int tx = tid & 31, ty = tid >> 5;       // 32 x 8
        int n0 = bxx * 32, k0 = byy * 32;
        #pragma unroll
        for (int j = 0; j < 4; j++)
            t[ty + 8*j][tx] = W[(size_t)(k0 + ty + 8*j) * HID + n0 + tx];
        __syncthreads();
        #pragma unroll
        for (int j = 0; j < 4; j++) {
            float v = t[tx][ty + 8*j];
            __nv_bfloat16 h = __float2bfloat16(v);
            __nv_bfloat16 l = __float2bfloat16(v - __bfloat162float(h));
            size_t o = (size_t)(n0 + ty + 8*j) * HID + k0 + tx;
            Th[o] = h;
            Tl[o] = l;
        }
    } else {
        // ---- mask normalization (dtype-agnostic) ----
        if (tid == 0) {
            const unsigned int* w = (const unsigned int*)raw;
            int cf = 0, byteish = 0;
            for (int i = 0; i < 128; i++) {
                unsigned int v = w[i];
                if (v == 0x3F800000u) cf++;
                bool b01 = true;
                #pragma unroll
                for (int bb = 0; bb < 4; bb++) {
                    unsigned int by = (v >> (8*bb)) & 0xFFu;
                    if (by > 1u) b01 = false;
                }
                if (b01 && v > 1u) byteish++;
            }
            mode = (cf > 64) ? 0 : ((byteish > 0) ? 2 : 1);  // 0=f32, 1=i32, 2=u8
        }
        __syncthreads();
        int md = mode;
        for (int i = tid; i < NB*SEQ; i += 256) {
            float m;
            if (md == 0)      m = (((const float*)raw)[i] != 0.0f) ? 1.0f : 0.0f;
            else if (md == 1) m = (((const int*)raw)[i]   != 0)    ? 1.0f : 0.0f;
            else              m = (raw[i]                 != 0)    ? 1.0f : 0.0f;
            g_maskf[i] = m;
        }
    }
}

// ================= bf16x3 tensor-core GEMM core (verified R4) =============
#define GBK 32
#define LDT 40
#define BUF_ELEMS (128 * LDT)
#define AH_OFS 0
#define ALO_OFS (2 * BUF_ELEMS)
#define BH_OFS  (4 * BUF_ELEMS)
#define BLO_OFS (6 * BUF_ELEMS)
#define GEMM_SMEM_BYTES (8 * BUF_ELEMS * 2)

__device__ __forceinline__ void bf16x3_gemm(
    const __nv_bfloat16* __restrict__ Ahi, const __nv_bfloat16* __restrict__ Alo,
    const __nv_bfloat16* __restrict__ Bhi, const __nv_bfloat16* __restrict__ Blo,
    int m0, int n0, __nv_bfloat16* sm, float acc[4][4][4])
{
    const int tid = threadIdx.x;
    const int lane = tid & 31, wid = tid >> 5;
    const int wm = wid >> 2, wn = wid & 3;
    const uint32_t smb = sm_u32(sm);

    #pragma unroll
    for (int mi = 0; mi < 4; mi++)
        #pragma unroll
        for (int ni = 0; ni < 4; ni++)
            #pragma unroll
            for (int r = 0; r < 4; r++) acc[mi][ni][r] = 0.0f;

    const int c0 = tid, c1 = tid + 256;
    const int r0 = c0 >> 2, s0 = c0 & 3;
    const int r1 = c1 >> 2, s1 = c1 & 3;

    auto load_chunk = [&](int kc, int buf) {
        const int k0 = kc * GBK;
        const uint32_t so0 = (uint32_t)(buf * BUF_ELEMS + r0 * LDT + s0 * 8) * 2;
        const uint32_t so1 = (uint32_t)(buf * BUF_ELEMS + r1 * LDT + s1 * 8) * 2;
        const size_t ga0 = (size_t)(m0 + r0) * HID + k0 + s0 * 8;
        const size_t ga1 = (size_t)(m0 + r1) * HID + k0 + s1 * 8;
        const size_t gb0 = (size_t)(n0 + r0) * HID + k0 + s0 * 8;
        const size_t gb1 = (size_t)(n0 + r1) * HID + k0 + s1 * 8;
        CP16(smb + AH_OFS*2  + so0, Ahi + ga0);
        CP16(smb + AH_OFS*2  + so1, Ahi + ga1);
        CP16(smb + ALO_OFS*2 + so0, Alo + ga0);
        CP16(smb + ALO_OFS*2 + so1, Alo + ga1);
        CP16(smb + BH_OFS*2  + so0, Bhi + gb0);
        CP16(smb + BH_OFS*2  + so1, Bhi + gb1);
        CP16(smb + BLO_OFS*2 + so0, Blo + gb0);
        CP16(smb + BLO_OFS*2 + so1, Blo + gb1);
    };

    const int arow = wm * 64 + (lane & 15);
    const int acolb = (lane >> 4) << 3;
    const int brow = wn * 32 + (lane & 7) + ((lane & 16) >> 1);
    const int bcolb = lane & 8;

    load_chunk(0, 0);
    CP_COMMIT();

    for (int kc = 0; kc < HID / GBK; kc++) {
        CP_WAIT0();
        __syncthreads();
        if (kc + 1 < HID / GBK) {
            load_chunk(kc + 1, (kc + 1) & 1);
            CP_COMMIT();
        }
        const int buf = kc & 1;
        #pragma unroll
        for (int ks = 0; ks < 2; ks++) {
            uint32_t ah[4][4], al[4][4], bh[2][4], bl[2][4];
            const int acol = ks * 16 + acolb;
            const int bcol = ks * 16 + bcolb;
            #pragma unroll
            for (int mi = 0; mi < 4; mi++) {
                uint32_t off = (uint32_t)(buf * BUF_ELEMS + (arow + mi*16) * LDT + acol) * 2;
                LDMX4(ah[mi], smb + AH_OFS*2 + off);
                LDMX4(al[mi], smb + ALO_OFS*2 + off);
            }
            #pragma unroll
            for (int p = 0; p < 2; p++) {
                uint32_t off = (uint32_t)(buf * BUF_ELEMS + (brow + p*16) * LDT + bcol) * 2;
                LDMX4(bh[p], smb + BH_OFS*2 + off);
                LDMX4(bl[p], smb + BLO_OFS*2 + off);
            }
            #pragma unroll
            for (int mi = 0; mi < 4; mi++)
                #pragma unroll
                for (int ni = 0; ni < 4; ni++) {
                    uint32_t* bhf = &bh[ni >> 1][(ni & 1) * 2];
                    uint32_t* blf = &bl[ni >> 1][(ni & 1) * 2];
                    MMA16816(acc[mi][ni], ah[mi], bhf);
                    MMA16816(acc[mi][ni], ah[mi], blf);
                    MMA16816(acc[mi][ni], al[mi], bhf);
                }
        }
        __syncthreads();
    }
}

// ---------------- qkv block body (one 128x128 tile of one of Q/K/V) --------
__device__ __forceinline__ void qkv_block(
    int qkv_id, __nv_bfloat16* sm,
    const float* __restrict__ bq, const float* __restrict__ bk,
    const float* __restrict__ bv)
{
    const int z = qkv_id >> 7;            // 0..2
    const int rem = qkv_id & 127;
    const int m0 = (rem >> 2) * 128;      // 32 m-tiles
    const int n0 = (rem & 3) * 128;       // 4 n-tiles
    const float* bias = (z == 0) ? bq : (z == 1) ? bk : bv;

    float acc[4][4][4];
    bf16x3_gemm(g_Ahi, g_Alo, g_WThi[z], g_WTlo[z], m0, n0, sm, acc);

    const int lane = threadIdx.x & 31, wid = threadIdx.x >> 5;
    const int wm = wid >> 2, wn = wid & 3;
    const int g = lane >> 2, tg = lane & 3;
    const float scale = (z == 0) ? 0.125f : 1.0f;

    __half* OUTF = (z == 0) ? g_Qf : g_Kf;

    #pragma unroll
    for (int mi = 0; mi < 4; mi++) {
        #pragma unroll
        for (int ni = 0; ni < 4; ni++) {
            int c = n0 + wn * 32 + ni * 8 + tg * 2;
            int hh = c >> 6, d = c & 63;
            float b0 = bias[c], b1 = bias[c + 1];
            #pragma unroll
            for (int half = 0; half < 2; half++) {
                int m = m0 + wm * 64 + mi * 16 + g + half * 8;
                int bb = m >> 9, n = m & 511;
                int bh = bb * NH + hh;
                float v0 = (acc[mi][ni][half*2 + 0] + b0) * scale;
                float v1 = (acc[mi][ni][half*2 + 1] + b1) * scale;
                if (z < 2) {
                    size_t a = ((size_t)bh * SEQ + n) * HD + d;
                    *(__half2*)&OUTF[a] = __floats2half2_rn(v0, v1);
                } else {
                    // V stored transposed: [b,h,d,n]
                    size_t a0 = ((size_t)bh * HD + d) * SEQ + n;
                    g_VTf[a0]       = __float2half(v0);
                    g_VTf[a0 + SEQ] = __float2half(v1);
                }
            }
        }
    }
}

// ---------------- dist block body ([256 rows, 64] @ [64, 8] + bd) ----------
__device__ __forceinline__ void dist_block(
    int dist_id, float* w /*shared 512+8*/,
    const float* __restrict__ D, const float* __restrict__ Wd,
    const float* __restrict__ bd)
{
    float* bsm = w + 512;
    const int tid = threadIdx.x;
    w[tid]       = Wd[tid];
    w[tid + 256] = Wd[tid + 256];
    if (tid < 8) bsm[tid] = bd[tid];
    __syncthreads();

    size_t r = (size_t)dist_id * 256 + tid;          // row over B*N*N
    const float* row = D + r * 64;
    float acc[8] = {0, 0, 0, 0, 0, 0, 0, 0};
    #pragma unroll
    for (int t = 0; t < 16; t++) {
        float4 v = __ldcs((const float4*)&row[t * 4]);
        float vv[4] = {v.x, v.y, v.z, v.w};
        #pragma unroll
        for (int e = 0; e < 4; e++) {
            int d = t * 4 + e;
            #pragma unroll
            for (int h = 0; h < 8; h++)
                acc[h] = fmaf(vv[e], w[d * 8 + h], acc[h]);
        }
    }
    int b = (int)(r >> 18);
    int rem = (int)(r & 262143);
    int q = rem >> 9, k = rem & 511;
    #pragma unroll
    for (int h = 0; h < 8; h++)
        g_biasf[(((size_t)(b * NH + h)) * SEQ + q) * SEQ + k] =
            __float2half(acc[h] + bsm[h]);
}

// ============== fused kernel: qkv GEMM (tensor) ∥ dist_bias (HBM) ==========
__global__ __launch_bounds__(256, 2) void fused_qkv_dist_kernel(
    const float* __restrict__ bq, const float* __restrict__ bk,
    const float* __restrict__ bv,
    const float* __restrict__ D, const float* __restrict__ Wd,
    const float* __restrict__ bd)
{
    extern __shared__ __nv_bfloat16 sm[];
    const int idx = blockIdx.x;
    const bool is_qkv = ((idx % 22) == 0) && (idx < 8448);
    if (is_qkv) {
        qkv_block(idx / 22, sm, bq, bk, bv);
    } else {
        const int nq_before = (idx < 8448) ? (idx / 22 + 1) : 384;
        dist_block(idx - nq_before, (float*)sm, D, Wd, bd);
    }
}

// ---------------- output projection (reads ctx hi/lo written by attn) ------
__global__ __launch_bounds__(256) void gemm_out_kernel(
    const float* __restrict__ bo, float* __restrict__ OUT)
{
    extern __shared__ __nv_bfloat16 sm[];
    const int m0 = blockIdx.y * 128, n0 = blockIdx.x * 128;

    float acc[4][4][4];
    bf16x3_gemm(g_Ahi, g_Alo, g_WThi[3], g_WTlo[3], m0, n0, sm, acc);

    const int lane = threadIdx.x & 31, wid = threadIdx.x >> 5;
    const int wm = wid >> 2, wn = wid & 3;
    const int g = lane >> 2, tg = lane & 3;

    #pragma unroll
    for (int mi = 0; mi < 4; mi++) {
        #pragma unroll
        for (int ni = 0; ni < 4; ni++) {
            int c = n0 + wn * 32 + ni * 8 + tg * 2;
            float b0 = bo[c], b1 = bo[c + 1];
            #pragma unroll
            for (int half = 0; half < 2; half++) {
                int m = m0 + wm * 64 + mi * 16 + g + half * 8;
                float mf = g_maskf[m];
                float2 v;
                v.x = (mf > 0.5f) ? acc[mi][ni][half*2 + 0] + b0 : 0.0f;
                v.y = (mf > 0.5f) ? acc[mi][ni][half*2 + 1] + b1 : 0.0f;
                *(float2*)&OUT[(size_t)m * HID + c] = v;
            }
        }
    }
}

// ======= fp16 tensor-core flash attention: CTA = (qb128, h, b), 8 warps ====
#define AT_LD 72                      // fp16 row stride (144B, ldmatrix-safe)
#define OQ 0                          // Q: 128 x AT_LD = 9216 halves
#define OK 9216                       // K: [2 buf][4608]
#define OV 18432                      // V^T: [2 buf][4608]
#define AT_MADD_B 55296               // byte offset of mask floats
#define ATTN_SMEM_BYTES (55296 + 2048)

__device__ __forceinline__ void attn_load_kv(
    uint32_t smb, int buf, int kb, int tid,
    const __half* Kf, const __half* Vf)
{
    const uint32_t bo = (uint32_t)(buf * 4608 * 2);
    #pragma unroll
    for (int j = 0; j < 2; j++) {
        int ch = j * 256 + tid;                // 512 chunks per matrix
        int r = ch >> 3, cc = ch & 7;
        uint32_t so = (uint32_t)((r * AT_LD + cc * 8) * 2);
        CP16(smb + OK*2 + bo + so, Kf + (size_t)(kb * 64 + r) * HD + cc * 8);
        CP16(smb + OV*2 + bo + so, Vf + (size_t)r * SEQ + kb * 64 + cc * 8);
    }
}

__global__ __launch_bounds__(256, 2) void attn_mma_kernel() {
    extern __shared__ __half smH[];
    float* madd = (float*)((char*)smH + AT_MADD_B);
    const uint32_t smb = sm_u32(smH);
    const int tid = threadIdx.x, lane = tid & 31, w = tid >> 5;   // 8 warps
    const int qb = blockIdx.x, h = blockIdx.y, b = blockIdx.z;
    const int bh = b * NH + h;
    const int g = lane >> 2, t4 = lane & 3;

    const __half* Qf = g_Qf + ((size_t)bh * SEQ + qb * 128) * HD;
    const __half* Kf = g_Kf + (size_t)bh * SEQ * HD;
    const __half* Vf = g_VTf + (size_t)bh * HD * SEQ;
    const __half* Bb = g_biasf + ((size_t)bh * SEQ + qb * 128) * SEQ;

    // additive key mask into smem
    #pragma unroll
    for (int j = 0; j < 2; j++) {
        int i = j * 256 + tid;
        madd[i] = (g_maskf[b * SEQ + i] > 0.5f) ? 0.0f : -1e9f;
    }

    // Q tile (128 x 64) + first KV tile
    #pragma unroll
    for (int j = 0; j < 4; j++) {
        int ch = j * 256 + tid;                // 1024 chunks
        int r = ch >> 3, cc = ch & 7;
        uint32_t so = (uint32_t)((r * AT_LD + cc * 8) * 2);
        CP16(smb + OQ*2 + so, Qf + (size_t)r * HD + cc * 8);
    }
    attn_load_kv(smb, 0, 0, tid, Kf, Vf);
    CP_COMMIT();
    CP_WAIT0();
    __syncthreads();

    // Q fragments (A, m16k16 per k-step); warp w owns rows [w*16, w*16+16)
    uint32_t qf[4][4];
    {
        int arow = w * 16 + (lane & 15);
        int acolb = (lane >> 4) << 3;
        #pragma unroll
        for (int ks = 0; ks < 4; ks++) {
            uint32_t off = (uint32_t)((arow * AT_LD + ks * 16 + acolb) * 2);
            LDMX4(qf[ks], smb + OQ*2 + off);
        }
    }

    float o[4][2][4];
    #pragma unroll
    for (int i = 0; i < 4; i++)
        #pragma unroll
        for (int j = 0; j < 2; j++)
            #pragma unroll
            for (int r = 0; r < 4; r++) o[i][j][r] = 0.0f;
    float mrun[2] = {-1e30f, -1e30f}, lrun[2] = {0.0f, 0.0f};

    const int browc = (lane & 7) + ((lane & 16) >> 1);
    const int bcolc = lane & 8;

    for (int kb = 0; kb < 8; kb++) {
        if (kb > 0) { CP_WAIT0(); __syncthreads(); }
        if (kb + 1 < 8) {
            attn_load_kv(smb, (kb + 1) & 1, kb + 1, tid, Kf, Vf);
            CP_COMMIT();
        }
        const uint32_t bufo = (uint32_t)((kb & 1) * 4608 * 2);

        // ---- S = Q K^T (fp16, single pass) + bias + mask ----
        float sv[2][16];
        #pragma unroll
        for (int ni2 = 0; ni2 < 4; ni2++) {
            float s0[4] = {0, 0, 0, 0}, s1[4] = {0, 0, 0, 0};
            #pragma unroll
            for (int ks = 0; ks < 4; ks++) {
                uint32_t off = (uint32_t)(((ni2 * 16 + browc) * AT_LD + ks * 16 + bcolc) * 2);
                uint32_t kf4[4];
                LDMX4(kf4, smb + OK*2 + bufo + off);
                MMA16816H(s0, qf[ks], &kf4[0]);
                MMA16816H(s1, qf[ks], &kf4[2]);
            }
            #pragma unroll
            for (int n8p = 0; n8p < 2; n8p++) {
                const float* sp = n8p ? s1 : s0;
                int col = kb * 64 + ni2 * 16 + n8p * 8 + t4 * 2;
                float2 mm = *(float2*)&madd[col];
                #pragma unroll
                for (int rh = 0; rh < 2; rh++) {
                    __half2 bb = *(const __half2*)
                        &Bb[(size_t)(w * 16 + g + rh * 8) * SEQ + col];
                    float2 bf = __half22float2(bb);
                    sv[rh][ni2*4 + n8p*2 + 0] = sp[rh*2 + 0] + bf.x + mm.x;
                    sv[rh][ni2*4 + n8p*2 + 1] = sp[rh*2 + 1] + bf.y + mm.y;
                }
            }
        }

        // ---- online softmax ----
        float corr[2];
        #pragma unroll
        for (int rh = 0; rh < 2; rh++) {
            float rmx = -1e30f;
            #pragma unroll
            for (int i = 0; i < 16; i++) rmx = fmaxf(rmx, sv[rh][i]);
            rmx = fmaxf(rmx, __shfl_xor_sync(0xffffffffu, rmx, 1));
            rmx = fmaxf(rmx, __shfl_xor_sync(0xffffffffu, rmx, 2));
            float mnew = fmaxf(mrun[rh], rmx);
            corr[rh] = __expf(mrun[rh] - mnew);
            mrun[rh] = mnew;
            float rs = 0.0f;
            #pragma unroll
            for (int i = 0; i < 16; i++) {
                float p = __expf(sv[rh][i] - mnew);
                sv[rh][i] = p;
                rs += p;
            }
            rs += __shfl_xor_sync(0xffffffffu, rs, 1);
            rs += __shfl_xor_sync(0xffffffffu, rs, 2);
            lrun[rh] = lrun[rh] * corr[rh] + rs;
        }
        #pragma unroll
        for (int ni2 = 0; ni2 < 4; ni2++)
            #pragma unroll
            for (int n8p = 0; n8p < 2; n8p++) {
                o[ni2][n8p][0] *= corr[0];
                o[ni2][n8p][1] *= corr[0];
                o[ni2][n8p][2] *= corr[1];
                o[ni2][n8p][3] *= corr[1];
            }

        // ---- O += P V (fp16 single pass) ----
        #pragma unroll
        for (int ks = 0; ks < 4; ks++) {
            uint32_t pf[4];
            pf[0] = packh2(sv[0][ks*4 + 0], sv[0][ks*4 + 1]);
            pf[1] = packh2(sv[1][ks*4 + 0], sv[1][ks*4 + 1]);
            pf[2] = packh2(sv[0][ks*4 + 2], sv[0][ks*4 + 3]);
            pf[3] = packh2(sv[1][ks*4 + 2], sv[1][ks*4 + 3]);
            #pragma unroll
            for (int ni2 = 0; ni2 < 4; ni2++) {
                uint32_t off = (uint32_t)(((ni2 * 16 + browc) * AT_LD + ks * 16 + bcolc) * 2);
                uint32_t vf4[4];
                LDMX4(vf4, smb + OV*2 + bufo + off);
                MMA16816H(o[ni2][0], pf, &vf4[0]);
                MMA16816H(o[ni2][1], pf, &vf4[2]);
            }
        }
    }

    // ---- epilogue: normalize, split hi/lo, write ctx ----
    float inv[2] = {1.0f / lrun[0], 1.0f / lrun[1]};
    #pragma unroll
    for (int ni2 = 0; ni2 < 4; ni2++) {
        #pragma unroll
        for (int n8p = 0; n8p < 2; n8p++) {
            int col = h * 64 + ni2 * 16 + n8p * 8 + t4 * 2;
            #pragma unroll
            for (int rh = 0; rh < 2; rh++) {
                size_t m = (size_t)b * SEQ + qb * 128 + w * 16 + g + rh * 8;
                float v0 = o[ni2][n8p][rh*2 + 0] * inv[rh];
                float v1 = o[ni2][n8p][rh*2 + 1] * inv[rh];
                uint32_t hiw, low;
                split2(v0, v1, hiw, low);
                *(uint32_t*)&g_Ahi[m * HID + col] = hiw;
                *(uint32_t*)&g_Alo[m * HID + col] = low;
            }
        }
    }
}

// ---------------- launch ----------------
extern "C" void kernel_launch(void* const* d_in, const int* in_sizes, int n_in,
                              void* d_out, int out_size)
{
    const float* x    = (const float*)d_in[0];
    const float* dist = (const float*)d_in[1];
    const unsigned char* mask = (const unsigned char*)d_in[2];
    const float* Wq = (const float*)d_in[3];
    const float* bq = (const float*)d_in[4];
    const float* Wk = (const float*)d_in[5];
    const float* bk = (const float*)d_in[6];
    const float* Wv = (const float*)d_in[7];
    const float* bv = (const float*)d_in[8];
    const float* Wo = (const float*)d_in[9];
    const float* bo = (const float*)d_in[10];
    const float* Wd = (const float*)d_in[11];
    const float* bd = (const float*)d_in[12];
    float* out = (float*)d_out;

    cudaFuncSetAttribute(fused_qkv_dist_kernel, cudaFuncAttributeMaxDynamicSharedMemorySize,
                         GEMM_SMEM_BYTES);
    cudaFuncSetAttribute(gemm_out_kernel, cudaFuncAttributeMaxDynamicSharedMemorySize,
                         GEMM_SMEM_BYTES);
    cudaFuncSetAttribute(attn_mma_kernel, cudaFuncAttributeMaxDynamicSharedMemorySize,
                         ATTN_SMEM_BYTES);

    prep_kernel<<<3073, 256>>>(x, Wq, Wk, Wv, Wo, mask);
    fused_qkv_dist_kernel<<<8576, 256, GEMM_SMEM_BYTES>>>(bq, bk, bv, dist, Wd, bd);
    attn_mma_kernel<<<dim3(4, NH, NB), 256, ATTN_SMEM_BYTES>>>();
    gemm_out_kernel<<<dim3(4, 32), 256, GEMM_SMEM_BYTES>>>(bo, out);
}

// round 9
// speedup vs baseline: 2.4175x; 1.0075x over previous
#include <cuda_runtime.h>
#include <cuda_bf16.h>
#include <cuda_fp16.h>
#include <stdint.h>
#include <math.h>

#define NB 8
#define NH 8
#define SEQ 512
#define HID 512
#define HD 64

// ---------------- scratch (device globals; no allocations) ----------------
__device__ float g_maskf[NB*SEQ];                        // 0/1 floats
__device__ __half g_biasf[(size_t)NB*NH*SEQ*SEQ];        // 32 MB fp16 bias
__device__ __half g_Qf[NB*NH*SEQ*HD];                    // [b,h,n,d] (pre-scaled)
__device__ __half g_Kf[NB*NH*SEQ*HD];                    // [b,h,n,d]
__device__ __half g_VTf[NB*NH*SEQ*HD];                   // [b,h,d,n]
__device__ __nv_bfloat16 g_Ahi[NB*SEQ*HID], g_Alo[NB*SEQ*HID];   // x / ctx
__device__ __nv_bfloat16 g_WThi[4][HID*HID], g_WTlo[4][HID*HID]; // W^T [n][k]

// ---------------- PTX helpers ----------------
__device__ __forceinline__ uint32_t sm_u32(const void* p) {
    return (uint32_t)__cvta_generic_to_shared(p);
}
#define CP16(dst_u32, gptr) \
    asm volatile("cp.async.ca.shared.global [%0], [%1], 16;" :: "r"(dst_u32), "l"(gptr))
#define CP_COMMIT() asm volatile("cp.async.commit_group;")
#define CP_WAIT0()  asm volatile("cp.async.wait_group 0;")
#define LDMX4(r, addr) \
    asm volatile("ldmatrix.sync.aligned.m8n8.x4.shared.b16 {%0,%1,%2,%3}, [%4];" \
        : "=r"((r)[0]), "=r"((r)[1]), "=r"((r)[2]), "=r"((r)[3]) : "r"(addr))
#define MMA16816(d, a, b) \
    asm volatile("mma.sync.aligned.m16n8k16.row.col.f32.bf16.bf16.f32 " \
        "{%0,%1,%2,%3},{%4,%5,%6,%7},{%8,%9},{%0,%1,%2,%3};\n" \
        : "+f"((d)[0]), "+f"((d)[1]), "+f"((d)[2]), "+f"((d)[3]) \
        : "r"((a)[0]), "r"((a)[1]), "r"((a)[2]), "r"((a)[3]), "r"((b)[0]), "r"((b)[1]))
#define MMA16816H(d, a, b) \
    asm volatile("mma.sync.aligned.m16n8k16.row.col.f32.f16.f16.f32 " \
        "{%0,%1,%2,%3},{%4,%5,%6,%7},{%8,%9},{%0,%1,%2,%3};\n" \
        : "+f"((d)[0]), "+f"((d)[1]), "+f"((d)[2]), "+f"((d)[3]) \
        : "r"((a)[0]), "r"((a)[1]), "r"((a)[2]), "r"((a)[3]), "r"((b)[0]), "r"((b)[1]))

// split pair (a=elem0, b=elem1) into packed bf16x2 hi and lo residual
__device__ __forceinline__ void split2(float a, float b, uint32_t& hi, uint32_t& lo) {
    __nv_bfloat16 ha = __float2bfloat16(a), hb = __float2bfloat16(b);
    __nv_bfloat16 la = __float2bfloat16(a - __bfloat162float(ha));
    __nv_bfloat16 lb = __float2bfloat16(b - __bfloat162float(hb));
    hi = ((uint32_t)__bfloat16_as_ushort(hb) << 16) | (uint32_t)__bfloat16_as_ushort(ha);
    lo = ((uint32_t)__bfloat16_as_ushort(lb) << 16) | (uint32_t)__bfloat16_as_ushort(la);
}

__device__ __forceinline__ uint32_t packh2(float a, float b) {
    __half2 h = __floats2half2_rn(a, b);
    return *reinterpret_cast<uint32_t*>(&h);
}

// ================= prep kernel: conv_pair(x) + conv_wT + mask ==============
__global__ __launch_bounds__(256) void prep_kernel(
    const float* __restrict__ x,
    const float* __restrict__ Wq, const float* __restrict__ Wk,
    const float* __restrict__ Wv, const float* __restrict__ Wo,
    const unsigned char* __restrict__ raw)
{
    __shared__ float t[32][33];
    __shared__ int mode;
    const int bx = blockIdx.x;
    const int tid = threadIdx.x;

    if (bx < 2048) {
        // ---- x -> hi/lo bf16 split ----
        int i = bx * 256 + tid;                 // over float4s (2M floats)
        float4 v = ((const float4*)x)[i];
        uint32_t h0, l0, h1, l1;
        split2(v.x, v.y, h0, l0);
        split2(v.z, v.w, h1, l1);
        uint32_t* hp = (uint32_t*)(g_Ahi + 4*(size_t)i);
        uint32_t* lp = (uint32_t*)(g_Alo + 4*(size_t)i);
        hp[0] = h0; hp[1] = h1;
        lp[0] = l0; lp[1] = l1;
    } else if (bx < 3072) {
        // ---- W -> W^T hi/lo (32x32 tile transpose) ----
        const int tt = bx - 2048;               // 0..1023
        const int z = tt >> 8;
        const int bxx = tt & 15, byy = (tt >> 4) & 15;
        const float* W = (z == 0) ? Wq : (z == 1) ? Wk : (z == 2) ? Wv : Wo;
        __nv_bfloat16* Th = g_WThi[z];
        __nv_bfloat16* Tl = g_WTlo[z];
        int tx = tid & 31, ty = tid >> 5;       // 32 x 8
        int n0 = bxx * 32, k0 = byy * 32;
        #pragma unroll
        for (int j = 0; j < 4; j++)
            t[ty + 8*j][tx] = W[(size_t)(k0 + ty + 8*j) * HID + n0 + tx];
        __syncthreads();
        #pragma unroll
        for (int j = 0; j < 4; j++) {
            float v = t[tx][ty + 8*j];
            __nv_bfloat16 h = __float2bfloat16(v);
            __nv_bfloat16 l = __float2bfloat16(v - __bfloat162float(h));
            size_t o = (size_t)(n0 + ty + 8*j) * HID + k0 + tx;
            Th[o] = h;
            Tl[o] = l;
        }
    } else {
        // ---- mask normalization (dtype-agnostic) ----
        if (tid == 0) {
            const unsigned int* w = (const unsigned int*)raw;
            int cf = 0, byteish = 0;
            for (int i = 0; i < 128; i++) {
                unsigned int v = w[i];
                if (v == 0x3F800000u) cf++;
                bool b01 = true;
                #pragma unroll
                for (int bb = 0; bb < 4; bb++) {
                    unsigned int by = (v >> (8*bb)) & 0xFFu;
                    if (by > 1u) b01 = false;
                }
                if (b01 && v > 1u) byteish++;
            }
            mode = (cf > 64) ? 0 : ((byteish > 0) ? 2 : 1);  // 0=f32, 1=i32, 2=u8
        }
        __syncthreads();
        int md = mode;
        for (int i = tid; i < NB*SEQ; i += 256) {
            float m;
            if (md == 0)      m = (((const float*)raw)[i] != 0.0f) ? 1.0f : 0.0f;
            else if (md == 1) m = (((const int*)raw)[i]   != 0)    ? 1.0f : 0.0f;
            else              m = (raw[i]                 != 0)    ? 1.0f : 0.0f;
            g_maskf[i] = m;
        }
    }
}

// ================= bf16x3 tensor-core GEMM core (verified R4) =============
#define GBK 32
#define LDT 40
#define BUF_ELEMS (128 * LDT)
#define AH_OFS 0
#define ALO_OFS (2 * BUF_ELEMS)
#define BH_OFS  (4 * BUF_ELEMS)
#define BLO_OFS (6 * BUF_ELEMS)
#define GEMM_SMEM_BYTES (8 * BUF_ELEMS * 2)

__device__ __forceinline__ void bf16x3_gemm(
    const __nv_bfloat16* __restrict__ Ahi, const __nv_bfloat16* __restrict__ Alo,
    const __nv_bfloat16* __restrict__ Bhi, const __nv_bfloat16* __restrict__ Blo,
    int m0, int n0, __nv_bfloat16* sm, float acc[4][4][4])
{
    const int tid = threadIdx.x;
    const int lane = tid & 31, wid = tid >> 5;
    const int wm = wid >> 2, wn = wid & 3;
    const uint32_t smb = sm_u32(sm);

    #pragma unroll
    for (int mi = 0; mi < 4; mi++)
        #pragma unroll
        for (int ni = 0; ni < 4; ni++)
            #pragma unroll
            for (int r = 0; r < 4; r++) acc[mi][ni][r] = 0.0f;

    const int c0 = tid, c1 = tid + 256;
    const int r0 = c0 >> 2, s0 = c0 & 3;
    const int r1 = c1 >> 2, s1 = c1 & 3;

    auto load_chunk = [&](int kc, int buf) {
        const int k0 = kc * GBK;
        const uint32_t so0 = (uint32_t)(buf * BUF_ELEMS + r0 * LDT + s0 * 8) * 2;
        const uint32_t so1 = (uint32_t)(buf * BUF_ELEMS + r1 * LDT + s1 * 8) * 2;
        const size_t ga0 = (size_t)(m0 + r0) * HID + k0 + s0 * 8;
        const size_t ga1 = (size_t)(m0 + r1) * HID + k0 + s1 * 8;
        const size_t gb0 = (size_t)(n0 + r0) * HID + k0 + s0 * 8;
        const size_t gb1 = (size_t)(n0 + r1) * HID + k0 + s1 * 8;
        CP16(smb + AH_OFS*2  + so0, Ahi + ga0);
        CP16(smb + AH_OFS*2  + so1, Ahi + ga1);
        CP16(smb + ALO_OFS*2 + so0, Alo + ga0);
        CP16(smb + ALO_OFS*2 + so1, Alo + ga1);
        CP16(smb + BH_OFS*2  + so0, Bhi + gb0);
        CP16(smb + BH_OFS*2  + so1, Bhi + gb1);
        CP16(smb + BLO_OFS*2 + so0, Blo + gb0);
        CP16(smb + BLO_OFS*2 + so1, Blo + gb1);
    };

    const int arow = wm * 64 + (lane & 15);
    const int acolb = (lane >> 4) << 3;
    const int brow = wn * 32 + (lane & 7) + ((lane & 16) >> 1);
    const int bcolb = lane & 8;

    load_chunk(0, 0);
    CP_COMMIT();

    for (int kc = 0; kc < HID / GBK; kc++) {
        CP_WAIT0();
        __syncthreads();
        if (kc + 1 < HID / GBK) {
            load_chunk(kc + 1, (kc + 1) & 1);
            CP_COMMIT();
        }
        const int buf = kc & 1;
        #pragma unroll
        for (int ks = 0; ks < 2; ks++) {
            uint32_t ah[4][4], al[4][4], bh[2][4], bl[2][4];
            const int acol = ks * 16 + acolb;
            const int bcol = ks * 16 + bcolb;
            #pragma unroll
            for (int mi = 0; mi < 4; mi++) {
                uint32_t off = (uint32_t)(buf * BUF_ELEMS + (arow + mi*16) * LDT + acol) * 2;
                LDMX4(ah[mi], smb + AH_OFS*2 + off);
                LDMX4(al[mi], smb + ALO_OFS*2 + off);
            }
            #pragma unroll
            for (int p = 0; p < 2; p++) {
                uint32_t off = (uint32_t)(buf * BUF_ELEMS + (brow + p*16) * LDT + bcol) * 2;
                LDMX4(bh[p], smb + BH_OFS*2 + off);
                LDMX4(bl[p], smb + BLO_OFS*2 + off);
            }
            #pragma unroll
            for (int mi = 0; mi < 4; mi++)
                #pragma unroll
                for (int ni = 0; ni < 4; ni++) {
                    uint32_t* bhf = &bh[ni >> 1][(ni & 1) * 2];
                    uint32_t* blf = &bl[ni >> 1][(ni & 1) * 2];
                    MMA16816(acc[mi][ni], ah[mi], bhf);
                    MMA16816(acc[mi][ni], ah[mi], blf);
                    MMA16816(acc[mi][ni], al[mi], bhf);
                }
        }
        __syncthreads();
    }
}

// ---------------- qkv block body (one 128x128 tile of one of Q/K/V) --------
__device__ __forceinline__ void qkv_block(
    int qkv_id, __nv_bfloat16* sm,
    const float* __restrict__ bq, const float* __restrict__ bk,
    const float* __restrict__ bv)
{
    const int z = qkv_id >> 7;            // 0..2
    const int rem = qkv_id & 127;
    const int m0 = (rem >> 2) * 128;      // 32 m-tiles
    const int n0 = (rem & 3) * 128;       // 4 n-tiles
    const float* bias = (z == 0) ? bq : (z == 1) ? bk : bv;

    float acc[4][4][4];
    bf16x3_gemm(g_Ahi, g_Alo, g_WThi[z], g_WTlo[z], m0, n0, sm, acc);

    const int lane = threadIdx.x & 31, wid = threadIdx.x >> 5;
    const int wm = wid >> 2, wn = wid & 3;
    const int g = lane >> 2, tg = lane & 3;
    const float scale = (z == 0) ? 0.125f : 1.0f;

    __half* OUTF = (z == 0) ? g_Qf : g_Kf;

    #pragma unroll
    for (int mi = 0; mi < 4; mi++) {
        #pragma unroll
        for (int ni = 0; ni < 4; ni++) {
            int c = n0 + wn * 32 + ni * 8 + tg * 2;
            int hh = c >> 6, d = c & 63;
            float b0 = bias[c], b1 = bias[c + 1];
            #pragma unroll
            for (int half = 0; half < 2; half++) {
                int m = m0 + wm * 64 + mi * 16 + g + half * 8;
                int bb = m >> 9, n = m & 511;
                int bh = bb * NH + hh;
                float v0 = (acc[mi][ni][half*2 + 0] + b0) * scale;
                float v1 = (acc[mi][ni][half*2 + 1] + b1) * scale;
                if (z < 2) {
                    size_t a = ((size_t)bh * SEQ + n) * HD + d;
                    *(__half2*)&OUTF[a] = __floats2half2_rn(v0, v1);
                } else {
                    // V stored transposed: [b,h,d,n]
                    size_t a0 = ((size_t)bh * HD + d) * SEQ + n;
                    g_VTf[a0]       = __float2half(v0);
                    g_VTf[a0 + SEQ] = __float2half(v1);
                }
            }
        }
    }
}

// ---------------- dist block body ([256 rows, 64] @ [64, 8] + bd) ----------
__device__ __forceinline__ void dist_block(
    int dist_id, float* w /*shared 512+8*/,
    const float* __restrict__ D, const float* __restrict__ Wd,
    const float* __restrict__ bd)
{
    float* bsm = w + 512;
    const int tid = threadIdx.x;
    w[tid]       = Wd[tid];
    w[tid + 256] = Wd[tid + 256];
    if (tid < 8) bsm[tid] = bd[tid];
    __syncthreads();

    size_t r = (size_t)dist_id * 256 + tid;          // row over B*N*N
    const float* row = D + r * 64;
    float acc[8] = {0, 0, 0, 0, 0, 0, 0, 0};
    #pragma unroll
    for (int t = 0; t < 16; t++) {
        float4 v = __ldcs((const float4*)&row[t * 4]);
        float vv[4] = {v.x, v.y, v.z, v.w};
        #pragma unroll
        for (int e = 0; e < 4; e++) {
            int d = t * 4 + e;
            #pragma unroll
            for (int h = 0; h < 8; h++)
                acc[h] = fmaf(vv[e], w[d * 8 + h], acc[h]);
        }
    }
    int b = (int)(r >> 18);
    int rem = (int)(r & 262143);
    int q = rem >> 9, k = rem & 511;
    #pragma unroll
    for (int h = 0; h < 8; h++)
        g_biasf[(((size_t)(b * NH + h)) * SEQ + q) * SEQ + k] =
            __float2half(acc[h] + bsm[h]);
}

// ============== fused kernel: qkv GEMM (tensor) ∥ dist_bias (HBM) ==========
__global__ __launch_bounds__(256, 2) void fused_qkv_dist_kernel(
    const float* __restrict__ bq, const float* __restrict__ bk,
    const float* __restrict__ bv,
    const float* __restrict__ D, const float* __restrict__ Wd,
    const float* __restrict__ bd)
{
    extern __shared__ __nv_bfloat16 sm[];
    const int idx = blockIdx.x;
    const bool is_qkv = ((idx % 22) == 0) && (idx < 8448);
    if (is_qkv) {
        qkv_block(idx / 22, sm, bq, bk, bv);
    } else {
        const int nq_before = (idx < 8448) ? (idx / 22 + 1) : 384;
        dist_block(idx - nq_before, (float*)sm, D, Wd, bd);
    }
}

// ---------------- output projection (reads ctx hi/lo written by attn) ------
__global__ __launch_bounds__(256) void gemm_out_kernel(
    const float* __restrict__ bo, float* __restrict__ OUT)
{
    extern __shared__ __nv_bfloat16 sm[];
    const int m0 = blockIdx.y * 128, n0 = blockIdx.x * 128;

    float acc[4][4][4];
    bf16x3_gemm(g_Ahi, g_Alo, g_WThi[3], g_WTlo[3], m0, n0, sm, acc);

    const int lane = threadIdx.x & 31, wid = threadIdx.x >> 5;
    const int wm = wid >> 2, wn = wid & 3;
    const int g = lane >> 2, tg = lane & 3;

    #pragma unroll
    for (int mi = 0; mi < 4; mi++) {
        #pragma unroll
        for (int ni = 0; ni < 4; ni++) {
            int c = n0 + wn * 32 + ni * 8 + tg * 2;
            float b0 = bo[c], b1 = bo[c + 1];
            #pragma unroll
            for (int half = 0; half < 2; half++) {
                int m = m0 + wm * 64 + mi * 16 + g + half * 8;
                float mf = g_maskf[m];
                float2 v;
                v.x = (mf > 0.5f) ? acc[mi][ni][half*2 + 0] + b0 : 0.0f;
                v.y = (mf > 0.5f) ? acc[mi][ni][half*2 + 1] + b1 : 0.0f;
                *(float2*)&OUT[(size_t)m * HID + c] = v;
            }
        }
    }
}

// ======= fp16 tensor-core flash attention: CTA = (qb128, h, b), 8 warps ====
// smem halves layout: Q | K[2] | V[2] | BIAS[2] ; mask floats at tail
#define AT_LD 72                      // fp16 row stride (144B, ldmatrix-safe)
#define BT_LD 72                      // bias tile row stride (conflict-free)
#define OQ 0                          // Q: 128 x AT_LD = 9216 halves
#define OK 9216                       // K: [2 buf][4608]
#define OV 18432                      // V^T: [2 buf][4608]
#define OB 27648                      // bias: [2 buf][128*BT_LD = 9216]
#define AT_MADD_B 92160               // byte offset of mask floats (46080 halves)
#define ATTN_SMEM_BYTES (92160 + 2048)

__device__ __forceinline__ void attn_load_kv(
    uint32_t smb, int buf, int kb, int tid,
    const __half* Kf, const __half* Vf, const __half* Bb)
{
    const uint32_t bo = (uint32_t)(buf * 4608 * 2);
    #pragma unroll
    for (int j = 0; j < 2; j++) {
        int ch = j * 256 + tid;                // 512 chunks per matrix
        int r = ch >> 3, cc = ch & 7;
        uint32_t so = (uint32_t)((r * AT_LD + cc * 8) * 2);
        CP16(smb + OK*2 + bo + so, Kf + (size_t)(kb * 64 + r) * HD + cc * 8);
        CP16(smb + OV*2 + bo + so, Vf + (size_t)r * SEQ + kb * 64 + cc * 8);
    }
    // bias tile: 128 rows x 64 halves (128B rows, fully coalesced)
    const uint32_t bob = (uint32_t)(buf * 9216 * 2);
    #pragma unroll
    for (int j = 0; j < 4; j++) {
        int ch = j * 256 + tid;                // 1024 chunks
        int r = ch >> 3, cc = ch & 7;
        uint32_t so = (uint32_t)((r * BT_LD + cc * 8) * 2);
        CP16(smb + OB*2 + bob + so, Bb + (size_t)r * SEQ + kb * 64 + cc * 8);
    }
}

__global__ __launch_bounds__(256, 2) void attn_mma_kernel() {
    extern __shared__ __half smH[];
    float* madd = (float*)((char*)smH + AT_MADD_B);
    const uint32_t smb = sm_u32(smH);
    const int tid = threadIdx.x, lane = tid & 31, w = tid >> 5;   // 8 warps
    const int qb = blockIdx.x, h = blockIdx.y, b = blockIdx.z;
    const int bh = b * NH + h;
    const int g = lane >> 2, t4 = lane & 3;

    const __half* Qf = g_Qf + ((size_t)bh * SEQ + qb * 128) * HD;
    const __half* Kf = g_Kf + (size_t)bh * SEQ * HD;
    const __half* Vf = g_VTf + (size_t)bh * HD * SEQ;
    const __half* Bb = g_biasf + ((size_t)bh * SEQ + qb * 128) * SEQ;

    // additive key mask into smem
    #pragma unroll
    for (int j = 0; j < 2; j++) {
        int i = j * 256 + tid;
        madd[i] = (g_maskf[b * SEQ + i] > 0.5f) ? 0.0f : -1e9f;
    }

    // Q tile (128 x 64) + first KV+bias tiles
    #pragma unroll
    for (int j = 0; j < 4; j++) {
        int ch = j * 256 + tid;                // 1024 chunks
        int r = ch >> 3, cc = ch & 7;
        uint32_t so = (uint32_t)((r * AT_LD + cc * 8) * 2);
        CP16(smb + OQ*2 + so, Qf + (size_t)r * HD + cc * 8);
    }
    attn_load_kv(smb, 0, 0, tid, Kf, Vf, Bb);
    CP_COMMIT();
    CP_WAIT0();
    __syncthreads();

    // Q fragments (A, m16k16 per k-step); warp w owns rows [w*16, w*16+16)
    uint32_t qf[4][4];
    {
        int arow = w * 16 + (lane & 15);
        int acolb = (lane >> 4) << 3;
        #pragma unroll
        for (int ks = 0; ks < 4; ks++) {
            uint32_t off = (uint32_t)((arow * AT_LD + ks * 16 + acolb) * 2);
            LDMX4(qf[ks], smb + OQ*2 + off);
        }
    }

    float o[4][2][4];
    #pragma unroll
    for (int i = 0; i < 4; i++)
        #pragma unroll
        for (int j = 0; j < 2; j++)
            #pragma unroll
            for (int r = 0; r < 4; r++) o[i][j][r] = 0.0f;
    float mrun[2] = {-1e30f, -1e30f}, lrun[2] = {0.0f, 0.0f};

    const int browc = (lane & 7) + ((lane & 16) >> 1);
    const int bcolc = lane & 8;

    for (int kb = 0; kb < 8; kb++) {
        if (kb > 0) { CP_WAIT0(); __syncthreads(); }
        if (kb + 1 < 8) {
            attn_load_kv(smb, (kb + 1) & 1, kb + 1, tid, Kf, Vf, Bb);
            CP_COMMIT();
        }
        const uint32_t bufo  = (uint32_t)((kb & 1) * 4608 * 2);
        const int      bbase = OB + (kb & 1) * 9216;

        // ---- S = Q K^T (fp16, single pass) + bias(smem) + mask ----
        float sv[2][16];
        #pragma unroll
        for (int ni2 = 0; ni2 < 4; ni2++) {
            float s0[4] = {0, 0, 0, 0}, s1[4] = {0, 0, 0, 0};
            #pragma unroll
            for (int ks = 0; ks < 4; ks++) {
                uint32_t off = (uint32_t)(((ni2 * 16 + browc) * AT_LD + ks * 16 + bcolc) * 2);
                uint32_t kf4[4];
                LDMX4(kf4, smb + OK*2 + bufo + off);
                MMA16816H(s0, qf[ks], &kf4[0]);
                MMA16816H(s1, qf[ks], &kf4[2]);
            }
            #pragma unroll
            for (int n8p = 0; n8p < 2; n8p++) {
                const float* sp = n8p ? s1 : s0;
                int lcol = ni2 * 16 + n8p * 8 + t4 * 2;
                float2 mm = *(float2*)&madd[kb * 64 + lcol];
                #pragma unroll
                for (int rh = 0; rh < 2; rh++) {
                    __half2 bb = *(const __half2*)
                        &smH[bbase + (w * 16 + g + rh * 8) * BT_LD + lcol];
                    float2 bf = __half22float2(bb);
                    sv[rh][ni2*4 + n8p*2 + 0] = sp[rh*2 + 0] + bf.x + mm.x;
                    sv[rh][ni2*4 + n8p*2 + 1] = sp[rh*2 + 1] + bf.y + mm.y;
                }
            }
        }

        // ---- online softmax ----
        float corr[2];
        #pragma unroll
        for (int rh = 0; rh < 2; rh++) {
            float rmx = -1e30f;
            #pragma unroll
            for (int i = 0; i < 16; i++) rmx = fmaxf(rmx, sv[rh][i]);
            rmx = fmaxf(rmx, __shfl_xor_sync(0xffffffffu, rmx, 1));
            rmx = fmaxf(rmx, __shfl_xor_sync(0xffffffffu, rmx, 2));
            float mnew = fmaxf(mrun[rh], rmx);
            corr[rh] = __expf(mrun[rh] - mnew);
            mrun[rh] = mnew;
            float rs = 0.0f;
            #pragma unroll
            for (int i = 0; i < 16; i++) {
                float p = __expf(sv[rh][i] - mnew);
                sv[rh][i] = p;
                rs += p;
            }
            rs += __shfl_xor_sync(0xffffffffu, rs, 1);
            rs += __shfl_xor_sync(0xffffffffu, rs, 2);
            lrun[rh] = lrun[rh] * corr[rh] + rs;
        }
        #pragma unroll
        for (int ni2 = 0; ni2 < 4; ni2++)
            #pragma unroll
            for (int n8p = 0; n8p < 2; n8p++) {
                o[ni2][n8p][0] *= corr[0];
                o[ni2][n8p][1] *= corr[0];
                o[ni2][n8p][2] *= corr[1];
                o[ni2][n8p][3] *= corr[1];
            }

        // ---- O += P V (fp16 single pass) ----
        #pragma unroll
        for (int ks = 0; ks < 4; ks++) {
            uint32_t pf[4];
            pf[0] = packh2(sv[0][ks*4 + 0], sv[0][ks*4 + 1]);
            pf[1] = packh2(sv[1][ks*4 + 0], sv[1][ks*4 + 1]);
            pf[2] = packh2(sv[0][ks*4 + 2], sv[0][ks*4 + 3]);
            pf[3] = packh2(sv[1][ks*4 + 2], sv[1][ks*4 + 3]);
            #pragma unroll
            for (int ni2 = 0; ni2 < 4; ni2++) {
                uint32_t off = (uint32_t)(((ni2 * 16 + browc) * AT_LD + ks * 16 + bcolc) * 2);
                uint32_t vf4[4];
                LDMX4(vf4, smb + OV*2 + bufo + off);
                MMA16816H(o[ni2][0], pf, &vf4[0]);
                MMA16816H(o[ni2][1], pf, &vf4[2]);
            }
        }
    }

    // ---- epilogue: normalize, split hi/lo, write ctx ----
    float inv[2] = {1.0f / lrun[0], 1.0f / lrun[1]};
    #pragma unroll
    for (int ni2 = 0; ni2 < 4; ni2++) {
        #pragma unroll
        for (int n8p = 0; n8p < 2; n8p++) {
            int col = h * 64 + ni2 * 16 + n8p * 8 + t4 * 2;
            #pragma unroll
            for (int rh = 0; rh < 2; rh++) {
                size_t m = (size_t)b * SEQ + qb * 128 + w * 16 + g + rh * 8;
                float v0 = o[ni2][n8p][rh*2 + 0] * inv[rh];
                float v1 = o[ni2][n8p][rh*2 + 1] * inv[rh];
                uint32_t hiw, low;
                split2(v0, v1, hiw, low);
                *(uint32_t*)&g_Ahi[m * HID + col] = hiw;
                *(uint32_t*)&g_Alo[m * HID + col] = low;
            }
        }
    }
}

// ---------------- launch ----------------
extern "C" void kernel_launch(void* const* d_in, const int* in_sizes, int n_in,
                              void* d_out, int out_size)
{
    const float* x    = (const float*)d_in[0];
    const float* dist = (const float*)d_in[1];
    const unsigned char* mask = (const unsigned char*)d_in[2];
    const float* Wq = (const float*)d_in[3];
    const float* bq = (const float*)d_in[4];
    const float* Wk = (const float*)d_in[5];
    const float* bk = (const float*)d_in[6];
    const float* Wv = (const float*)d_in[7];
    const float* bv = (const float*)d_in[8];
    const float* Wo = (const float*)d_in[9];
    const float* bo = (const float*)d_in[10];
    const float* Wd = (const float*)d_in[11];
    const float* bd = (const float*)d_in[12];
    float* out = (float*)d_out;

    cudaFuncSetAttribute(fused_qkv_dist_kernel, cudaFuncAttributeMaxDynamicSharedMemorySize,
                         GEMM_SMEM_BYTES);
    cudaFuncSetAttribute(gemm_out_kernel, cudaFuncAttributeMaxDynamicSharedMemorySize,
                         GEMM_SMEM_BYTES);
    cudaFuncSetAttribute(attn_mma_kernel, cudaFuncAttributeMaxDynamicSharedMemorySize,
                         ATTN_SMEM_BYTES);

    prep_kernel<<<3073, 256>>>(x, Wq, Wk, Wv, Wo, mask);
    fused_qkv_dist_kernel<<<8576, 256, GEMM_SMEM_BYTES>>>(bq, bk, bv, dist, Wd, bd);
    attn_mma_kernel<<<dim3(4, NH, NB), 256, ATTN_SMEM_BYTES>>>();
    gemm_out_kernel<<<dim3(4, 32), 256, GEMM_SMEM_BYTES>>>(bo, out);
}

// round 10
// speedup vs baseline: 3.0611x; 1.2662x over previous
#include <cuda_runtime.h>
#include <cuda_bf16.h>
#include <cuda_fp16.h>
#include <stdint.h>
#include <math.h>

#define NB 8
#define NH 8
#define SEQ 512
#define HID 512
#define HD 64

// ---------------- scratch (device globals; no allocations) ----------------
__device__ float g_maskf[NB*SEQ];                        // 0/1 floats
__device__ __half g_biasf[(size_t)NB*NH*SEQ*SEQ];        // 32 MB fp16 bias (+key mask)
__device__ __half g_Qf[NB*NH*SEQ*HD];                    // [b,h,n,d] (pre-scaled)
__device__ __half g_Kf[NB*NH*SEQ*HD];                    // [b,h,n,d]
__device__ __half g_VTf[NB*NH*SEQ*HD];                   // [b,h,d,n]
__device__ __nv_bfloat16 g_Ahi[NB*SEQ*HID], g_Alo[NB*SEQ*HID];   // x / ctx
__device__ __nv_bfloat16 g_WThi[4][HID*HID], g_WTlo[4][HID*HID]; // W^T [n][k]

// ---------------- PTX helpers ----------------
__device__ __forceinline__ uint32_t sm_u32(const void* p) {
    return (uint32_t)__cvta_generic_to_shared(p);
}
#define CP16(dst_u32, gptr) \
    asm volatile("cp.async.ca.shared.global [%0], [%1], 16;" :: "r"(dst_u32), "l"(gptr))
#define CP_COMMIT() asm volatile("cp.async.commit_group;")
#define CP_WAIT0()  asm volatile("cp.async.wait_group 0;")
#define LDMX4(r, addr) \
    asm volatile("ldmatrix.sync.aligned.m8n8.x4.shared.b16 {%0,%1,%2,%3}, [%4];" \
        : "=r"((r)[0]), "=r"((r)[1]), "=r"((r)[2]), "=r"((r)[3]) : "r"(addr))
#define MMA16816(d, a, b) \
    asm volatile("mma.sync.aligned.m16n8k16.row.col.f32.bf16.bf16.f32 " \
        "{%0,%1,%2,%3},{%4,%5,%6,%7},{%8,%9},{%0,%1,%2,%3};\n" \
        : "+f"((d)[0]), "+f"((d)[1]), "+f"((d)[2]), "+f"((d)[3]) \
        : "r"((a)[0]), "r"((a)[1]), "r"((a)[2]), "r"((a)[3]), "r"((b)[0]), "r"((b)[1]))
#define MMA16816H(d, a, b) \
    asm volatile("mma.sync.aligned.m16n8k16.row.col.f32.f16.f16.f32 " \
        "{%0,%1,%2,%3},{%4,%5,%6,%7},{%8,%9},{%0,%1,%2,%3};\n" \
        : "+f"((d)[0]), "+f"((d)[1]), "+f"((d)[2]), "+f"((d)[3]) \
        : "r"((a)[0]), "r"((a)[1]), "r"((a)[2]), "r"((a)[3]), "r"((b)[0]), "r"((b)[1]))

// split pair (a=elem0, b=elem1) into packed bf16x2 hi and lo residual
__device__ __forceinline__ void split2(float a, float b, uint32_t& hi, uint32_t& lo) {
    __nv_bfloat16 ha = __float2bfloat16(a), hb = __float2bfloat16(b);
    __nv_bfloat16 la = __float2bfloat16(a - __bfloat162float(ha));
    __nv_bfloat16 lb = __float2bfloat16(b - __bfloat162float(hb));
    hi = ((uint32_t)__bfloat16_as_ushort(hb) << 16) | (uint32_t)__bfloat16_as_ushort(ha);
    lo = ((uint32_t)__bfloat16_as_ushort(lb) << 16) | (uint32_t)__bfloat16_as_ushort(la);
}

__device__ __forceinline__ uint32_t packh2(float a, float b) {
    __half2 h = __floats2half2_rn(a, b);
    return *reinterpret_cast<uint32_t*>(&h);
}

// ================= prep kernel: conv_pair(x) + conv_wT + mask ==============
__global__ __launch_bounds__(256) void prep_kernel(
    const float* __restrict__ x,
    const float* __restrict__ Wq, const float* __restrict__ Wk,
    const float* __restrict__ Wv, const float* __restrict__ Wo,
    const unsigned char* __restrict__ raw)
{
    __shared__ float t[32][33];
    __shared__ int mode;
    const int bx = blockIdx.x;
    const int tid = threadIdx.x;

    if (bx < 2048) {
        // ---- x -> hi/lo bf16 split ----
        int i = bx * 256 + tid;                 // over float4s (2M floats)
        float4 v = ((const float4*)x)[i];
        uint32_t h0, l0, h1, l1;
        split2(v.x, v.y, h0, l0);
        split2(v.z, v.w, h1, l1);
        uint32_t* hp = (uint32_t*)(g_Ahi + 4*(size_t)i);
        uint32_t* lp = (uint32_t*)(g_Alo + 4*(size_t)i);
        hp[0] = h0; hp[1] = h1;
        lp[0] = l0; lp[1] = l1;
    } else if (bx < 3072) {
        // ---- W -> W^T hi/lo (32x32 tile transpose) ----
        const int tt = bx - 2048;               // 0..1023
        const int z = tt >> 8;
        const int bxx = tt & 15, byy = (tt >> 4) & 15;
        const float* W = (z == 0) ? Wq : (z == 1) ? Wk : (z == 2) ? Wv : Wo;
        __nv_bfloat16* Th = g_WThi[z];
        __nv_bfloat16* Tl = g_WTlo[z];
        int tx = tid & 31, ty = tid >> 5;       // 32 x 8
        int n0 = bxx * 32, k0 = byy * 32;
        #pragma unroll
        for (int j = 0; j < 4; j++)
            t[ty + 8*j][tx] = W[(size_t)(k0 + ty + 8*j) * HID + n0 + tx];
        __syncthreads();
        #pragma unroll
        for (int j = 0; j < 4; j++) {
            float v = t[tx][ty + 8*j];
            __nv_bfloat16 h = __float2bfloat16(v);
            __nv_bfloat16 l = __float2bfloat16(v - __bfloat162float(h));
            size_t o = (size_t)(n0 + ty + 8*j) * HID + k0 + tx;
            Th[o] = h;
            Tl[o] = l;
        }
    } else {
        // ---- mask normalization (dtype-agnostic) ----
        if (tid == 0) {
            const unsigned int* w = (const unsigned int*)raw;
            int cf = 0, byteish = 0;
            for (int i = 0; i < 128; i++) {
                unsigned int v = w[i];
                if (v == 0x3F800000u) cf++;
                bool b01 = true;
                #pragma unroll
                for (int bb = 0; bb < 4; bb++) {
                    unsigned int by = (v >> (8*bb)) & 0xFFu;
                    if (by > 1u) b01 = false;
                }
                if (b01 && v > 1u) byteish++;
            }
            mode = (cf > 64) ? 0 : ((byteish > 0) ? 2 : 1);  // 0=f32, 1=i32, 2=u8
        }
        __syncthreads();
        int md = mode;
        for (int i = tid; i < NB*SEQ; i += 256) {
            float m;
            if (md == 0)      m = (((const float*)raw)[i] != 0.0f) ? 1.0f : 0.0f;
            else if (md == 1) m = (((const int*)raw)[i]   != 0)    ? 1.0f : 0.0f;
            else              m = (raw[i]                 != 0)    ? 1.0f : 0.0f;
            g_maskf[i] = m;
        }
    }
}

// ================= bf16x3 tensor-core GEMM core (verified R4) =============
#define GBK 32
#define LDT 40
#define BUF_ELEMS (128 * LDT)
#define AH_OFS 0
#define ALO_OFS (2 * BUF_ELEMS)
#define BH_OFS  (4 * BUF_ELEMS)
#define BLO_OFS (6 * BUF_ELEMS)
#define GEMM_SMEM_BYTES (8 * BUF_ELEMS * 2)

__device__ __forceinline__ void bf16x3_gemm(
    const __nv_bfloat16* __restrict__ Ahi, const __nv_bfloat16* __restrict__ Alo,
    const __nv_bfloat16* __restrict__ Bhi, const __nv_bfloat16* __restrict__ Blo,
    int m0, int n0, __nv_bfloat16* sm, float acc[4][4][4])
{
    const int tid = threadIdx.x;
    const int lane = tid & 31, wid = tid >> 5;
    const int wm = wid >> 2, wn = wid & 3;
    const uint32_t smb = sm_u32(sm);

    #pragma unroll
    for (int mi = 0; mi < 4; mi++)
        #pragma unroll
        for (int ni = 0; ni < 4; ni++)
            #pragma unroll
            for (int r = 0; r < 4; r++) acc[mi][ni][r] = 0.0f;

    const int c0 = tid, c1 = tid + 256;
    const int r0 = c0 >> 2, s0 = c0 & 3;
    const int r1 = c1 >> 2, s1 = c1 & 3;

    auto load_chunk = [&](int kc, int buf) {
        const int k0 = kc * GBK;
        const uint32_t so0 = (uint32_t)(buf * BUF_ELEMS + r0 * LDT + s0 * 8) * 2;
        const uint32_t so1 = (uint32_t)(buf * BUF_ELEMS + r1 * LDT + s1 * 8) * 2;
        const size_t ga0 = (size_t)(m0 + r0) * HID + k0 + s0 * 8;
        const size_t ga1 = (size_t)(m0 + r1) * HID + k0 + s1 * 8;
        const size_t gb0 = (size_t)(n0 + r0) * HID + k0 + s0 * 8;
        const size_t gb1 = (size_t)(n0 + r1) * HID + k0 + s1 * 8;
        CP16(smb + AH_OFS*2  + so0, Ahi + ga0);
        CP16(smb + AH_OFS*2  + so1, Ahi + ga1);
        CP16(smb + ALO_OFS*2 + so0, Alo + ga0);
        CP16(smb + ALO_OFS*2 + so1, Alo + ga1);
        CP16(smb + BH_OFS*2  + so0, Bhi + gb0);
        CP16(smb + BH_OFS*2  + so1, Bhi + gb1);
        CP16(smb + BLO_OFS*2 + so0, Blo + gb0);
        CP16(smb + BLO_OFS*2 + so1, Blo + gb1);
    };

    const int arow = wm * 64 + (lane & 15);
    const int acolb = (lane >> 4) << 3;
    const int brow = wn * 32 + (lane & 7) + ((lane & 16) >> 1);
    const int bcolb = lane & 8;

    load_chunk(0, 0);
    CP_COMMIT();

    for (int kc = 0; kc < HID / GBK; kc++) {
        CP_WAIT0();
        __syncthreads();
        if (kc + 1 < HID / GBK) {
            load_chunk(kc + 1, (kc + 1) & 1);
            CP_COMMIT();
        }
        const int buf = kc & 1;
        #pragma unroll
        for (int ks = 0; ks < 2; ks++) {
            uint32_t ah[4][4], al[4][4], bh[2][4], bl[2][4];
            const int acol = ks * 16 + acolb;
            const int bcol = ks * 16 + bcolb;
            #pragma unroll
            for (int mi = 0; mi < 4; mi++) {
                uint32_t off = (uint32_t)(buf * BUF_ELEMS + (arow + mi*16) * LDT + acol) * 2;
                LDMX4(ah[mi], smb + AH_OFS*2 + off);
                LDMX4(al[mi], smb + ALO_OFS*2 + off);
            }
            #pragma unroll
            for (int p = 0; p < 2; p++) {
                uint32_t off = (uint32_t)(buf * BUF_ELEMS + (brow + p*16) * LDT + bcol) * 2;
                LDMX4(bh[p], smb + BH_OFS*2 + off);
                LDMX4(bl[p], smb + BLO_OFS*2 + off);
            }
            #pragma unroll
            for (int mi = 0; mi < 4; mi++)
                #pragma unroll
                for (int ni = 0; ni < 4; ni++) {
                    uint32_t* bhf = &bh[ni >> 1][(ni & 1) * 2];
                    uint32_t* blf = &bl[ni >> 1][(ni & 1) * 2];
                    MMA16816(acc[mi][ni], ah[mi], bhf);
                    MMA16816(acc[mi][ni], ah[mi], blf);
                    MMA16816(acc[mi][ni], al[mi], bhf);
                }
        }
        __syncthreads();
    }
}

// ---------------- qkv block body (one 128x128 tile of one of Q/K/V) --------
__device__ __forceinline__ void qkv_block(
    int qkv_id, __nv_bfloat16* sm,
    const float* __restrict__ bq, const float* __restrict__ bk,
    const float* __restrict__ bv)
{
    const int z = qkv_id >> 7;            // 0..2
    const int rem = qkv_id & 127;
    const int m0 = (rem >> 2) * 128;      // 32 m-tiles
    const int n0 = (rem & 3) * 128;       // 4 n-tiles
    const float* bias = (z == 0) ? bq : (z == 1) ? bk : bv;

    float acc[4][4][4];
    bf16x3_gemm(g_Ahi, g_Alo, g_WThi[z], g_WTlo[z], m0, n0, sm, acc);

    const int lane = threadIdx.x & 31, wid = threadIdx.x >> 5;
    const int wm = wid >> 2, wn = wid & 3;
    const int g = lane >> 2, tg = lane & 3;
    const float scale = (z == 0) ? 0.125f : 1.0f;

    __half* OUTF = (z == 0) ? g_Qf : g_Kf;

    #pragma unroll
    for (int mi = 0; mi < 4; mi++) {
        #pragma unroll
        for (int ni = 0; ni < 4; ni++) {
            int c = n0 + wn * 32 + ni * 8 + tg * 2;
            int hh = c >> 6, d = c & 63;
            float b0 = bias[c], b1 = bias[c + 1];
            #pragma unroll
            for (int half = 0; half < 2; half++) {
                int m = m0 + wm * 64 + mi * 16 + g + half * 8;
                int bb = m >> 9, n = m & 511;
                int bh = bb * NH + hh;
                float v0 = (acc[mi][ni][half*2 + 0] + b0) * scale;
                float v1 = (acc[mi][ni][half*2 + 1] + b1) * scale;
                if (z < 2) {
                    size_t a = ((size_t)bh * SEQ + n) * HD + d;
                    *(__half2*)&OUTF[a] = __floats2half2_rn(v0, v1);
                } else {
                    // V stored transposed: [b,h,d,n]
                    size_t a0 = ((size_t)bh * HD + d) * SEQ + n;
                    g_VTf[a0]       = __float2half(v0);
                    g_VTf[a0 + SEQ] = __float2half(v1);
                }
            }
        }
    }
}

// -------- dist block: smem-staged coalesced version --------
// smem layout (bytes): w[512]f @0 | bsm[8]f @2048 | rows 256x68f @2080 |
//                      outsm 8x256 half @71712  (total 75808 <= 81920)
__device__ __forceinline__ void dist_block(
    int dist_id, char* smraw,
    const float* __restrict__ D, const float* __restrict__ Wd,
    const float* __restrict__ bd)
{
    float* w     = (float*)smraw;
    float* bsm   = (float*)(smraw + 2048);
    float* rows  = (float*)(smraw + 2080);
    __half* outsm = (__half*)(smraw + 71712);
    const uint32_t rows_b = sm_u32(smraw + 2080);
    const int tid = threadIdx.x;

    // stage 256 rows x 256B into smem, fully coalesced 16B chunks
    const float* src = D + (size_t)dist_id * 256 * 64;
    #pragma unroll
    for (int j = 0; j < 16; j++) {
        int c = j * 256 + tid;
        int r = c >> 4, o = c & 15;
        CP16(rows_b + (uint32_t)(r * 272 + o * 16), src + (size_t)c * 4);
    }
    CP_COMMIT();

    w[tid]       = Wd[tid];
    w[tid + 256] = Wd[tid + 256];
    if (tid < 8) bsm[tid] = bd[tid];

    CP_WAIT0();
    __syncthreads();

    // thread-per-row compute from smem (68-float stride: LDS.128 conflict-free)
    const float* rp = rows + tid * 68;
    float acc[8] = {0, 0, 0, 0, 0, 0, 0, 0};
    #pragma unroll
    for (int t = 0; t < 16; t++) {
        float4 v = *(const float4*)(rp + t * 4);
        float vv[4] = {v.x, v.y, v.z, v.w};
        #pragma unroll
        for (int e = 0; e < 4; e++) {
            int d = t * 4 + e;
            #pragma unroll
            for (int h = 0; h < 8; h++)
                acc[h] = fmaf(vv[e], w[d * 8 + h], acc[h]);
        }
    }

    // indices: 256 rows of this block share (b, q); k = k0 + tid
    int b  = dist_id >> 10;
    int rem = (dist_id * 256) & 262143;
    int q  = rem >> 9;
    int k0 = rem & 511;
    // fold key-side mask into bias (-30000 saturates softmax to 0 in fp16)
    float madd = (g_maskf[b * SEQ + k0 + tid] > 0.5f) ? 0.0f : -30000.0f;
    #pragma unroll
    for (int h = 0; h < 8; h++)
        outsm[h * 256 + tid] = __float2half(acc[h] + bsm[h] + madd);
    __syncthreads();

    // coalesced global write: warp h writes its plane's 512B
    int h = tid >> 5, c = tid & 31;
    uint4 vout = *(const uint4*)&outsm[h * 256 + c * 8];
    *(uint4*)&g_biasf[(((size_t)(b * NH + h)) * SEQ + q) * SEQ + k0 + c * 8] = vout;
}

// ============== fused kernel: qkv GEMM (tensor) ∥ dist_bias (HBM) ==========
__global__ __launch_bounds__(256, 2) void fused_qkv_dist_kernel(
    const float* __restrict__ bq, const float* __restrict__ bk,
    const float* __restrict__ bv,
    const float* __restrict__ D, const float* __restrict__ Wd,
    const float* __restrict__ bd)
{
    extern __shared__ __nv_bfloat16 sm[];
    const int idx = blockIdx.x;
    const bool is_qkv = ((idx % 22) == 0) && (idx < 8448);
    if (is_qkv) {
        qkv_block(idx / 22, sm, bq, bk, bv);
    } else {
        const int nq_before = (idx < 8448) ? (idx / 22 + 1) : 384;
        dist_block(idx - nq_before, (char*)sm, D, Wd, bd);
    }
}

// ---------------- output projection (reads ctx hi/lo written by attn) ------
__global__ __launch_bounds__(256) void gemm_out_kernel(
    const float* __restrict__ bo, float* __restrict__ OUT)
{
    extern __shared__ __nv_bfloat16 sm[];
    const int m0 = blockIdx.y * 128, n0 = blockIdx.x * 128;

    float acc[4][4][4];
    bf16x3_gemm(g_Ahi, g_Alo, g_WThi[3], g_WTlo[3], m0, n0, sm, acc);

    const int lane = threadIdx.x & 31, wid = threadIdx.x >> 5;
    const int wm = wid >> 2, wn = wid & 3;
    const int g = lane >> 2, tg = lane & 3;

    #pragma unroll
    for (int mi = 0; mi < 4; mi++) {
        #pragma unroll
        for (int ni = 0; ni < 4; ni++) {
            int c = n0 + wn * 32 + ni * 8 + tg * 2;
            float b0 = bo[c], b1 = bo[c + 1];
            #pragma unroll
            for (int half = 0; half < 2; half++) {
                int m = m0 + wm * 64 + mi * 16 + g + half * 8;
                float mf = g_maskf[m];
                float2 v;
                v.x = (mf > 0.5f) ? acc[mi][ni][half*2 + 0] + b0 : 0.0f;
                v.y = (mf > 0.5f) ? acc[mi][ni][half*2 + 1] + b1 : 0.0f;
                *(float2*)&OUT[(size_t)m * HID + c] = v;
            }
        }
    }
}

// ======= fp16 tensor-core flash attention: CTA = (qb128, h, b), 8 warps ====
// smem halves layout: Q | K[2] | V[2] | BIAS[2] (mask folded into bias)
#define AT_LD 72                      // fp16 row stride (144B, ldmatrix-safe)
#define BT_LD 72                      // bias tile row stride (conflict-free)
#define OQ 0                          // Q: 128 x AT_LD = 9216 halves
#define OK 9216                       // K: [2 buf][4608]
#define OV 18432                      // V^T: [2 buf][4608]
#define OB 27648                      // bias: [2 buf][128*BT_LD = 9216]
#define ATTN_SMEM_BYTES 92160

__device__ __forceinline__ void attn_load_kv(
    uint32_t smb, int buf, int kb, int tid,
    const __half* Kf, const __half* Vf, const __half* Bb)
{
    const uint32_t bo = (uint32_t)(buf * 4608 * 2);
    #pragma unroll
    for (int j = 0; j < 2; j++) {
        int ch = j * 256 + tid;                // 512 chunks per matrix
        int r = ch >> 3, cc = ch & 7;
        uint32_t so = (uint32_t)((r * AT_LD + cc * 8) * 2);
        CP16(smb + OK*2 + bo + so, Kf + (size_t)(kb * 64 + r) * HD + cc * 8);
        CP16(smb + OV*2 + bo + so, Vf + (size_t)r * SEQ + kb * 64 + cc * 8);
    }
    // bias tile: 128 rows x 64 halves (128B rows, fully coalesced)
    const uint32_t bob = (uint32_t)(buf * 9216 * 2);
    #pragma unroll
    for (int j = 0; j < 4; j++) {
        int ch = j * 256 + tid;                // 1024 chunks
        int r = ch >> 3, cc = ch & 7;
        uint32_t so = (uint32_t)((r * BT_LD + cc * 8) * 2);
        CP16(smb + OB*2 + bob + so, Bb + (size_t)r * SEQ + kb * 64 + cc * 8);
    }
}

__global__ __launch_bounds__(256, 2) void attn_mma_kernel() {
    extern __shared__ __half smH[];
    const uint32_t smb = sm_u32(smH);
    const int tid = threadIdx.x, lane = tid & 31, w = tid >> 5;   // 8 warps
    const int qb = blockIdx.x, h = blockIdx.y, b = blockIdx.z;
    const int bh = b * NH + h;
    const int g = lane >> 2, t4 = lane & 3;

    const __half* Qf = g_Qf + ((size_t)bh * SEQ + qb * 128) * HD;
    const __half* Kf = g_Kf + (size_t)bh * SEQ * HD;
    const __half* Vf = g_VTf + (size_t)bh * HD * SEQ;
    const __half* Bb = g_biasf + ((size_t)bh * SEQ + qb * 128) * SEQ;

    // Q tile (128 x 64) + first KV+bias tiles
    #pragma unroll
    for (int j = 0; j < 4; j++) {
        int ch = j * 256 + tid;                // 1024 chunks
        int r = ch >> 3, cc = ch & 7;
        uint32_t so = (uint32_t)((r * AT_LD + cc * 8) * 2);
        CP16(smb + OQ*2 + so, Qf + (size_t)r * HD + cc * 8);
    }
    attn_load_kv(smb, 0, 0, tid, Kf, Vf, Bb);
    CP_COMMIT();
    CP_WAIT0();
    __syncthreads();

    // Q fragments (A, m16k16 per k-step); warp w owns rows [w*16, w*16+16)
    uint32_t qf[4][4];
    {
        int arow = w * 16 + (lane & 15);
        int acolb = (lane >> 4) << 3;
        #pragma unroll
        for (int ks = 0; ks < 4; ks++) {
            uint32_t off = (uint32_t)((arow * AT_LD + ks * 16 + acolb) * 2);
            LDMX4(qf[ks], smb + OQ*2 + off);
        }
    }

    float o[4][2][4];
    #pragma unroll
    for (int i = 0; i < 4; i++)
        #pragma unroll
        for (int j = 0; j < 2; j++)
            #pragma unroll
            for (int r = 0; r < 4; r++) o[i][j][r] = 0.0f;
    float mrun[2] = {-1e30f, -1e30f}, lrun[2] = {0.0f, 0.0f};

    const int browc = (lane & 7) + ((lane & 16) >> 1);
    const int bcolc = lane & 8;

    for (int kb = 0; kb < 8; kb++) {
        if (kb > 0) { CP_WAIT0(); __syncthreads(); }
        if (kb + 1 < 8) {
            attn_load_kv(smb, (kb + 1) & 1, kb + 1, tid, Kf, Vf, Bb);
            CP_COMMIT();
        }
        const uint32_t bufo  = (uint32_t)((kb & 1) * 4608 * 2);
        const int      bbase = OB + (kb & 1) * 9216;

        // ---- S = Q K^T (fp16, single pass) + (bias+mask)(smem) ----
        float sv[2][16];
        #pragma unroll
        for (int ni2 = 0; ni2 < 4; ni2++) {
            float s0[4] = {0, 0, 0, 0}, s1[4] = {0, 0, 0, 0};
            #pragma unroll
            for (int ks = 0; ks < 4; ks++) {
                uint32_t off = (uint32_t)(((ni2 * 16 + browc) * AT_LD + ks * 16 + bcolc) * 2);
                uint32_t kf4[4];
                LDMX4(kf4, smb + OK*2 + bufo + off);
                MMA16816H(s0, qf[ks], &kf4[0]);
                MMA16816H(s1, qf[ks], &kf4[2]);
            }
            #pragma unroll
            for (int n8p = 0; n8p < 2; n8p++) {
                const float* sp = n8p ? s1 : s0;
                int lcol = ni2 * 16 + n8p * 8 + t4 * 2;
                #pragma unroll
                for (int rh = 0; rh < 2; rh++) {
                    __half2 bb = *(const __half2*)
                        &smH[bbase + (w * 16 + g + rh * 8) * BT_LD + lcol];
                    float2 bf = __half22float2(bb);
                    sv[rh][ni2*4 + n8p*2 + 0] = sp[rh*2 + 0] + bf.x;
                    sv[rh][ni2*4 + n8p*2 + 1] = sp[rh*2 + 1] + bf.y;
                }
            }
        }

        // ---- online softmax ----
        float corr[2];
        #pragma unroll
        for (int rh = 0; rh < 2; rh++) {
            float rmx = -1e30f;
            #pragma unroll
            for (int i = 0; i < 16; i++) rmx = fmaxf(rmx, sv[rh][i]);
            rmx = fmaxf(rmx, __shfl_xor_sync(0xffffffffu, rmx, 1));
            rmx = fmaxf(rmx, __shfl_xor_sync(0xffffffffu, rmx, 2));
            float mnew = fmaxf(mrun[rh], rmx);
            corr[rh] = __expf(mrun[rh] - mnew);
            mrun[rh] = mnew;
            float rs = 0.0f;
            #pragma unroll
            for (int i = 0; i < 16; i++) {
                float p = __expf(sv[rh][i] - mnew);
                sv[rh][i] = p;
                rs += p;
            }
            rs += __shfl_xor_sync(0xffffffffu, rs, 1);
            rs += __shfl_xor_sync(0xffffffffu, rs, 2);
            lrun[rh] = lrun[rh] * corr[rh] + rs;
        }
        #pragma unroll
        for (int ni2 = 0; ni2 < 4; ni2++)
            #pragma unroll
            for (int n8p = 0; n8p < 2; n8p++) {
                o[ni2][n8p][0] *= corr[0];
                o[ni2][n8p][1] *= corr[0];
                o[ni2][n8p][2] *= corr[1];
                o[ni2][n8p][3] *= corr[1];
            }

        // ---- O += P V (fp16 single pass) ----
        #pragma unroll
        for (int ks = 0; ks < 4; ks++) {
            uint32_t pf[4];
            pf[0] = packh2(sv[0][ks*4 + 0], sv[0][ks*4 + 1]);
            pf[1] = packh2(sv[1][ks*4 + 0], sv[1][ks*4 + 1]);
            pf[2] = packh2(sv[0][ks*4 + 2], sv[0][ks*4 + 3]);
            pf[3] = packh2(sv[1][ks*4 + 2], sv[1][ks*4 + 3]);
            #pragma unroll
            for (int ni2 = 0; ni2 < 4; ni2++) {
                uint32_t off = (uint32_t)(((ni2 * 16 + browc) * AT_LD + ks * 16 + bcolc) * 2);
                uint32_t vf4[4];
                LDMX4(vf4, smb + OV*2 + bufo + off);
                MMA16816H(o[ni2][0], pf, &vf4[0]);
                MMA16816H(o[ni2][1], pf, &vf4[2]);
            }
        }
    }

    // ---- epilogue: normalize, split hi/lo, write ctx ----
    float inv[2] = {1.0f / lrun[0], 1.0f / lrun[1]};
    #pragma unroll
    for (int ni2 = 0; ni2 < 4; ni2++) {
        #pragma unroll
        for (int n8p = 0; n8p < 2; n8p++) {
            int col = h * 64 + ni2 * 16 + n8p * 8 + t4 * 2;
            #pragma unroll
            for (int rh = 0; rh < 2; rh++) {
                size_t m = (size_t)b * SEQ + qb * 128 + w * 16 + g + rh * 8;
                float v0 = o[ni2][n8p][rh*2 + 0] * inv[rh];
                float v1 = o[ni2][n8p][rh*2 + 1] * inv[rh];
                uint32_t hiw, low;
                split2(v0, v1, hiw, low);
                *(uint32_t*)&g_Ahi[m * HID + col] = hiw;
                *(uint32_t*)&g_Alo[m * HID + col] = low;
            }
        }
    }
}

// ---------------- launch ----------------
extern "C" void kernel_launch(void* const* d_in, const int* in_sizes, int n_in,
                              void* d_out, int out_size)
{
    const float* x    = (const float*)d_in[0];
    const float* dist = (const float*)d_in[1];
    const unsigned char* mask = (const unsigned char*)d_in[2];
    const float* Wq = (const float*)d_in[3];
    const float* bq = (const float*)d_in[4];
    const float* Wk = (const float*)d_in[5];
    const float* bk = (const float*)d_in[6];
    const float* Wv = (const float*)d_in[7];
    const float* bv = (const float*)d_in[8];
    const float* Wo = (const float*)d_in[9];
    const float* bo = (const float*)d_in[10];
    const float* Wd = (const float*)d_in[11];
    const float* bd = (const float*)d_in[12];
    float* out = (float*)d_out;

    cudaFuncSetAttribute(fused_qkv_dist_kernel, cudaFuncAttributeMaxDynamicSharedMemorySize,
                         GEMM_SMEM_BYTES);
    cudaFuncSetAttribute(gemm_out_kernel, cudaFuncAttributeMaxDynamicSharedMemorySize,
                         GEMM_SMEM_BYTES);
    cudaFuncSetAttribute(attn_mma_kernel, cudaFuncAttributeMaxDynamicSharedMemorySize,
                         ATTN_SMEM_BYTES);

    prep_kernel<<<3073, 256>>>(x, Wq, Wk, Wv, Wo, mask);
    fused_qkv_dist_kernel<<<8576, 256, GEMM_SMEM_BYTES>>>(bq, bk, bv, dist, Wd, bd);
    attn_mma_kernel<<<dim3(4, NH, NB), 256, ATTN_SMEM_BYTES>>>();
    gemm_out_kernel<<<dim3(4, 32), 256, GEMM_SMEM_BYTES>>>(bo, out);
}

// round 11
// speedup vs baseline: 3.1096x; 1.0158x over previous
#include <cuda_runtime.h>
#include <cuda_bf16.h>
#include <cuda_fp16.h>
#include <stdint.h>
#include <math.h>

#define NB 8
#define NH 8
#define SEQ 512
#define HID 512
#define HD 64

// ---------------- scratch (device globals; no allocations) ----------------
__device__ float g_maskf[NB*SEQ];                        // 0/1 floats
__device__ __half g_biasf[(size_t)NB*NH*SEQ*SEQ];        // 32 MB fp16 bias (+key mask)
__device__ __half g_Qf[NB*NH*SEQ*HD];                    // [b,h,n,d] (pre-scaled)
__device__ __half g_Kf[NB*NH*SEQ*HD];                    // [b,h,n,d]
__device__ __half g_VTf[NB*NH*SEQ*HD];                   // [b,h,d,n]
__device__ __nv_bfloat16 g_Ahi[NB*SEQ*HID], g_Alo[NB*SEQ*HID];   // x / ctx
__device__ __nv_bfloat16 g_WThi[4][HID*HID], g_WTlo[4][HID*HID]; // W^T [n][k]

// ---------------- PTX helpers ----------------
__device__ __forceinline__ uint32_t sm_u32(const void* p) {
    return (uint32_t)__cvta_generic_to_shared(p);
}
#define CP16(dst_u32, gptr) \
    asm volatile("cp.async.ca.shared.global [%0], [%1], 16;" :: "r"(dst_u32), "l"(gptr))
#define CP_COMMIT() asm volatile("cp.async.commit_group;")
#define CP_WAIT0()  asm volatile("cp.async.wait_group 0;")
#define LDMX4(r, addr) \
    asm volatile("ldmatrix.sync.aligned.m8n8.x4.shared.b16 {%0,%1,%2,%3}, [%4];" \
        : "=r"((r)[0]), "=r"((r)[1]), "=r"((r)[2]), "=r"((r)[3]) : "r"(addr))
#define MMA16816(d, a, b) \
    asm volatile("mma.sync.aligned.m16n8k16.row.col.f32.bf16.bf16.f32 " \
        "{%0,%1,%2,%3},{%4,%5,%6,%7},{%8,%9},{%0,%1,%2,%3};\n" \
        : "+f"((d)[0]), "+f"((d)[1]), "+f"((d)[2]), "+f"((d)[3]) \
        : "r"((a)[0]), "r"((a)[1]), "r"((a)[2]), "r"((a)[3]), "r"((b)[0]), "r"((b)[1]))
#define MMA16816H(d, a, b) \
    asm volatile("mma.sync.aligned.m16n8k16.row.col.f32.f16.f16.f32 " \
        "{%0,%1,%2,%3},{%4,%5,%6,%7},{%8,%9},{%0,%1,%2,%3};\n" \
        : "+f"((d)[0]), "+f"((d)[1]), "+f"((d)[2]), "+f"((d)[3]) \
        : "r"((a)[0]), "r"((a)[1]), "r"((a)[2]), "r"((a)[3]), "r"((b)[0]), "r"((b)[1]))

// split pair (a=elem0, b=elem1) into packed bf16x2 hi and lo residual
__device__ __forceinline__ void split2(float a, float b, uint32_t& hi, uint32_t& lo) {
    __nv_bfloat16 ha = __float2bfloat16(a), hb = __float2bfloat16(b);
    __nv_bfloat16 la = __float2bfloat16(a - __bfloat162float(ha));
    __nv_bfloat16 lb = __float2bfloat16(b - __bfloat162float(hb));
    hi = ((uint32_t)__bfloat16_as_ushort(hb) << 16) | (uint32_t)__bfloat16_as_ushort(ha);
    lo = ((uint32_t)__bfloat16_as_ushort(lb) << 16) | (uint32_t)__bfloat16_as_ushort(la);
}

__device__ __forceinline__ uint32_t packh2(float a, float b) {
    __half2 h = __floats2half2_rn(a, b);
    return *reinterpret_cast<uint32_t*>(&h);
}

// ================= prep kernel: conv_pair(x) + conv_wT + mask ==============
__global__ __launch_bounds__(256) void prep_kernel(
    const float* __restrict__ x,
    const float* __restrict__ Wq, const float* __restrict__ Wk,
    const float* __restrict__ Wv, const float* __restrict__ Wo,
    const unsigned char* __restrict__ raw)
{
    __shared__ float t[32][33];
    __shared__ int mode;
    const int bx = blockIdx.x;
    const int tid = threadIdx.x;

    if (bx < 2048) {
        // ---- x -> hi/lo bf16 split ----
        int i = bx * 256 + tid;                 // over float4s (2M floats)
        float4 v = ((const float4*)x)[i];
        uint32_t h0, l0, h1, l1;
        split2(v.x, v.y, h0, l0);
        split2(v.z, v.w, h1, l1);
        uint32_t* hp = (uint32_t*)(g_Ahi + 4*(size_t)i);
        uint32_t* lp = (uint32_t*)(g_Alo + 4*(size_t)i);
        hp[0] = h0; hp[1] = h1;
        lp[0] = l0; lp[1] = l1;
    } else if (bx < 3072) {
        // ---- W -> W^T hi/lo (32x32 tile transpose) ----
        const int tt = bx - 2048;               // 0..1023
        const int z = tt >> 8;
        const int bxx = tt & 15, byy = (tt >> 4) & 15;
        const float* W = (z == 0) ? Wq : (z == 1) ? Wk : (z == 2) ? Wv : Wo;
        __nv_bfloat16* Th = g_WThi[z];
        __nv_bfloat16* Tl = g_WTlo[z];
        int tx = tid & 31, ty = tid >> 5;       // 32 x 8
        int n0 = bxx * 32, k0 = byy * 32;
        #pragma unroll
        for (int j = 0; j < 4; j++)
            t[ty + 8*j][tx] = W[(size_t)(k0 + ty + 8*j) * HID + n0 + tx];
        __syncthreads();
        #pragma unroll
        for (int j = 0; j < 4; j++) {
            float v = t[tx][ty + 8*j];
            __nv_bfloat16 h = __float2bfloat16(v);
            __nv_bfloat16 l = __float2bfloat16(v - __bfloat162float(h));
            size_t o = (size_t)(n0 + ty + 8*j) * HID + k0 + tx;
            Th[o] = h;
            Tl[o] = l;
        }
    } else {
        // ---- mask normalization (dtype-agnostic) ----
        if (tid == 0) {
            const unsigned int* w = (const unsigned int*)raw;
            int cf = 0, byteish = 0;
            for (int i = 0; i < 128; i++) {
                unsigned int v = w[i];
                if (v == 0x3F800000u) cf++;
                bool b01 = true;
                #pragma unroll
                for (int bb = 0; bb < 4; bb++) {
                    unsigned int by = (v >> (8*bb)) & 0xFFu;
                    if (by > 1u) b01 = false;
                }
                if (b01 && v > 1u) byteish++;
            }
            mode = (cf > 64) ? 0 : ((byteish > 0) ? 2 : 1);  // 0=f32, 1=i32, 2=u8
        }
        __syncthreads();
        int md = mode;
        for (int i = tid; i < NB*SEQ; i += 256) {
            float m;
            if (md == 0)      m = (((const float*)raw)[i] != 0.0f) ? 1.0f : 0.0f;
            else if (md == 1) m = (((const int*)raw)[i]   != 0)    ? 1.0f : 0.0f;
            else              m = (raw[i]                 != 0)    ? 1.0f : 0.0f;
            g_maskf[i] = m;
        }
    }
}

// ================= bf16x3 tensor-core GEMM core (verified R4) =============
#define GBK 32
#define LDT 40
#define BUF_ELEMS (128 * LDT)
#define AH_OFS 0
#define ALO_OFS (2 * BUF_ELEMS)
#define BH_OFS  (4 * BUF_ELEMS)
#define BLO_OFS (6 * BUF_ELEMS)
#define GEMM_SMEM_BYTES (8 * BUF_ELEMS * 2)

__device__ __forceinline__ void bf16x3_gemm(
    const __nv_bfloat16* __restrict__ Ahi, const __nv_bfloat16* __restrict__ Alo,
    const __nv_bfloat16* __restrict__ Bhi, const __nv_bfloat16* __restrict__ Blo,
    int m0, int n0, __nv_bfloat16* sm, float acc[4][4][4])
{
    const int tid = threadIdx.x;
    const int lane = tid & 31, wid = tid >> 5;
    const int wm = wid >> 2, wn = wid & 3;
    const uint32_t smb = sm_u32(sm);

    #pragma unroll
    for (int mi = 0; mi < 4; mi++)
        #pragma unroll
        for (int ni = 0; ni < 4; ni++)
            #pragma unroll
            for (int r = 0; r < 4; r++) acc[mi][ni][r] = 0.0f;

    const int c0 = tid, c1 = tid + 256;
    const int r0 = c0 >> 2, s0 = c0 & 3;
    const int r1 = c1 >> 2, s1 = c1 & 3;

    auto load_chunk = [&](int kc, int buf) {
        const int k0 = kc * GBK;
        const uint32_t so0 = (uint32_t)(buf * BUF_ELEMS + r0 * LDT + s0 * 8) * 2;
        const uint32_t so1 = (uint32_t)(buf * BUF_ELEMS + r1 * LDT + s1 * 8) * 2;
        const size_t ga0 = (size_t)(m0 + r0) * HID + k0 + s0 * 8;
        const size_t ga1 = (size_t)(m0 + r1) * HID + k0 + s1 * 8;
        const size_t gb0 = (size_t)(n0 + r0) * HID + k0 + s0 * 8;
        const size_t gb1 = (size_t)(n0 + r1) * HID + k0 + s1 * 8;
        CP16(smb + AH_OFS*2  + so0, Ahi + ga0);
        CP16(smb + AH_OFS*2  + so1, Ahi + ga1);
        CP16(smb + ALO_OFS*2 + so0, Alo + ga0);
        CP16(smb + ALO_OFS*2 + so1, Alo + ga1);
        CP16(smb + BH_OFS*2  + so0, Bhi + gb0);
        CP16(smb + BH_OFS*2  + so1, Bhi + gb1);
        CP16(smb + BLO_OFS*2 + so0, Blo + gb0);
        CP16(smb + BLO_OFS*2 + so1, Blo + gb1);
    };

    const int arow = wm * 64 + (lane & 15);
    const int acolb = (lane >> 4) << 3;
    const int brow = wn * 32 + (lane & 7) + ((lane & 16) >> 1);
    const int bcolb = lane & 8;

    load_chunk(0, 0);
    CP_COMMIT();

    for (int kc = 0; kc < HID / GBK; kc++) {
        CP_WAIT0();
        __syncthreads();
        if (kc + 1 < HID / GBK) {
            load_chunk(kc + 1, (kc + 1) & 1);
            CP_COMMIT();
        }
        const int buf = kc & 1;
        #pragma unroll
        for (int ks = 0; ks < 2; ks++) {
            uint32_t ah[4][4], al[4][4], bh[2][4], bl[2][4];
            const int acol = ks * 16 + acolb;
            const int bcol = ks * 16 + bcolb;
            #pragma unroll
            for (int mi = 0; mi < 4; mi++) {
                uint32_t off = (uint32_t)(buf * BUF_ELEMS + (arow + mi*16) * LDT + acol) * 2;
                LDMX4(ah[mi], smb + AH_OFS*2 + off);
                LDMX4(al[mi], smb + ALO_OFS*2 + off);
            }
            #pragma unroll
            for (int p = 0; p < 2; p++) {
                uint32_t off = (uint32_t)(buf * BUF_ELEMS + (brow + p*16) * LDT + bcol) * 2;
                LDMX4(bh[p], smb + BH_OFS*2 + off);
                LDMX4(bl[p], smb + BLO_OFS*2 + off);
            }
            #pragma unroll
            for (int mi = 0; mi < 4; mi++)
                #pragma unroll
                for (int ni = 0; ni < 4; ni++) {
                    uint32_t* bhf = &bh[ni >> 1][(ni & 1) * 2];
                    uint32_t* blf = &bl[ni >> 1][(ni & 1) * 2];
                    MMA16816(acc[mi][ni], ah[mi], bhf);
                    MMA16816(acc[mi][ni], ah[mi], blf);
                    MMA16816(acc[mi][ni], al[mi], bhf);
                }
        }
        __syncthreads();
    }
}

// ---------------- qkv block body (one 128x128 tile of one of Q/K/V) --------
__device__ __forceinline__ void qkv_block(
    int qkv_id, __nv_bfloat16* sm,
    const float* __restrict__ bq, const float* __restrict__ bk,
    const float* __restrict__ bv)
{
    const int z = qkv_id >> 7;            // 0..2
    const int rem = qkv_id & 127;
    const int m0 = (rem >> 2) * 128;      // 32 m-tiles
    const int n0 = (rem & 3) * 128;       // 4 n-tiles
    const float* bias = (z == 0) ? bq : (z == 1) ? bk : bv;

    float acc[4][4][4];
    bf16x3_gemm(g_Ahi, g_Alo, g_WThi[z], g_WTlo[z], m0, n0, sm, acc);

    const int lane = threadIdx.x & 31, wid = threadIdx.x >> 5;
    const int wm = wid >> 2, wn = wid & 3;
    const int g = lane >> 2, tg = lane & 3;
    const float scale = (z == 0) ? 0.125f : 1.0f;

    __half* OUTF = (z == 0) ? g_Qf : g_Kf;

    #pragma unroll
    for (int mi = 0; mi < 4; mi++) {
        #pragma unroll
        for (int ni = 0; ni < 4; ni++) {
            int c = n0 + wn * 32 + ni * 8 + tg * 2;
            int hh = c >> 6, d = c & 63;
            float b0 = bias[c], b1 = bias[c + 1];
            #pragma unroll
            for (int half = 0; half < 2; half++) {
                int m = m0 + wm * 64 + mi * 16 + g + half * 8;
                int bb = m >> 9, n = m & 511;
                int bh = bb * NH + hh;
                float v0 = (acc[mi][ni][half*2 + 0] + b0) * scale;
                float v1 = (acc[mi][ni][half*2 + 1] + b1) * scale;
                if (z < 2) {
                    size_t a = ((size_t)bh * SEQ + n) * HD + d;
                    *(__half2*)&OUTF[a] = __floats2half2_rn(v0, v1);
                } else {
                    // V stored transposed: [b,h,d,n]
                    size_t a0 = ((size_t)bh * HD + d) * SEQ + n;
                    g_VTf[a0]       = __float2half(v0);
                    g_VTf[a0 + SEQ] = __float2half(v1);
                }
            }
        }
    }
}

// -------- dist block: smem-staged coalesced version --------
__device__ __forceinline__ void dist_block(
    int dist_id, char* smraw,
    const float* __restrict__ D, const float* __restrict__ Wd,
    const float* __restrict__ bd)
{
    float* w     = (float*)smraw;
    float* bsm   = (float*)(smraw + 2048);
    float* rows  = (float*)(smraw + 2080);
    __half* outsm = (__half*)(smraw + 71712);
    const uint32_t rows_b = sm_u32(smraw + 2080);
    const int tid = threadIdx.x;

    // stage 256 rows x 256B into smem, fully coalesced 16B chunks
    const float* src = D + (size_t)dist_id * 256 * 64;
    #pragma unroll
    for (int j = 0; j < 16; j++) {
        int c = j * 256 + tid;
        int r = c >> 4, o = c & 15;
        CP16(rows_b + (uint32_t)(r * 272 + o * 16), src + (size_t)c * 4);
    }
    CP_COMMIT();

    w[tid]       = Wd[tid];
    w[tid + 256] = Wd[tid + 256];
    if (tid < 8) bsm[tid] = bd[tid];

    CP_WAIT0();
    __syncthreads();

    // thread-per-row compute from smem (68-float stride: LDS.128 conflict-free)
    const float* rp = rows + tid * 68;
    float acc[8] = {0, 0, 0, 0, 0, 0, 0, 0};
    #pragma unroll
    for (int t = 0; t < 16; t++) {
        float4 v = *(const float4*)(rp + t * 4);
        float vv[4] = {v.x, v.y, v.z, v.w};
        #pragma unroll
        for (int e = 0; e < 4; e++) {
            int d = t * 4 + e;
            #pragma unroll
            for (int h = 0; h < 8; h++)
                acc[h] = fmaf(vv[e], w[d * 8 + h], acc[h]);
        }
    }

    // indices: 256 rows of this block share (b, q); k = k0 + tid
    int b  = dist_id >> 10;
    int rem = (dist_id * 256) & 262143;
    int q  = rem >> 9;
    int k0 = rem & 511;
    // fold key-side mask into bias (-30000 saturates softmax to 0)
    float madd = (g_maskf[b * SEQ + k0 + tid] > 0.5f) ? 0.0f : -30000.0f;
    #pragma unroll
    for (int h = 0; h < 8; h++)
        outsm[h * 256 + tid] = __float2half(acc[h] + bsm[h] + madd);
    __syncthreads();

    // coalesced global write: warp h writes its plane's 512B
    int h = tid >> 5, c = tid & 31;
    uint4 vout = *(const uint4*)&outsm[h * 256 + c * 8];
    *(uint4*)&g_biasf[(((size_t)(b * NH + h)) * SEQ + q) * SEQ + k0 + c * 8] = vout;
}

// ============== fused kernel: qkv GEMM (tensor) ∥ dist_bias (HBM) ==========
__global__ __launch_bounds__(256, 2) void fused_qkv_dist_kernel(
    const float* __restrict__ bq, const float* __restrict__ bk,
    const float* __restrict__ bv,
    const float* __restrict__ D, const float* __restrict__ Wd,
    const float* __restrict__ bd)
{
    extern __shared__ __nv_bfloat16 sm[];
    const int idx = blockIdx.x;
    const bool is_qkv = ((idx % 22) == 0) && (idx < 8448);
    if (is_qkv) {
        qkv_block(idx / 22, sm, bq, bk, bv);
    } else {
        const int nq_before = (idx < 8448) ? (idx / 22 + 1) : 384;
        dist_block(idx - nq_before, (char*)sm, D, Wd, bd);
    }
}

// ---------------- output projection (reads ctx hi/lo written by attn) ------
__global__ __launch_bounds__(256) void gemm_out_kernel(
    const float* __restrict__ bo, float* __restrict__ OUT)
{
    extern __shared__ __nv_bfloat16 sm[];
    const int m0 = blockIdx.y * 128, n0 = blockIdx.x * 128;

    float acc[4][4][4];
    bf16x3_gemm(g_Ahi, g_Alo, g_WThi[3], g_WTlo[3], m0, n0, sm, acc);

    const int lane = threadIdx.x & 31, wid = threadIdx.x >> 5;
    const int wm = wid >> 2, wn = wid & 3;
    const int g = lane >> 2, tg = lane & 3;

    #pragma unroll
    for (int mi = 0; mi < 4; mi++) {
        #pragma unroll
        for (int ni = 0; ni < 4; ni++) {
            int c = n0 + wn * 32 + ni * 8 + tg * 2;
            float b0 = bo[c], b1 = bo[c + 1];
            #pragma unroll
            for (int half = 0; half < 2; half++) {
                int m = m0 + wm * 64 + mi * 16 + g + half * 8;
                float mf = g_maskf[m];
                float2 v;
                v.x = (mf > 0.5f) ? acc[mi][ni][half*2 + 0] + b0 : 0.0f;
                v.y = (mf > 0.5f) ? acc[mi][ni][half*2 + 1] + b1 : 0.0f;
                *(float2*)&OUT[(size_t)m * HID + c] = v;
            }
        }
    }
}

// ======= fp16 tensor-core flash attention, exact softmax w/o running max ===
#define AT_LD 72                      // fp16 row stride (144B, ldmatrix-safe)
#define BT_LD 72
#define OQ 0                          // Q: 128 x AT_LD = 9216 halves
#define OK 9216                       // K: [2 buf][4608]
#define OV 18432                      // V^T: [2 buf][4608]
#define OB 27648                      // bias: [2 buf][9216]
#define ATTN_SMEM_BYTES 92160

__device__ __forceinline__ void attn_load_kv(
    uint32_t smb, int buf, int kb, int tid,
    const __half* Kf, const __half* Vf, const __half* Bb)
{
    const uint32_t bo = (uint32_t)(buf * 4608 * 2);
    #pragma unroll
    for (int j = 0; j < 2; j++) {
        int ch = j * 256 + tid;
        int r = ch >> 3, cc = ch & 7;
        uint32_t so = (uint32_t)((r * AT_LD + cc * 8) * 2);
        CP16(smb + OK*2 + bo + so, Kf + (size_t)(kb * 64 + r) * HD + cc * 8);
        CP16(smb + OV*2 + bo + so, Vf + (size_t)r * SEQ + kb * 64 + cc * 8);
    }
    const uint32_t bob = (uint32_t)(buf * 9216 * 2);
    #pragma unroll
    for (int j = 0; j < 4; j++) {
        int ch = j * 256 + tid;
        int r = ch >> 3, cc = ch & 7;
        uint32_t so = (uint32_t)((r * BT_LD + cc * 8) * 2);
        CP16(smb + OB*2 + bob + so, Bb + (size_t)r * SEQ + kb * 64 + cc * 8);
    }
}

__global__ __launch_bounds__(256, 2) void attn_mma_kernel() {
    extern __shared__ __half smH[];
    const uint32_t smb = sm_u32(smH);
    const int tid = threadIdx.x, lane = tid & 31, w = tid >> 5;   // 8 warps
    const int qb = blockIdx.x, h = blockIdx.y, b = blockIdx.z;
    const int bh = b * NH + h;
    const int g = lane >> 2, t4 = lane & 3;

    const __half* Qf = g_Qf + ((size_t)bh * SEQ + qb * 128) * HD;
    const __half* Kf = g_Kf + (size_t)bh * SEQ * HD;
    const __half* Vf = g_VTf + (size_t)bh * HD * SEQ;
    const __half* Bb = g_biasf + ((size_t)bh * SEQ + qb * 128) * SEQ;

    // Q tile (128 x 64) + first KV+bias tiles
    #pragma unroll
    for (int j = 0; j < 4; j++) {
        int ch = j * 256 + tid;
        int r = ch >> 3, cc = ch & 7;
        uint32_t so = (uint32_t)((r * AT_LD + cc * 8) * 2);
        CP16(smb + OQ*2 + so, Qf + (size_t)r * HD + cc * 8);
    }
    attn_load_kv(smb, 0, 0, tid, Kf, Vf, Bb);
    CP_COMMIT();
    CP_WAIT0();
    __syncthreads();

    // Q fragments; warp w owns rows [w*16, w*16+16)
    uint32_t qf[4][4];
    {
        int arow = w * 16 + (lane & 15);
        int acolb = (lane >> 4) << 3;
        #pragma unroll
        for (int ks = 0; ks < 4; ks++) {
            uint32_t off = (uint32_t)((arow * AT_LD + ks * 16 + acolb) * 2);
            LDMX4(qf[ks], smb + OQ*2 + off);
        }
    }

    float o[4][2][4];
    #pragma unroll
    for (int i = 0; i < 4; i++)
        #pragma unroll
        for (int j = 0; j < 2; j++)
            #pragma unroll
            for (int r = 0; r < 4; r++) o[i][j][r] = 0.0f;
    float lsum[2] = {0.0f, 0.0f};          // per-thread partial row sums

    const int browc = (lane & 7) + ((lane & 16) >> 1);
    const int bcolc = lane & 8;

    for (int kb = 0; kb < 8; kb++) {
        if (kb > 0) { CP_WAIT0(); __syncthreads(); }
        if (kb + 1 < 8) {
            attn_load_kv(smb, (kb + 1) & 1, kb + 1, tid, Kf, Vf, Bb);
            CP_COMMIT();
        }
        const uint32_t bufo  = (uint32_t)((kb & 1) * 4608 * 2);
        const int      bbase = OB + (kb & 1) * 9216;

        // ---- P = exp(Q K^T + bias+mask) directly; no max, no correction ----
        float sv[2][16];
        #pragma unroll
        for (int ni2 = 0; ni2 < 4; ni2++) {
            float s0[4] = {0, 0, 0, 0}, s1[4] = {0, 0, 0, 0};
            #pragma unroll
            for (int ks = 0; ks < 4; ks++) {
                uint32_t off = (uint32_t)(((ni2 * 16 + browc) * AT_LD + ks * 16 + bcolc) * 2);
                uint32_t kf4[4];
                LDMX4(kf4, smb + OK*2 + bufo + off);
                MMA16816H(s0, qf[ks], &kf4[0]);
                MMA16816H(s1, qf[ks], &kf4[2]);
            }
            #pragma unroll
            for (int n8p = 0; n8p < 2; n8p++) {
                const float* sp = n8p ? s1 : s0;
                int lcol = ni2 * 16 + n8p * 8 + t4 * 2;
                #pragma unroll
                for (int rh = 0; rh < 2; rh++) {
                    __half2 bb = *(const __half2*)
                        &smH[bbase + (w * 16 + g + rh * 8) * BT_LD + lcol];
                    float2 bf = __half22float2(bb);
                    float p0 = __expf(sp[rh*2 + 0] + bf.x);
                    float p1 = __expf(sp[rh*2 + 1] + bf.y);
                    sv[rh][ni2*4 + n8p*2 + 0] = p0;
                    sv[rh][ni2*4 + n8p*2 + 1] = p1;
                    lsum[rh] += p0 + p1;
                }
            }
        }

        // ---- O += P V (fp16 single pass) ----
        #pragma unroll
        for (int ks = 0; ks < 4; ks++) {
            uint32_t pf[4];
            pf[0] = packh2(sv[0][ks*4 + 0], sv[0][ks*4 + 1]);
            pf[1] = packh2(sv[1][ks*4 + 0], sv[1][ks*4 + 1]);
            pf[2] = packh2(sv[0][ks*4 + 2], sv[0][ks*4 + 3]);
            pf[3] = packh2(sv[1][ks*4 + 2], sv[1][ks*4 + 3]);
            #pragma unroll
            for (int ni2 = 0; ni2 < 4; ni2++) {
                uint32_t off = (uint32_t)(((ni2 * 16 + browc) * AT_LD + ks * 16 + bcolc) * 2);
                uint32_t vf4[4];
                LDMX4(vf4, smb + OV*2 + bufo + off);
                MMA16816H(o[ni2][0], pf, &vf4[0]);
                MMA16816H(o[ni2][1], pf, &vf4[2]);
            }
        }
    }

    // ---- final row-sum reduction (once) + epilogue ----
    #pragma unroll
    for (int rh = 0; rh < 2; rh++) {
        lsum[rh] += __shfl_xor_sync(0xffffffffu, lsum[rh], 1);
        lsum[rh] += __shfl_xor_sync(0xffffffffu, lsum[rh], 2);
    }
    float inv[2] = {1.0f / lsum[0], 1.0f / lsum[1]};
    #pragma unroll
    for (int ni2 = 0; ni2 < 4; ni2++) {
        #pragma unroll
        for (int n8p = 0; n8p < 2; n8p++) {
            int col = h * 64 + ni2 * 16 + n8p * 8 + t4 * 2;
            #pragma unroll
            for (int rh = 0; rh < 2; rh++) {
                size_t m = (size_t)b * SEQ + qb * 128 + w * 16 + g + rh * 8;
                float v0 = o[ni2][n8p][rh*2 + 0] * inv[rh];
                float v1 = o[ni2][n8p][rh*2 + 1] * inv[rh];
                uint32_t hiw, low;
                split2(v0, v1, hiw, low);
                *(uint32_t*)&g_Ahi[m * HID + col] = hiw;
                *(uint32_t*)&g_Alo[m * HID + col] = low;
            }
        }
    }
}

// ---------------- launch ----------------
extern "C" void kernel_launch(void* const* d_in, const int* in_sizes, int n_in,
                              void* d_out, int out_size)
{
    const float* x    = (const float*)d_in[0];
    const float* dist = (const float*)d_in[1];
    const unsigned char* mask = (const unsigned char*)d_in[2];
    const float* Wq = (const float*)d_in[3];
    const float* bq = (const float*)d_in[4];
    const float* Wk = (const float*)d_in[5];
    const float* bk = (const float*)d_in[6];
    const float* Wv = (const float*)d_in[7];
    const float* bv = (const float*)d_in[8];
    const float* Wo = (const float*)d_in[9];
    const float* bo = (const float*)d_in[10];
    const float* Wd = (const float*)d_in[11];
    const float* bd = (const float*)d_in[12];
    float* out = (float*)d_out;

    cudaFuncSetAttribute(fused_qkv_dist_kernel, cudaFuncAttributeMaxDynamicSharedMemorySize,
                         GEMM_SMEM_BYTES);
    cudaFuncSetAttribute(gemm_out_kernel, cudaFuncAttributeMaxDynamicSharedMemorySize,
                         GEMM_SMEM_BYTES);
    cudaFuncSetAttribute(attn_mma_kernel, cudaFuncAttributeMaxDynamicSharedMemorySize,
                         ATTN_SMEM_BYTES);

    prep_kernel<<<3073, 256>>>(x, Wq, Wk, Wv, Wo, mask);
    fused_qkv_dist_kernel<<<8576, 256, GEMM_SMEM_BYTES>>>(bq, bk, bv, dist, Wd, bd);
    attn_mma_kernel<<<dim3(4, NH, NB), 256, ATTN_SMEM_BYTES>>>();
    gemm_out_kernel<<<dim3(4, 32), 256, GEMM_SMEM_BYTES>>>(bo, out);
}